// round 3
// baseline (speedup 1.0000x reference)
#include <cuda_runtime.h>
#include <math.h>
#include <stdint.h>

#define BB 32
#define NN 128
#define CD 128
#define PP 8128
#define RNDS 3

// ---------------- persistent device scratch (rewritten fully every launch) ----
__device__ float g_e   [(size_t)BB*NN*NN*CD];   // 256 MB edge features
__device__ float g_mbuf[(size_t)BB*NN*NN*CD];   // 256 MB messages (pre-reduction)
__device__ float g_h   [BB*NN*CD];
__device__ float g_hp  [BB*NN*512];             // [hwl | hvl | hwm | hvm]
__device__ float g_ms  [BB*NN*CD];
__device__ float g_gi  [BB*NN*384];
__device__ float g_gh  [BB*NN*384];
__device__ int   g_iu  [PP];
__device__ int   g_ju  [PP];

// ---------------- init kernels ------------------------------------------------
__global__ void k_init_e(const int* __restrict__ eids, const float* __restrict__ emb) {
    size_t t = (size_t)blockIdx.x * blockDim.x + threadIdx.x;   // over B*N*N*(CD/4)
    size_t total = (size_t)BB*NN*NN*(CD/4);
    if (t >= total) return;
    size_t edge = t >> 5;        // CD/4 = 32 float4 per edge
    int c4 = (int)(t & 31);
    int id = eids[edge];
    ((float4*)g_e)[t] = ((const float4*)emb)[id*(CD/4) + c4];
}

__global__ void k_copy_h(const float* __restrict__ nf) {
    int t = blockIdx.x * blockDim.x + threadIdx.x;
    if (t < BB*NN*CD/4) ((float4*)g_h)[t] = ((const float4*)nf)[t];
}

__global__ void k_init_pairs() {
    int t = blockIdx.x * blockDim.x + threadIdx.x;
    if (t >= NN*NN) return;
    int i = t / NN, j = t % NN;
    if (j > i) {
        int p = i*(NN-1) - i*(i-1)/2 + (j - i - 1);
        g_iu[p] = i; g_ju[p] = j;
    }
}

// ---------------- small row-block GEMM: C[rows,outC] = A[rows,128] @ W + bias --
__global__ void k_rowgemm(const float* __restrict__ A, const float* __restrict__ W,
                          const float* __restrict__ bias, float* __restrict__ C,
                          int outC, int ldC, int colOff) {
    __shared__ float sA[32*CD];
    int row0 = blockIdx.x * 32;
    for (int t = threadIdx.x; t < 32*CD; t += blockDim.x)
        sA[t] = A[(size_t)row0*CD + t];
    __syncthreads();
    int col = threadIdx.x;
    if (col >= outC) return;
    float acc[32];
#pragma unroll
    for (int r = 0; r < 32; ++r) acc[r] = 0.f;
    for (int c = 0; c < CD; ++c) {
        float w = W[c*outC + col];
#pragma unroll
        for (int r = 0; r < 32; ++r) acc[r] = fmaf(sA[r*CD + c], w, acc[r]);
    }
    float bv = bias ? bias[col] : 0.f;
    for (int r = 0; r < 32; ++r)
        C[(size_t)(row0 + r)*ldC + colOff + col] = acc[r] + bv;
}

// ---------------- shared 8x8 register-tile GEMM core ---------------------------
template<int LDA, int LDB, int KSTEPS>
__device__ __forceinline__ void gemm_tile(const float* __restrict__ pA,   // &sA[r0*LDA + cbeg]
                                          const float* __restrict__ pB,   // &sB[0*LDB + k0]
                                          float acc[8][8]) {
#pragma unroll 2
    for (int c0 = 0; c0 < KSTEPS; c0 += 4) {
        float4 a4[8];
#pragma unroll
        for (int r = 0; r < 8; ++r)
            a4[r] = *(const float4*)(pA + r*LDA + c0);
#pragma unroll
        for (int cs = 0; cs < 4; ++cs) {
            float4 b0 = *(const float4*)(pB + (size_t)(c0 + cs)*LDB);
            float4 b1 = *(const float4*)(pB + (size_t)(c0 + cs)*LDB + 4);
            float bb[8] = {b0.x,b0.y,b0.z,b0.w,b1.x,b1.y,b1.z,b1.w};
#pragma unroll
            for (int r = 0; r < 8; ++r) {
                float av = (cs==0) ? a4[r].x : (cs==1) ? a4[r].y : (cs==2) ? a4[r].z : a4[r].w;
#pragma unroll
                for (int c = 0; c < 8; ++c)
                    acc[r][c] = fmaf(av, bb[c], acc[r][c]);
            }
        }
    }
}

// ---------------- the fused per-edge-row kernel (hot loop) ---------------------
// CTA = (b, i). E tile 128x128 in smem; 4 GEMMs:
//  1) E@Wl_e -> z -> adj -> s          2) E@Wm_e -> m (masked*scaled) -> sM, g_mbuf
//  3) E@Wu_e (+)  4) sM@Wu_m  -> e_new = pm ? relu(.+bu) : e_old
#define EDGE_SMEM_FLOATS (16384*3 + 2048 + 128)
__global__ __launch_bounds__(256, 1)
void k_edge(const float* __restrict__ Wl_e, const float* __restrict__ Wm_e,
            const float* __restrict__ Wu_e, const float* __restrict__ Wu_m,
            const float* __restrict__ wl2,  const float* __restrict__ bl2,
            const float* __restrict__ bu,   const int* __restrict__ ev)
{
    extern __shared__ float sm[];
    float* sE    = sm;
    float* sW    = sm + 16384;
    float* sM    = sm + 32768;
    float* sPart = sm + 49152;   // [128][16] adj partials (deterministic reduce)
    float* sS    = sm + 51200;   // [128]

    int tid = threadIdx.x;
    int bi  = blockIdx.x;
    int b = bi / NN, i = bi % NN;
    int vn = ev[b];
    bool pmi = (i < vn);
    int tx = tid & 15, ty = tid >> 4;
    int j0 = ty*8, k0 = tx*8;

    const float* erow = g_e + (size_t)bi*NN*CD;
    for (int t = tid; t < NN*CD/4; t += 256) {
        ((float4*)sE)[t] = ((const float4*)erow)[t];
        ((float4*)sW)[t] = ((const float4*)Wl_e)[t];
    }
    __syncthreads();

    const float* hpi = g_hp + (size_t)bi*512;
    const float* hpb = g_hp + (size_t)b*NN*512;

    float acc[8][8];
    // ---- GEMM1: z / adj ----
#pragma unroll
    for (int r=0;r<8;++r)
#pragma unroll
        for (int c=0;c<8;++c) acc[r][c]=0.f;
    gemm_tile<128,128,128>(sE + j0*128, sW + k0, acc);
    {
        float hwl[8], w2[8];
#pragma unroll
        for (int c=0;c<8;++c) { hwl[c] = hpi[k0+c]; w2[c] = wl2[k0+c]; }
#pragma unroll
        for (int r=0;r<8;++r) {
            const float* hv = hpb + (size_t)(j0+r)*512 + 128;
            float part = 0.f;
#pragma unroll
            for (int c=0;c<8;++c) {
                float z = acc[r][c] + hwl[c] + hv[k0+c];
                z = fmaxf(z, 0.f);
                part = fmaf(z, w2[c], part);
            }
            sPart[(j0+r)*16 + tx] = part;
        }
    }
    __syncthreads();
    if (tid < NN) {
        float a = 0.f;
#pragma unroll
        for (int t=0;t<16;++t) a += sPart[tid*16 + t];
        a += bl2[0];
        bool pm = pmi && (tid < vn);
        sS[tid] = pm ? (1.f/(1.f + expf(-a))) : 0.f;
    }
    for (int t = tid; t < NN*CD/4; t += 256)
        ((float4*)sW)[t] = ((const float4*)Wm_e)[t];
    __syncthreads();

    // ---- GEMM2: m ----
#pragma unroll
    for (int r=0;r<8;++r)
#pragma unroll
        for (int c=0;c<8;++c) acc[r][c]=0.f;
    gemm_tile<128,128,128>(sE + j0*128, sW + k0, acc);
    {
        float hwm[8];
#pragma unroll
        for (int c=0;c<8;++c) hwm[c] = hpi[256 + k0 + c];
        float* mout = g_mbuf + (size_t)bi*NN*CD;
#pragma unroll
        for (int r=0;r<8;++r) {
            float sj = sS[j0+r];
            const float* hv = hpb + (size_t)(j0+r)*512 + 384;
            float v[8];
#pragma unroll
            for (int c=0;c<8;++c)
                v[c] = fmaxf(acc[r][c] + hwm[c] + hv[k0+c], 0.f) * sj;
            float4 v0 = {v[0],v[1],v[2],v[3]};
            float4 v1 = {v[4],v[5],v[6],v[7]};
            *(float4*)(sM + (j0+r)*CD + k0)     = v0;
            *(float4*)(sM + (j0+r)*CD + k0 + 4) = v1;
            *(float4*)(mout + (size_t)(j0+r)*CD + k0)     = v0;
            *(float4*)(mout + (size_t)(j0+r)*CD + k0 + 4) = v1;
        }
    }
    __syncthreads();

    // ---- GEMM3: E@Wu_e ----
    for (int t = tid; t < NN*CD/4; t += 256)
        ((float4*)sW)[t] = ((const float4*)Wu_e)[t];
    __syncthreads();
#pragma unroll
    for (int r=0;r<8;++r)
#pragma unroll
        for (int c=0;c<8;++c) acc[r][c]=0.f;
    gemm_tile<128,128,128>(sE + j0*128, sW + k0, acc);
    __syncthreads();
    for (int t = tid; t < NN*CD/4; t += 256)
        ((float4*)sW)[t] = ((const float4*)Wu_m)[t];
    __syncthreads();
    // ---- GEMM4: + sM@Wu_m ----
    gemm_tile<128,128,128>(sM + j0*128, sW + k0, acc);
    {
        float bur[8];
#pragma unroll
        for (int c=0;c<8;++c) bur[c] = bu[k0+c];
        float* eout = g_e + (size_t)bi*NN*CD;
#pragma unroll
        for (int r=0;r<8;++r) {
            bool pm = pmi && ((j0+r) < vn);
            float v[8];
#pragma unroll
            for (int c=0;c<8;++c) {
                float nv = fmaxf(acc[r][c] + bur[c], 0.f);
                v[c] = pm ? nv : sE[(j0+r)*CD + k0 + c];
            }
            float4 v0 = {v[0],v[1],v[2],v[3]};
            float4 v1 = {v[4],v[5],v[6],v[7]};
            *(float4*)(eout + (size_t)(j0+r)*CD + k0)     = v0;
            *(float4*)(eout + (size_t)(j0+r)*CD + k0 + 4) = v1;
        }
    }
}

// ---------------- ms = sum_i m[b,i,j,k]  (deterministic fixed-order) ----------
__global__ void k_reduce_ms() {
    int t = blockIdx.x * blockDim.x + threadIdx.x;
    if (t >= BB*NN*CD) return;
    int b  = t / (NN*CD);
    int jk = t % (NN*CD);
    const float* base = g_mbuf + (size_t)b*NN*NN*CD + jk;
    float s = 0.f;
#pragma unroll 4
    for (int i = 0; i < NN; ++i) s += base[(size_t)i*NN*CD];
    g_ms[t] = s;
}

// ---------------- GRU gate update ---------------------------------------------
__global__ void k_gru(const int* __restrict__ ev) {
    int t = blockIdx.x * blockDim.x + threadIdx.x;
    if (t >= BB*NN*CD) return;
    int row = t / CD, c = t % CD;
    int b = row / NN, n = row % NN;
    if (n >= ev[b]) return;
    const float* gi = g_gi + (size_t)row*384;
    const float* gh = g_gh + (size_t)row*384;
    float ir = gi[c], iz = gi[CD+c], in = gi[2*CD+c];
    float hr = gh[c], hz = gh[CD+c], hn = gh[2*CD+c];
    float r  = 1.f/(1.f + expf(-(ir+hr)));
    float z  = 1.f/(1.f + expf(-(iz+hz)));
    float nn = tanhf(in + r*hn);
    float hold = g_h[t];
    g_h[t] = (1.f - z)*nn + z*hold;
}

// ---------------- readout: pairwise MLP + masked scatter ----------------------
#define RO_SMEM_FLOATS (16384*3)
__global__ __launch_bounds__(256, 1)
void k_readout(const float* __restrict__ Wr1, const float* __restrict__ br1,
               const float* __restrict__ Wr2, const float* __restrict__ br2,
               const int* __restrict__ ev, float* __restrict__ out)
{
    extern __shared__ float sm[];
    float* sF = sm;            // 64 x 256 feat
    float* sW = sm + 16384;    // 64 x 256 weight chunk
    float* sH = sm + 32768;    // 64 x 256 hidden
    int tid = threadIdx.x;
    int b   = blockIdx.y;
    int p0  = blockIdx.x * 64;   // P = 8128 = 127 * 64, always full tile

    for (int t = tid; t < 64*64; t += 256) {   // 64 pairs x 64 float4
        int lp = t >> 6; int c = (t & 63) * 4;
        int p = p0 + lp;
        int iu = g_iu[p], ju = g_ju[p];
        const float* src = (c < 128)
            ? g_e + (((size_t)(b*NN + iu))*NN + ju)*CD + c
            : g_e + (((size_t)(b*NN + ju))*NN + iu)*CD + (c - 128);
        *(float4*)(sF + lp*256 + c) = *(const float4*)src;
    }

    int tx = tid & 31, ty = tid >> 5;
    int r0 = ty*8, k0 = tx*8;
    float acc[8][8];
#pragma unroll
    for (int r=0;r<8;++r)
#pragma unroll
        for (int c=0;c<8;++c) acc[r][c]=0.f;

    for (int cc = 0; cc < 4; ++cc) {
        __syncthreads();   // sF ready (cc=0) / previous chunk consumed (cc>0)
        for (int t = tid; t < 64*64; t += 256) {
            int rr = t >> 6; int c = (t & 63) * 4;
            *(float4*)(sW + rr*256 + c) = *(const float4*)(Wr1 + (size_t)(cc*64 + rr)*256 + c);
        }
        __syncthreads();
        gemm_tile<256,256,64>(sF + r0*256 + cc*64, sW + k0, acc);
    }
    __syncthreads();
#pragma unroll
    for (int r=0;r<8;++r)
#pragma unroll
        for (int c=0;c<8;++c)
            sH[(r0+r)*256 + k0 + c] = fmaxf(acc[r][c] + br1[k0+c], 0.f);
    __syncthreads();

    int vn = ev[b];
    for (int o = tid; o < 64*10; o += 256) {
        int lp = o / 10, t5 = o % 10;
        const float* hrow = sH + lp*256;
        float s = br2[t5];
#pragma unroll 4
        for (int c = 0; c < 256; ++c) s = fmaf(hrow[c], Wr2[c*10 + t5], s);
        int p = p0 + lp;
        int iu = g_iu[p], ju = g_ju[p];
        if (ju < vn) {
            int idx = iu*vn - iu*(iu+1)/2 + (ju - iu - 1);
            out[(((size_t)b*5 + (t5 >> 1))*PP + idx)*2 + (t5 & 1)] = s;
        }
    }
}

// ---------------- host orchestration ------------------------------------------
extern "C" void kernel_launch(void* const* d_in, const int* in_sizes, int n_in,
                              void* d_out, int out_size) {
    const int*   edge_ids      = (const int*)  d_in[0];
    const float* node_features = (const float*)d_in[1];
    const int*   ev            = (const int*)  d_in[3];
    const float* emb           = (const float*)d_in[4];
    const float* Wl_e = (const float*)d_in[5];
    const float* Wl_w = (const float*)d_in[6];
    const float* Wl_v = (const float*)d_in[7];
    const float* bl1  = (const float*)d_in[8];
    const float* wl2  = (const float*)d_in[9];
    const float* bl2  = (const float*)d_in[10];
    const float* Wm_w = (const float*)d_in[11];
    const float* Wm_v = (const float*)d_in[12];
    const float* Wm_e = (const float*)d_in[13];
    const float* bm   = (const float*)d_in[14];
    const float* Wu_e = (const float*)d_in[15];
    const float* Wu_m = (const float*)d_in[16];
    const float* bu   = (const float*)d_in[17];
    const float* W_ih = (const float*)d_in[18];
    const float* W_hh = (const float*)d_in[19];
    const float* b_ih = (const float*)d_in[20];
    const float* b_hh = (const float*)d_in[21];
    const float* Wr1  = (const float*)d_in[22];
    const float* br1  = (const float*)d_in[23];
    const float* Wr2  = (const float*)d_in[24];
    const float* br2  = (const float*)d_in[25];

    cudaFuncSetAttribute(k_edge,    cudaFuncAttributeMaxDynamicSharedMemorySize,
                         EDGE_SMEM_FLOATS * (int)sizeof(float));
    cudaFuncSetAttribute(k_readout, cudaFuncAttributeMaxDynamicSharedMemorySize,
                         RO_SMEM_FLOATS * (int)sizeof(float));

    void *p_h, *p_hp, *p_ms, *p_gi, *p_gh;
    cudaGetSymbolAddress(&p_h,  g_h);
    cudaGetSymbolAddress(&p_hp, g_hp);
    cudaGetSymbolAddress(&p_ms, g_ms);
    cudaGetSymbolAddress(&p_gi, g_gi);
    cudaGetSymbolAddress(&p_gh, g_gh);

    k_init_e<<<65536, 256>>>(edge_ids, emb);
    k_copy_h<<<(BB*NN*CD/4 + 255)/256, 256>>>(node_features);
    k_init_pairs<<<(NN*NN + 255)/256, 256>>>();

    for (int r = 0; r < RNDS; ++r) {
        // node projections: [hwl(+bl1) | hvl | hwm(+bm) | hvm]
        k_rowgemm<<<BB*NN/32, 128>>>((const float*)p_h, Wl_w, bl1,     (float*)p_hp, 128, 512, 0);
        k_rowgemm<<<BB*NN/32, 128>>>((const float*)p_h, Wl_v, nullptr, (float*)p_hp, 128, 512, 128);
        k_rowgemm<<<BB*NN/32, 128>>>((const float*)p_h, Wm_w, bm,      (float*)p_hp, 128, 512, 256);
        k_rowgemm<<<BB*NN/32, 128>>>((const float*)p_h, Wm_v, nullptr, (float*)p_hp, 128, 512, 384);

        k_edge<<<BB*NN, 256, EDGE_SMEM_FLOATS * sizeof(float)>>>(
            Wl_e, Wm_e, Wu_e, Wu_m, wl2, bl2, bu, ev);

        k_reduce_ms<<<(BB*NN*CD + 255)/256, 256>>>();

        k_rowgemm<<<BB*NN/32, 384>>>((const float*)p_ms, W_ih, b_ih, (float*)p_gi, 384, 384, 0);
        k_rowgemm<<<BB*NN/32, 384>>>((const float*)p_h,  W_hh, b_hh, (float*)p_gh, 384, 384, 0);
        k_gru<<<(BB*NN*CD + 255)/256, 256>>>(ev);
    }

    cudaMemsetAsync(d_out, 0, (size_t)out_size * sizeof(float));
    k_readout<<<dim3(PP/64, BB), 256, RO_SMEM_FLOATS * sizeof(float)>>>(
        Wr1, br1, Wr2, br2, ev, (float*)d_out);
}

// round 4
// speedup vs baseline: 1.0087x; 1.0087x over previous
#include <cuda_runtime.h>
#include <math.h>
#include <stdint.h>

#define BB 32
#define NN 128
#define CD 128
#define PP 8128
#define RNDS 3

// ---------------- persistent device scratch (rewritten fully every launch) ----
__device__ float g_e   [(size_t)BB*NN*NN*CD];   // 256 MB edge features
__device__ float g_mbuf[(size_t)BB*NN*NN*CD];   // 256 MB messages (pre-reduction)
__device__ float g_h   [BB*NN*CD];
__device__ float g_hp  [BB*NN*512];             // [hwl | hvl | hwm | hvm]
__device__ float g_ms  [BB*NN*CD];
__device__ float g_gi  [BB*NN*384];
__device__ float g_gh  [BB*NN*384];
__device__ int   g_iu  [PP];
__device__ int   g_ju  [PP];

// ---------------- init kernels ------------------------------------------------
__global__ void k_init_e(const int* __restrict__ eids, const float* __restrict__ emb) {
    size_t t = (size_t)blockIdx.x * blockDim.x + threadIdx.x;   // over B*N*N*(CD/4)
    size_t total = (size_t)BB*NN*NN*(CD/4);
    if (t >= total) return;
    size_t edge = t >> 5;        // CD/4 = 32 float4 per edge
    int c4 = (int)(t & 31);
    int id = eids[edge];
    ((float4*)g_e)[t] = ((const float4*)emb)[id*(CD/4) + c4];
}

__global__ void k_copy_h(const float* __restrict__ nf) {
    int t = blockIdx.x * blockDim.x + threadIdx.x;
    if (t < BB*NN*CD/4) ((float4*)g_h)[t] = ((const float4*)nf)[t];
}

__global__ void k_init_pairs() {
    int t = blockIdx.x * blockDim.x + threadIdx.x;
    if (t >= NN*NN) return;
    int i = t / NN, j = t % NN;
    if (j > i) {
        int p = i*(NN-1) - i*(i-1)/2 + (j - i - 1);
        g_iu[p] = i; g_ju[p] = j;
    }
}

// ---------------- small row-block GEMM: C[rows,outC] = A[rows,128] @ W + bias --
__global__ void k_rowgemm(const float* __restrict__ A, const float* __restrict__ W,
                          const float* __restrict__ bias, float* __restrict__ C,
                          int outC, int ldC, int colOff) {
    __shared__ float sA[32*CD];
    int row0 = blockIdx.x * 32;
    for (int t = threadIdx.x; t < 32*CD; t += blockDim.x)
        sA[t] = A[(size_t)row0*CD + t];
    __syncthreads();
    int col = threadIdx.x;
    if (col >= outC) return;
    float acc[32];
#pragma unroll
    for (int r = 0; r < 32; ++r) acc[r] = 0.f;
    for (int c = 0; c < CD; ++c) {
        float w = W[c*outC + col];
#pragma unroll
        for (int r = 0; r < 32; ++r) acc[r] = fmaf(sA[r*CD + c], w, acc[r]);
    }
    float bv = bias ? bias[col] : 0.f;
    for (int r = 0; r < 32; ++r)
        C[(size_t)(row0 + r)*ldC + colOff + col] = acc[r] + bv;
}

// ---------------- shared 8x8 register-tile GEMM core ---------------------------
template<int LDA, int LDB, int KSTEPS>
__device__ __forceinline__ void gemm_tile(const float* __restrict__ pA,   // &sA[r0*LDA + cbeg]
                                          const float* __restrict__ pB,   // &sB[0*LDB + k0]
                                          float acc[8][8]) {
#pragma unroll 2
    for (int c0 = 0; c0 < KSTEPS; c0 += 4) {
        float4 a4[8];
#pragma unroll
        for (int r = 0; r < 8; ++r)
            a4[r] = *(const float4*)(pA + r*LDA + c0);
#pragma unroll
        for (int cs = 0; cs < 4; ++cs) {
            float4 b0 = *(const float4*)(pB + (size_t)(c0 + cs)*LDB);
            float4 b1 = *(const float4*)(pB + (size_t)(c0 + cs)*LDB + 4);
            float bb[8] = {b0.x,b0.y,b0.z,b0.w,b1.x,b1.y,b1.z,b1.w};
#pragma unroll
            for (int r = 0; r < 8; ++r) {
                float av = (cs==0) ? a4[r].x : (cs==1) ? a4[r].y : (cs==2) ? a4[r].z : a4[r].w;
#pragma unroll
                for (int c = 0; c < 8; ++c)
                    acc[r][c] = fmaf(av, bb[c], acc[r][c]);
            }
        }
    }
}

// ---------------- the fused per-edge-row kernel (hot loop) ---------------------
// CTA = (b, i). E tile 128x128 in smem; 4 GEMMs:
//  1) E@Wl_e -> z -> adj -> s          2) E@Wm_e -> m (masked*scaled) -> sM, g_mbuf
//  3) E@Wu_e (+)  4) sM@Wu_m  -> e_new = pm ? relu(.+bu) : e_old
#define EDGE_SMEM_FLOATS (16384*3 + 2048 + 128)
__global__ __launch_bounds__(256, 1)
void k_edge(const float* __restrict__ Wl_e, const float* __restrict__ Wm_e,
            const float* __restrict__ Wu_e, const float* __restrict__ Wu_m,
            const float* __restrict__ wl2,  const float* __restrict__ bl2,
            const float* __restrict__ bu,   const int* __restrict__ ev)
{
    extern __shared__ float sm[];
    float* sE    = sm;
    float* sW    = sm + 16384;
    float* sM    = sm + 32768;
    float* sPart = sm + 49152;   // [128][16] adj partials (deterministic reduce)
    float* sS    = sm + 51200;   // [128]

    int tid = threadIdx.x;
    int bi  = blockIdx.x;
    int b = bi / NN, i = bi % NN;
    int vn = ev[b];
    bool pmi = (i < vn);
    int tx = tid & 15, ty = tid >> 4;
    int j0 = ty*8, k0 = tx*8;

    const float* erow = g_e + (size_t)bi*NN*CD;
    for (int t = tid; t < NN*CD/4; t += 256) {
        ((float4*)sE)[t] = ((const float4*)erow)[t];
        ((float4*)sW)[t] = ((const float4*)Wl_e)[t];
    }
    __syncthreads();

    const float* hpi = g_hp + (size_t)bi*512;
    const float* hpb = g_hp + (size_t)b*NN*512;

    float acc[8][8];
    // ---- GEMM1: z / adj ----
#pragma unroll
    for (int r=0;r<8;++r)
#pragma unroll
        for (int c=0;c<8;++c) acc[r][c]=0.f;
    gemm_tile<128,128,128>(sE + j0*128, sW + k0, acc);
    {
        float hwl[8], w2[8];
#pragma unroll
        for (int c=0;c<8;++c) { hwl[c] = hpi[k0+c]; w2[c] = wl2[k0+c]; }
#pragma unroll
        for (int r=0;r<8;++r) {
            const float* hv = hpb + (size_t)(j0+r)*512 + 128;
            float part = 0.f;
#pragma unroll
            for (int c=0;c<8;++c) {
                float z = acc[r][c] + hwl[c] + hv[k0+c];
                z = fmaxf(z, 0.f);
                part = fmaf(z, w2[c], part);
            }
            sPart[(j0+r)*16 + tx] = part;
        }
    }
    __syncthreads();
    if (tid < NN) {
        float a = 0.f;
#pragma unroll
        for (int t=0;t<16;++t) a += sPart[tid*16 + t];
        a += bl2[0];
        bool pm = pmi && (tid < vn);
        sS[tid] = pm ? (1.f/(1.f + expf(-a))) : 0.f;
    }
    for (int t = tid; t < NN*CD/4; t += 256)
        ((float4*)sW)[t] = ((const float4*)Wm_e)[t];
    __syncthreads();

    // ---- GEMM2: m ----
#pragma unroll
    for (int r=0;r<8;++r)
#pragma unroll
        for (int c=0;c<8;++c) acc[r][c]=0.f;
    gemm_tile<128,128,128>(sE + j0*128, sW + k0, acc);
    {
        float hwm[8];
#pragma unroll
        for (int c=0;c<8;++c) hwm[c] = hpi[256 + k0 + c];
        float* mout = g_mbuf + (size_t)bi*NN*CD;
#pragma unroll
        for (int r=0;r<8;++r) {
            float sj = sS[j0+r];
            const float* hv = hpb + (size_t)(j0+r)*512 + 384;
            float v[8];
#pragma unroll
            for (int c=0;c<8;++c)
                v[c] = fmaxf(acc[r][c] + hwm[c] + hv[k0+c], 0.f) * sj;
            float4 v0 = {v[0],v[1],v[2],v[3]};
            float4 v1 = {v[4],v[5],v[6],v[7]};
            *(float4*)(sM + (j0+r)*CD + k0)     = v0;
            *(float4*)(sM + (j0+r)*CD + k0 + 4) = v1;
            *(float4*)(mout + (size_t)(j0+r)*CD + k0)     = v0;
            *(float4*)(mout + (size_t)(j0+r)*CD + k0 + 4) = v1;
        }
    }
    __syncthreads();

    // ---- GEMM3: E@Wu_e ----
    for (int t = tid; t < NN*CD/4; t += 256)
        ((float4*)sW)[t] = ((const float4*)Wu_e)[t];
    __syncthreads();
#pragma unroll
    for (int r=0;r<8;++r)
#pragma unroll
        for (int c=0;c<8;++c) acc[r][c]=0.f;
    gemm_tile<128,128,128>(sE + j0*128, sW + k0, acc);
    __syncthreads();
    for (int t = tid; t < NN*CD/4; t += 256)
        ((float4*)sW)[t] = ((const float4*)Wu_m)[t];
    __syncthreads();
    // ---- GEMM4: + sM@Wu_m ----
    gemm_tile<128,128,128>(sM + j0*128, sW + k0, acc);
    {
        float bur[8];
#pragma unroll
        for (int c=0;c<8;++c) bur[c] = bu[k0+c];
        float* eout = g_e + (size_t)bi*NN*CD;
#pragma unroll
        for (int r=0;r<8;++r) {
            bool pm = pmi && ((j0+r) < vn);
            float v[8];
#pragma unroll
            for (int c=0;c<8;++c) {
                float nv = fmaxf(acc[r][c] + bur[c], 0.f);
                v[c] = pm ? nv : sE[(j0+r)*CD + k0 + c];
            }
            float4 v0 = {v[0],v[1],v[2],v[3]};
            float4 v1 = {v[4],v[5],v[6],v[7]};
            *(float4*)(eout + (size_t)(j0+r)*CD + k0)     = v0;
            *(float4*)(eout + (size_t)(j0+r)*CD + k0 + 4) = v1;
        }
    }
}

// ---------------- ms = sum_i m[b,i,j,k]  (deterministic fixed-order) ----------
__global__ void k_reduce_ms() {
    int t = blockIdx.x * blockDim.x + threadIdx.x;
    if (t >= BB*NN*CD) return;
    int b  = t / (NN*CD);
    int jk = t % (NN*CD);
    const float* base = g_mbuf + (size_t)b*NN*NN*CD + jk;
    float s = 0.f;
#pragma unroll 4
    for (int i = 0; i < NN; ++i) s += base[(size_t)i*NN*CD];
    g_ms[t] = s;
}

// ---------------- GRU gate update ---------------------------------------------
__global__ void k_gru(const int* __restrict__ ev) {
    int t = blockIdx.x * blockDim.x + threadIdx.x;
    if (t >= BB*NN*CD) return;
    int row = t / CD, c = t % CD;
    int b = row / NN, n = row % NN;
    if (n >= ev[b]) return;
    const float* gi = g_gi + (size_t)row*384;
    const float* gh = g_gh + (size_t)row*384;
    float ir = gi[c], iz = gi[CD+c], in = gi[2*CD+c];
    float hr = gh[c], hz = gh[CD+c], hn = gh[2*CD+c];
    float r  = 1.f/(1.f + expf(-(ir+hr)));
    float z  = 1.f/(1.f + expf(-(iz+hz)));
    float nn = tanhf(in + r*hn);
    float hold = g_h[t];
    g_h[t] = (1.f - z)*nn + z*hold;
}

// ---------------- readout: pairwise MLP + masked scatter ----------------------
#define RO_SMEM_FLOATS (16384*3)
__global__ __launch_bounds__(256, 1)
void k_readout(const float* __restrict__ Wr1, const float* __restrict__ br1,
               const float* __restrict__ Wr2, const float* __restrict__ br2,
               const int* __restrict__ ev, float* __restrict__ out)
{
    extern __shared__ float sm[];
    float* sF = sm;            // 64 x 256 feat
    float* sW = sm + 16384;    // 64 x 256 weight chunk
    float* sH = sm + 32768;    // 64 x 256 hidden
    int tid = threadIdx.x;
    int b   = blockIdx.y;
    int p0  = blockIdx.x * 64;   // P = 8128 = 127 * 64, always full tile

    for (int t = tid; t < 64*64; t += 256) {   // 64 pairs x 64 float4
        int lp = t >> 6; int c = (t & 63) * 4;
        int p = p0 + lp;
        int iu = g_iu[p], ju = g_ju[p];
        const float* src = (c < 128)
            ? g_e + (((size_t)(b*NN + iu))*NN + ju)*CD + c
            : g_e + (((size_t)(b*NN + ju))*NN + iu)*CD + (c - 128);
        *(float4*)(sF + lp*256 + c) = *(const float4*)src;
    }

    int tx = tid & 31, ty = tid >> 5;
    int r0 = ty*8, k0 = tx*8;
    float acc[8][8];
#pragma unroll
    for (int r=0;r<8;++r)
#pragma unroll
        for (int c=0;c<8;++c) acc[r][c]=0.f;

    for (int cc = 0; cc < 4; ++cc) {
        __syncthreads();   // sF ready (cc=0) / previous chunk consumed (cc>0)
        for (int t = tid; t < 64*64; t += 256) {
            int rr = t >> 6; int c = (t & 63) * 4;
            *(float4*)(sW + rr*256 + c) = *(const float4*)(Wr1 + (size_t)(cc*64 + rr)*256 + c);
        }
        __syncthreads();
        gemm_tile<256,256,64>(sF + r0*256 + cc*64, sW + k0, acc);
    }
    __syncthreads();
#pragma unroll
    for (int r=0;r<8;++r)
#pragma unroll
        for (int c=0;c<8;++c)
            sH[(r0+r)*256 + k0 + c] = fmaxf(acc[r][c] + br1[k0+c], 0.f);
    __syncthreads();

    int vn = ev[b];
    for (int o = tid; o < 64*10; o += 256) {
        int lp = o / 10, t5 = o % 10;
        const float* hrow = sH + lp*256;
        float s = br2[t5];
#pragma unroll 4
        for (int c = 0; c < 256; ++c) s = fmaf(hrow[c], Wr2[c*10 + t5], s);
        int p = p0 + lp;
        int iu = g_iu[p], ju = g_ju[p];
        if (ju < vn) {
            int idx = iu*vn - iu*(iu+1)/2 + (ju - iu - 1);
            out[(((size_t)b*5 + (t5 >> 1))*PP + idx)*2 + (t5 & 1)] = s;
        }
    }
}

// ---------------- host orchestration ------------------------------------------
extern "C" void kernel_launch(void* const* d_in, const int* in_sizes, int n_in,
                              void* d_out, int out_size) {
    const int*   edge_ids      = (const int*)  d_in[0];
    const float* node_features = (const float*)d_in[1];
    const int*   ev            = (const int*)  d_in[3];
    const float* emb           = (const float*)d_in[4];
    const float* Wl_e = (const float*)d_in[5];
    const float* Wl_w = (const float*)d_in[6];
    const float* Wl_v = (const float*)d_in[7];
    const float* bl1  = (const float*)d_in[8];
    const float* wl2  = (const float*)d_in[9];
    const float* bl2  = (const float*)d_in[10];
    const float* Wm_w = (const float*)d_in[11];
    const float* Wm_v = (const float*)d_in[12];
    const float* Wm_e = (const float*)d_in[13];
    const float* bm   = (const float*)d_in[14];
    const float* Wu_e = (const float*)d_in[15];
    const float* Wu_m = (const float*)d_in[16];
    const float* bu   = (const float*)d_in[17];
    const float* W_ih = (const float*)d_in[18];
    const float* W_hh = (const float*)d_in[19];
    const float* b_ih = (const float*)d_in[20];
    const float* b_hh = (const float*)d_in[21];
    const float* Wr1  = (const float*)d_in[22];
    const float* br1  = (const float*)d_in[23];
    const float* Wr2  = (const float*)d_in[24];
    const float* br2  = (const float*)d_in[25];

    cudaFuncSetAttribute(k_edge,    cudaFuncAttributeMaxDynamicSharedMemorySize,
                         EDGE_SMEM_FLOATS * (int)sizeof(float));
    cudaFuncSetAttribute(k_readout, cudaFuncAttributeMaxDynamicSharedMemorySize,
                         RO_SMEM_FLOATS * (int)sizeof(float));

    void *p_h, *p_hp, *p_ms, *p_gi, *p_gh;
    cudaGetSymbolAddress(&p_h,  g_h);
    cudaGetSymbolAddress(&p_hp, g_hp);
    cudaGetSymbolAddress(&p_ms, g_ms);
    cudaGetSymbolAddress(&p_gi, g_gi);
    cudaGetSymbolAddress(&p_gh, g_gh);

    k_init_e<<<65536, 256>>>(edge_ids, emb);
    k_copy_h<<<(BB*NN*CD/4 + 255)/256, 256>>>(node_features);
    k_init_pairs<<<(NN*NN + 255)/256, 256>>>();

    for (int r = 0; r < RNDS; ++r) {
        // node projections: [hwl(+bl1) | hvl | hwm(+bm) | hvm]
        k_rowgemm<<<BB*NN/32, 128>>>((const float*)p_h, Wl_w, bl1,     (float*)p_hp, 128, 512, 0);
        k_rowgemm<<<BB*NN/32, 128>>>((const float*)p_h, Wl_v, nullptr, (float*)p_hp, 128, 512, 128);
        k_rowgemm<<<BB*NN/32, 128>>>((const float*)p_h, Wm_w, bm,      (float*)p_hp, 128, 512, 256);
        k_rowgemm<<<BB*NN/32, 128>>>((const float*)p_h, Wm_v, nullptr, (float*)p_hp, 128, 512, 384);

        k_edge<<<BB*NN, 256, EDGE_SMEM_FLOATS * sizeof(float)>>>(
            Wl_e, Wm_e, Wu_e, Wu_m, wl2, bl2, bu, ev);

        k_reduce_ms<<<(BB*NN*CD + 255)/256, 256>>>();

        k_rowgemm<<<BB*NN/32, 384>>>((const float*)p_ms, W_ih, b_ih, (float*)p_gi, 384, 384, 0);
        k_rowgemm<<<BB*NN/32, 384>>>((const float*)p_h,  W_hh, b_hh, (float*)p_gh, 384, 384, 0);
        k_gru<<<(BB*NN*CD + 255)/256, 256>>>(ev);
    }

    cudaMemsetAsync(d_out, 0, (size_t)out_size * sizeof(float));
    k_readout<<<dim3(PP/64, BB), 256, RO_SMEM_FLOATS * sizeof(float)>>>(
        Wr1, br1, Wr2, br2, ev, (float*)d_out);
}

// round 6
// speedup vs baseline: 1.7589x; 1.7437x over previous
#include <cuda_runtime.h>
#include <cuda_bf16.h>
#include <math.h>
#include <stdint.h>

#define BB 32
#define NN 128
#define CD 128
#define PP 8128
#define RNDS 3

// ===================== low-level helpers (base ISA only) ======================
__device__ __forceinline__ uint32_t smem_u32(const void* p) {
    uint32_t a;
    asm("{ .reg .u64 t; cvta.to.shared.u64 t, %1; cvt.u32.u64 %0, t; }" : "=r"(a) : "l"(p));
    return a;
}
__device__ __forceinline__ void ldsm4(uint32_t r[4], uint32_t addr) {
    asm volatile("ldmatrix.sync.aligned.m8n8.x4.shared.b16 {%0,%1,%2,%3}, [%4];"
        : "=r"(r[0]), "=r"(r[1]), "=r"(r[2]), "=r"(r[3]) : "r"(addr));
}
__device__ __forceinline__ void mma_bf16(float c[4], const uint32_t a[4],
                                         uint32_t b0, uint32_t b1) {
    asm volatile("mma.sync.aligned.m16n8k16.row.col.f32.bf16.bf16.f32 "
        "{%0,%1,%2,%3}, {%4,%5,%6,%7}, {%8,%9}, {%0,%1,%2,%3};"
        : "+f"(c[0]), "+f"(c[1]), "+f"(c[2]), "+f"(c[3])
        : "r"(a[0]), "r"(a[1]), "r"(a[2]), "r"(a[3]), "r"(b0), "r"(b1));
}
// split (x,y) into packed bf16 hi pair + bf16 residual pair
__device__ __forceinline__ void split_pair(float x, float y, uint32_t& hi, uint32_t& lo) {
    __nv_bfloat16 hx = __float2bfloat16(x), hy = __float2bfloat16(y);
    float rx = x - __bfloat162float(hx), ry = y - __bfloat162float(hy);
    __nv_bfloat16 lx = __float2bfloat16(rx), ly = __float2bfloat16(ry);
    hi = (uint32_t)*(uint16_t*)&hx | ((uint32_t)*(uint16_t*)&hy << 16);
    lo = (uint32_t)*(uint16_t*)&lx | ((uint32_t)*(uint16_t*)&ly << 16);
}
// XOR-swizzled byte offset for bf16 element (r, k); row stride = 1<<SH bytes
template<int SH>
__device__ __host__ __forceinline__ uint32_t swz(int r, int k) {
    return ((uint32_t)r << SH) + ((uint32_t)(((k >> 3) ^ (r & 7))) << 4) + ((uint32_t)(k & 7) << 1);
}

// 3-pass split GEMM: acc += Ahi*Bhi + Alo*Bhi + Ahi*Blo.
// A: [M][K] k-major swizzled bf16; B: [N][K] k-major swizzled bf16.
// Warp computes rows mbase..mbase+15 x all N (NTP pairs of n8-tiles).
template<int SH, int NKS, int NTP>
__device__ __forceinline__ void gemm_split(uint32_t sb, uint32_t offA, uint32_t offAlo,
                                           uint32_t offB, uint32_t offBlo,
                                           int mbase, int lane, float acc[][4]) {
    int arow = mbase + (lane & 7) + (((lane >> 3) & 1) << 3);
    uint32_t aBase   = sb + offA + ((uint32_t)arow << SH);
    uint32_t aBaseLo = sb + offAlo + ((uint32_t)arow << SH);
    int a7 = arow & 7, agrp = (lane >> 4) & 1;
    int brow0 = (lane & 7) + ((lane >> 4) << 3);
    int b7 = lane & 7, bkb = (lane >> 3) & 1;
#pragma unroll
    for (int ks = 0; ks < NKS; ++ks) {
        uint32_t ak = (uint32_t)((((ks << 1) | agrp) ^ a7) << 4);
        uint32_t Ah[4], Al[4];
        ldsm4(Ah, aBase + ak);
        ldsm4(Al, aBaseLo + ak);
        uint32_t bk = (uint32_t)((((ks << 1) | bkb) ^ b7) << 4);
#pragma unroll
        for (int tp = 0; tp < NTP; ++tp) {
            uint32_t brow = (uint32_t)(brow0 + (tp << 4)) << SH;
            uint32_t Bh[4], Bl[4];
            ldsm4(Bh, sb + offB + brow + bk);
            ldsm4(Bl, sb + offBlo + brow + bk);
            mma_bf16(acc[2*tp],     Ah, Bh[0], Bh[1]);
            mma_bf16(acc[2*tp],     Al, Bh[0], Bh[1]);
            mma_bf16(acc[2*tp],     Ah, Bl[0], Bl[1]);
            mma_bf16(acc[2*tp + 1], Ah, Bh[2], Bh[3]);
            mma_bf16(acc[2*tp + 1], Al, Bh[2], Bh[3]);
            mma_bf16(acc[2*tp + 1], Ah, Bl[2], Bl[3]);
        }
    }
}

// ===================== persistent device scratch ==============================
__device__ float g_e   [(size_t)BB*NN*NN*CD];
__device__ float g_mbuf[(size_t)BB*NN*NN*CD];
__device__ float g_h   [BB*NN*CD];
__device__ float g_hp  [BB*NN*512];             // [hwl+bl1 | hvl | hwm+bm | hvm]
__device__ float g_ms  [BB*NN*CD];
__device__ float g_gi  [BB*NN*384];
__device__ float g_gh  [BB*NN*384];
__device__ int   g_iu  [PP];
__device__ int   g_ju  [PP];
__device__ unsigned short g_wt[4*32768];        // 4 edge weights: [hi 32KB][lo 32KB] each, swizzled [n][k]
__device__ unsigned short g_wr[4*32768];        // Wr1 in 4 n-chunks: [hi 32KB][lo 32KB] each

// ===================== init / prep kernels ====================================
__global__ void k_init_e(const int* __restrict__ eids, const float* __restrict__ emb) {
    size_t t = (size_t)blockIdx.x * blockDim.x + threadIdx.x;
    size_t total = (size_t)BB*NN*NN*(CD/4);
    if (t >= total) return;
    size_t edge = t >> 5;
    int c4 = (int)(t & 31);
    int id = eids[edge];
    ((float4*)g_e)[t] = ((const float4*)emb)[id*(CD/4) + c4];
}

__global__ void k_copy_h(const float* __restrict__ nf) {
    int t = blockIdx.x * blockDim.x + threadIdx.x;
    if (t < BB*NN*CD/4) ((float4*)g_h)[t] = ((const float4*)nf)[t];
}

__global__ void k_init_pairs() {
    int t = blockIdx.x * blockDim.x + threadIdx.x;
    if (t >= NN*NN) return;
    int i = t / NN, j = t % NN;
    if (j > i) {
        int p = i*(NN-1) - i*(i-1)/2 + (j - i - 1);
        g_iu[p] = i; g_ju[p] = j;
    }
}

__global__ void k_prep_w(const float* __restrict__ Wl_e, const float* __restrict__ Wm_e,
                         const float* __restrict__ Wu_e, const float* __restrict__ Wu_m) {
    int idx = blockIdx.x * blockDim.x + threadIdx.x;
    if (idx >= 4*16384) return;
    int m = idx >> 14, r = idx & 16383, n = r >> 7, k = r & 127;
    const float* W = (m == 0) ? Wl_e : (m == 1) ? Wm_e : (m == 2) ? Wu_e : Wu_m;
    float v = W[k*128 + n];
    __nv_bfloat16 hi = __float2bfloat16(v);
    __nv_bfloat16 lo = __float2bfloat16(v - __bfloat162float(hi));
    uint32_t o = swz<8>(n, k);
    char* base = (char*)g_wt + (size_t)m*65536;
    *(__nv_bfloat16*)(base + o) = hi;
    *(__nv_bfloat16*)(base + 32768 + o) = lo;
}

__global__ void k_prep_wr(const float* __restrict__ Wr1) {   // [256][256] k x n
    int idx = blockIdx.x * blockDim.x + threadIdx.x;
    if (idx >= 65536) return;
    int n = idx >> 8, k = idx & 255;
    float v = Wr1[k*256 + n];
    __nv_bfloat16 hi = __float2bfloat16(v);
    __nv_bfloat16 lo = __float2bfloat16(v - __bfloat162float(hi));
    int cc = n >> 6, r = n & 63;
    uint32_t o = swz<9>(r, k);
    char* base = (char*)g_wr + (size_t)cc*65536;
    *(__nv_bfloat16*)(base + o) = hi;
    *(__nv_bfloat16*)(base + 32768 + o) = lo;
}

// ===================== node-level GEMM (small) ================================
__global__ __launch_bounds__(256)
void k_rowgemm2(const float* __restrict__ A, const float* __restrict__ W,
                const float* __restrict__ bias, float* __restrict__ C,
                int outC, int ldC, int colOff) {
    __shared__ float sA[32*128];
    int row0 = blockIdx.x * 32;
    int c0 = blockIdx.y * 128;
    for (int t = threadIdx.x; t < 1024; t += 256)
        ((float4*)sA)[t] = ((const float4*)(A + (size_t)row0*128))[t];
    __syncthreads();
    int col = c0 + (threadIdx.x & 127);
    int half = threadIdx.x >> 7;
    float acc[16];
#pragma unroll
    for (int r = 0; r < 16; ++r) acc[r] = 0.f;
    const float* sAr = sA + half*16*128;
    for (int k = 0; k < 128; ++k) {
        float w = W[(size_t)k*outC + col];
#pragma unroll
        for (int r = 0; r < 16; ++r) acc[r] = fmaf(sAr[r*128 + k], w, acc[r]);
    }
    float bv = bias ? bias[col] : 0.f;
    for (int r = 0; r < 16; ++r)
        C[(size_t)(row0 + half*16 + r)*ldC + colOff + col] = acc[r] + bv;
}

// ===================== fused edge kernel (HMMA) ===============================
// smem: [Ehi 32K][Elo 32K][Mhi 32K][Mlo 32K][Whi 32K][Wlo 32K] = 192KB
#define EOF_EHI 0u
#define EOF_ELO 32768u
#define EOF_MHI 65536u
#define EOF_MLO 98304u
#define EOF_WHI 131072u
#define EOF_WLO 163840u
#define EDGE_SMEM 196608

__global__ __launch_bounds__(256, 1)
void k_edge_mma(const float* __restrict__ wl2, const float* __restrict__ bl2,
                const float* __restrict__ bu,  const int* __restrict__ ev) {
    extern __shared__ char smem[];
    uint32_t sb = smem_u32(smem);
    int tid = threadIdx.x, warp = tid >> 5, l = tid & 31, q = l & 3;
    int bi = blockIdx.x, b = bi >> 7, i = bi & 127;
    int vn = ev[b];
    bool pmi = (i < vn);

    // load + split E tile, load W1
    const float4* er4 = (const float4*)(g_e + (size_t)bi*NN*CD);
    for (int t = tid; t < 4096; t += 256) {
        float4 v = er4[t];
        int j = t >> 5, k0 = (t & 31) << 2;
        uint32_t h01, l01, h23, l23;
        split_pair(v.x, v.y, h01, l01);
        split_pair(v.z, v.w, h23, l23);
        uint32_t off = swz<8>(j, k0);
        *(uint2*)(smem + EOF_EHI + off) = make_uint2(h01, h23);
        *(uint2*)(smem + EOF_ELO + off) = make_uint2(l01, l23);
    }
    for (int t = tid; t < 4096; t += 256)
        ((float4*)(smem + EOF_WHI))[t] = ((const float4*)g_wt)[t];
    __syncthreads();

    int rA = (warp << 4) + (l >> 2), rB = rA + 8;
    bool pA = pmi && (rA < vn), pB = pmi && (rB < vn);
    float acc[16][4];

    // ---- GEMM1: E @ Wl_e ----
#pragma unroll
    for (int t = 0; t < 16; ++t)
#pragma unroll
        for (int e = 0; e < 4; ++e) acc[t][e] = 0.f;
    gemm_split<8,8,8>(sb, EOF_EHI, EOF_ELO, EOF_WHI, EOF_WLO, warp << 4, l, acc);

    // ---- epi1: z -> adj -> s ----
    const float* hpi  = g_hp + (size_t)bi*512;
    const float* hv1A = g_hp + ((size_t)(b*NN + rA))*512 + 128;
    const float* hv1B = g_hp + ((size_t)(b*NN + rB))*512 + 128;
    float pa = 0.f, pb = 0.f;
#pragma unroll
    for (int t = 0; t < 16; ++t) {
        int c = (t << 3) + (q << 1);
        float2 hw = *(const float2*)(hpi + c);
        float2 w2 = *(const float2*)(wl2 + c);
        float2 vA = *(const float2*)(hv1A + c);
        float2 vB = *(const float2*)(hv1B + c);
        pa = fmaf(fmaxf(acc[t][0] + hw.x + vA.x, 0.f), w2.x, pa);
        pa = fmaf(fmaxf(acc[t][1] + hw.y + vA.y, 0.f), w2.y, pa);
        pb = fmaf(fmaxf(acc[t][2] + hw.x + vB.x, 0.f), w2.x, pb);
        pb = fmaf(fmaxf(acc[t][3] + hw.y + vB.y, 0.f), w2.y, pb);
    }
    pa += __shfl_xor_sync(~0u, pa, 1); pa += __shfl_xor_sync(~0u, pa, 2);
    pb += __shfl_xor_sync(~0u, pb, 1); pb += __shfl_xor_sync(~0u, pb, 2);
    float bl2v = bl2[0];
    float sA = pA ? (1.f/(1.f + expf(-(pa + bl2v)))) : 0.f;
    float sB = pB ? (1.f/(1.f + expf(-(pb + bl2v)))) : 0.f;

    // ---- GEMM2: E @ Wm_e ----
    __syncthreads();
    for (int t = tid; t < 4096; t += 256)
        ((float4*)(smem + EOF_WHI))[t] = ((const float4*)(g_wt + 32768))[t];
    __syncthreads();
#pragma unroll
    for (int t = 0; t < 16; ++t)
#pragma unroll
        for (int e = 0; e < 4; ++e) acc[t][e] = 0.f;
    gemm_split<8,8,8>(sb, EOF_EHI, EOF_ELO, EOF_WHI, EOF_WLO, warp << 4, l, acc);

    // ---- epi2: m -> M smem (bf16 split) + g_mbuf (fp32) ----
    const float* hv2A = g_hp + ((size_t)(b*NN + rA))*512 + 384;
    const float* hv2B = g_hp + ((size_t)(b*NN + rB))*512 + 384;
    float* mb = g_mbuf + (size_t)bi*NN*CD;
#pragma unroll
    for (int t = 0; t < 16; ++t) {
        int c = (t << 3) + (q << 1);
        float2 hw = *(const float2*)(hpi + 256 + c);
        float2 vA = *(const float2*)(hv2A + c);
        float2 vB = *(const float2*)(hv2B + c);
        float mA0 = fmaxf(acc[t][0] + hw.x + vA.x, 0.f) * sA;
        float mA1 = fmaxf(acc[t][1] + hw.y + vA.y, 0.f) * sA;
        float mB0 = fmaxf(acc[t][2] + hw.x + vB.x, 0.f) * sB;
        float mB1 = fmaxf(acc[t][3] + hw.y + vB.y, 0.f) * sB;
        *(float2*)(mb + (size_t)rA*CD + c) = make_float2(mA0, mA1);
        *(float2*)(mb + (size_t)rB*CD + c) = make_float2(mB0, mB1);
        uint32_t hA, lA, hB, lB;
        split_pair(mA0, mA1, hA, lA);
        split_pair(mB0, mB1, hB, lB);
        uint32_t oA = swz<8>(rA, c), oB = swz<8>(rB, c);
        *(uint32_t*)(smem + EOF_MHI + oA) = hA;
        *(uint32_t*)(smem + EOF_MLO + oA) = lA;
        *(uint32_t*)(smem + EOF_MHI + oB) = hB;
        *(uint32_t*)(smem + EOF_MLO + oB) = lB;
    }

    // ---- GEMM3: E @ Wu_e ----
    __syncthreads();
    for (int t = tid; t < 4096; t += 256)
        ((float4*)(smem + EOF_WHI))[t] = ((const float4*)(g_wt + 2*32768))[t];
    __syncthreads();
#pragma unroll
    for (int t = 0; t < 16; ++t)
#pragma unroll
        for (int e = 0; e < 4; ++e) acc[t][e] = 0.f;
    gemm_split<8,8,8>(sb, EOF_EHI, EOF_ELO, EOF_WHI, EOF_WLO, warp << 4, l, acc);

    // ---- GEMM4: += M @ Wu_m ----
    __syncthreads();
    for (int t = tid; t < 4096; t += 256)
        ((float4*)(smem + EOF_WHI))[t] = ((const float4*)(g_wt + 3*32768))[t];
    __syncthreads();
    gemm_split<8,8,8>(sb, EOF_MHI, EOF_MLO, EOF_WHI, EOF_WLO, warp << 4, l, acc);

    // ---- epi3: e_new = pm ? relu(acc+bu) : e_old ----
    float* eo = g_e + (size_t)bi*NN*CD;
#pragma unroll
    for (int t = 0; t < 16; ++t) {
        int c = (t << 3) + (q << 1);
        float2 b2 = *(const float2*)(bu + c);
        float eA0, eA1, eB0, eB1;
        if (pA) {
            eA0 = fmaxf(acc[t][0] + b2.x, 0.f);
            eA1 = fmaxf(acc[t][1] + b2.y, 0.f);
        } else {
            uint32_t o = swz<8>(rA, c);
            __nv_bfloat162 hh = *(__nv_bfloat162*)(smem + EOF_EHI + o);
            __nv_bfloat162 ll = *(__nv_bfloat162*)(smem + EOF_ELO + o);
            eA0 = __bfloat162float(hh.x) + __bfloat162float(ll.x);
            eA1 = __bfloat162float(hh.y) + __bfloat162float(ll.y);
        }
        if (pB) {
            eB0 = fmaxf(acc[t][2] + b2.x, 0.f);
            eB1 = fmaxf(acc[t][3] + b2.y, 0.f);
        } else {
            uint32_t o = swz<8>(rB, c);
            __nv_bfloat162 hh = *(__nv_bfloat162*)(smem + EOF_EHI + o);
            __nv_bfloat162 ll = *(__nv_bfloat162*)(smem + EOF_ELO + o);
            eB0 = __bfloat162float(hh.x) + __bfloat162float(ll.x);
            eB1 = __bfloat162float(hh.y) + __bfloat162float(ll.y);
        }
        *(float2*)(eo + (size_t)rA*CD + c) = make_float2(eA0, eA1);
        *(float2*)(eo + (size_t)rB*CD + c) = make_float2(eB0, eB1);
    }
}

// ===================== ms reduce / GRU ========================================
__global__ void k_reduce_ms() {
    int t = blockIdx.x * blockDim.x + threadIdx.x;
    if (t >= BB*NN*CD) return;
    int b  = t / (NN*CD);
    int jk = t % (NN*CD);
    const float* base = g_mbuf + (size_t)b*NN*NN*CD + jk;
    float s = 0.f;
#pragma unroll 4
    for (int i = 0; i < NN; ++i) s += base[(size_t)i*NN*CD];
    g_ms[t] = s;
}

__global__ void k_gru(const int* __restrict__ ev) {
    int t = blockIdx.x * blockDim.x + threadIdx.x;
    if (t >= BB*NN*CD) return;
    int row = t / CD, c = t % CD;
    int b = row / NN, n = row % NN;
    if (n >= ev[b]) return;
    const float* gi = g_gi + (size_t)row*384;
    const float* gh = g_gh + (size_t)row*384;
    float ir = gi[c], iz = gi[CD+c], in = gi[2*CD+c];
    float hr = gh[c], hz = gh[CD+c], hn = gh[2*CD+c];
    float r  = 1.f/(1.f + expf(-(ir+hr)));
    float z  = 1.f/(1.f + expf(-(iz+hz)));
    float nn = tanhf(in + r*hn);
    float hold = g_h[t];
    g_h[t] = (1.f - z)*nn + z*hold;
}

// ===================== readout (HMMA) =========================================
// smem: [Ahi 64K][Alo 64K][Whi 32K][Wlo 32K] = 192KB dynamic
#define ROF_AHI 0u
#define ROF_ALO 65536u
#define ROF_WHI 131072u
#define ROF_WLO 163840u
#define RO_SMEM 196608

__global__ __launch_bounds__(256, 1)
void k_readout_mma(const float* __restrict__ br1, const float* __restrict__ Wr2g,
                   const float* __restrict__ br2, const int* __restrict__ ev,
                   float* __restrict__ out) {
    extern __shared__ char smem[];
    __shared__ float sWr2[2560];
    __shared__ float sBr1[256];
    uint32_t sb = smem_u32(smem);
    int tid = threadIdx.x, warp = tid >> 5, l = tid & 31, q = l & 3;
    int b = blockIdx.y, p0 = blockIdx.x * 128;
    int vn = ev[b];

    for (int t = tid; t < 2560; t += 256) sWr2[t] = Wr2g[t];
    if (tid < 256) sBr1[tid] = br1[tid];

    // gather + split feat [128 pairs][256]
    for (int t = tid; t < 8192; t += 256) {
        int lp = t >> 6, c = (t & 63) << 2;
        int p = p0 + lp; if (p >= PP) p = PP - 1;
        int iu = g_iu[p], ju = g_ju[p];
        const float* src = (c < 128)
            ? &g_e[(((size_t)(b*NN + iu))*NN + ju)*CD + c]
            : &g_e[(((size_t)(b*NN + ju))*NN + iu)*CD + (c - 128)];
        float4 v = *(const float4*)src;
        uint32_t h01, l01, h23, l23;
        split_pair(v.x, v.y, h01, l01);
        split_pair(v.z, v.w, h23, l23);
        uint32_t off = swz<9>(lp, c);
        *(uint2*)(smem + ROF_AHI + off) = make_uint2(h01, h23);
        *(uint2*)(smem + ROF_ALO + off) = make_uint2(l01, l23);
    }

    int rA = (warp << 4) + (l >> 2), rB = rA + 8;
    float outA[10], outB[10];
#pragma unroll
    for (int t5 = 0; t5 < 10; ++t5) { outA[t5] = 0.f; outB[t5] = 0.f; }

    for (int cc = 0; cc < 4; ++cc) {
        __syncthreads();
        for (int t = tid; t < 4096; t += 256)
            ((float4*)(smem + ROF_WHI))[t] = ((const float4*)(g_wr + (size_t)cc*32768))[t];
        __syncthreads();
        float acc[8][4];
#pragma unroll
        for (int t = 0; t < 8; ++t)
#pragma unroll
            for (int e = 0; e < 4; ++e) acc[t][e] = 0.f;
        gemm_split<9,16,4>(sb, ROF_AHI, ROF_ALO, ROF_WHI, ROF_WLO, warp << 4, l, acc);
        // fused second layer
#pragma unroll
        for (int t = 0; t < 8; ++t) {
            int n0 = (cc << 6) + (t << 3) + (q << 1);
#pragma unroll
            for (int e = 0; e < 4; ++e) {
                int n = n0 + (e & 1);
                float h = fmaxf(acc[t][e] + sBr1[n], 0.f);
                float* o = (e < 2) ? outA : outB;
                const float* w = sWr2 + n*10;
#pragma unroll
                for (int t5 = 0; t5 < 10; ++t5) o[t5] = fmaf(h, w[t5], o[t5]);
            }
        }
    }
#pragma unroll
    for (int t5 = 0; t5 < 10; ++t5) {
        outA[t5] += __shfl_xor_sync(~0u, outA[t5], 1);
        outA[t5] += __shfl_xor_sync(~0u, outA[t5], 2);
        outB[t5] += __shfl_xor_sync(~0u, outB[t5], 1);
        outB[t5] += __shfl_xor_sync(~0u, outB[t5], 2);
    }
    if (q == 0) {
#pragma unroll
        for (int h2 = 0; h2 < 2; ++h2) {
            int r = h2 ? rB : rA;
            float* o = h2 ? outB : outA;
            int p = p0 + r;
            if (p < PP) {
                int iu = g_iu[p], ju = g_ju[p];
                if (ju < vn) {
                    int idx = iu*vn - iu*(iu+1)/2 + (ju - iu - 1);
#pragma unroll
                    for (int t5 = 0; t5 < 10; ++t5)
                        out[(((size_t)b*5 + (t5 >> 1))*PP + idx)*2 + (t5 & 1)] = o[t5] + br2[t5];
                }
            }
        }
    }
}

// ===================== host orchestration =====================================
extern "C" void kernel_launch(void* const* d_in, const int* in_sizes, int n_in,
                              void* d_out, int out_size) {
    const int*   edge_ids      = (const int*)  d_in[0];
    const float* node_features = (const float*)d_in[1];
    const int*   ev            = (const int*)  d_in[3];
    const float* emb           = (const float*)d_in[4];
    const float* Wl_e = (const float*)d_in[5];
    const float* Wl_w = (const float*)d_in[6];
    const float* Wl_v = (const float*)d_in[7];
    const float* bl1  = (const float*)d_in[8];
    const float* wl2  = (const float*)d_in[9];
    const float* bl2  = (const float*)d_in[10];
    const float* Wm_w = (const float*)d_in[11];
    const float* Wm_v = (const float*)d_in[12];
    const float* Wm_e = (const float*)d_in[13];
    const float* bm   = (const float*)d_in[14];
    const float* Wu_e = (const float*)d_in[15];
    const float* Wu_m = (const float*)d_in[16];
    const float* bu   = (const float*)d_in[17];
    const float* W_ih = (const float*)d_in[18];
    const float* W_hh = (const float*)d_in[19];
    const float* b_ih = (const float*)d_in[20];
    const float* b_hh = (const float*)d_in[21];
    const float* Wr1  = (const float*)d_in[22];
    const float* br1  = (const float*)d_in[23];
    const float* Wr2  = (const float*)d_in[24];
    const float* br2  = (const float*)d_in[25];

    cudaFuncSetAttribute(k_edge_mma,    cudaFuncAttributeMaxDynamicSharedMemorySize, EDGE_SMEM);
    cudaFuncSetAttribute(k_readout_mma, cudaFuncAttributeMaxDynamicSharedMemorySize, RO_SMEM);

    void *p_h, *p_hp, *p_ms, *p_gi, *p_gh;
    cudaGetSymbolAddress(&p_h,  g_h);
    cudaGetSymbolAddress(&p_hp, g_hp);
    cudaGetSymbolAddress(&p_ms, g_ms);
    cudaGetSymbolAddress(&p_gi, g_gi);
    cudaGetSymbolAddress(&p_gh, g_gh);

    k_init_e<<<65536, 256>>>(edge_ids, emb);
    k_copy_h<<<(BB*NN*CD/4 + 255)/256, 256>>>(node_features);
    k_init_pairs<<<(NN*NN + 255)/256, 256>>>();
    k_prep_w<<<256, 256>>>(Wl_e, Wm_e, Wu_e, Wu_m);
    k_prep_wr<<<256, 256>>>(Wr1);

    for (int r = 0; r < RNDS; ++r) {
        k_rowgemm2<<<dim3(128,1), 256>>>((const float*)p_h, Wl_w, bl1,     (float*)p_hp, 128, 512, 0);
        k_rowgemm2<<<dim3(128,1), 256>>>((const float*)p_h, Wl_v, nullptr, (float*)p_hp, 128, 512, 128);
        k_rowgemm2<<<dim3(128,1), 256>>>((const float*)p_h, Wm_w, bm,      (float*)p_hp, 128, 512, 256);
        k_rowgemm2<<<dim3(128,1), 256>>>((const float*)p_h, Wm_v, nullptr, (float*)p_hp, 128, 512, 384);

        k_edge_mma<<<BB*NN, 256, EDGE_SMEM>>>(wl2, bl2, bu, ev);

        k_reduce_ms<<<(BB*NN*CD + 255)/256, 256>>>();

        k_rowgemm2<<<dim3(128,3), 256>>>((const float*)p_ms, W_ih, b_ih, (float*)p_gi, 384, 384, 0);
        k_rowgemm2<<<dim3(128,3), 256>>>((const float*)p_h,  W_hh, b_hh, (float*)p_gh, 384, 384, 0);
        k_gru<<<(BB*NN*CD + 255)/256, 256>>>(ev);
    }

    cudaMemsetAsync(d_out, 0, (size_t)out_size * sizeof(float));
    k_readout_mma<<<dim3(64, BB), 256, RO_SMEM>>>(br1, Wr2, br2, ev, (float*)d_out);
}

// round 8
// speedup vs baseline: 2.4062x; 1.3680x over previous
#include <cuda_runtime.h>
#include <cuda_bf16.h>
#include <math.h>
#include <stdint.h>

#define BB 32
#define NN 128
#define CD 128
#define PP 8128
#define RNDS 3

// ===================== low-level helpers (base ISA only) ======================
__device__ __forceinline__ uint32_t smem_u32(const void* p) {
    uint32_t a;
    asm("{ .reg .u64 t; cvta.to.shared.u64 t, %1; cvt.u32.u64 %0, t; }" : "=r"(a) : "l"(p));
    return a;
}
__device__ __forceinline__ void ldsm4(uint32_t r[4], uint32_t addr) {
    asm volatile("ldmatrix.sync.aligned.m8n8.x4.shared.b16 {%0,%1,%2,%3}, [%4];"
        : "=r"(r[0]), "=r"(r[1]), "=r"(r[2]), "=r"(r[3]) : "r"(addr));
}
__device__ __forceinline__ void mma_bf16(float c[4], const uint32_t a[4],
                                         uint32_t b0, uint32_t b1) {
    asm volatile("mma.sync.aligned.m16n8k16.row.col.f32.bf16.bf16.f32 "
        "{%0,%1,%2,%3}, {%4,%5,%6,%7}, {%8,%9}, {%0,%1,%2,%3};"
        : "+f"(c[0]), "+f"(c[1]), "+f"(c[2]), "+f"(c[3])
        : "r"(a[0]), "r"(a[1]), "r"(a[2]), "r"(a[3]), "r"(b0), "r"(b1));
}
__device__ __forceinline__ void cp16(uint32_t dst, const void* src) {
    asm volatile("cp.async.cg.shared.global [%0], [%1], 16;" :: "r"(dst), "l"(src));
}
#define CP_COMMIT() asm volatile("cp.async.commit_group;" ::: "memory")
#define CP_WAIT1()  asm volatile("cp.async.wait_group 1;" ::: "memory")
#define CP_WAIT0()  asm volatile("cp.async.wait_group 0;" ::: "memory")

// split (x,y) into packed bf16 hi pair + bf16 residual pair
__device__ __forceinline__ void split_pair(float x, float y, uint32_t& hi, uint32_t& lo) {
    __nv_bfloat16 hx = __float2bfloat16(x), hy = __float2bfloat16(y);
    float rx = x - __bfloat162float(hx), ry = y - __bfloat162float(hy);
    __nv_bfloat16 lx = __float2bfloat16(rx), ly = __float2bfloat16(ry);
    hi = (uint32_t)*(uint16_t*)&hx | ((uint32_t)*(uint16_t*)&hy << 16);
    lo = (uint32_t)*(uint16_t*)&lx | ((uint32_t)*(uint16_t*)&ly << 16);
}
// XOR-swizzled byte offset for bf16 element (r, k); row stride = 1<<SH bytes
template<int SH>
__device__ __host__ __forceinline__ uint32_t swz(int r, int k) {
    return ((uint32_t)r << SH) + ((uint32_t)(((k >> 3) ^ (r & 7))) << 4) + ((uint32_t)(k & 7) << 1);
}

// 3-pass split GEMM over NKS k16-steps: acc += Ahi*Bhi + Alo*Bhi + Ahi*Blo.
// A: row stride 1<<SHA, k-index offset ks0 (k-halves). B: row stride 1<<SHB, local k.
template<int SHA, int SHB, int NKS, int NTP>
__device__ __forceinline__ void gemm_split2(uint32_t sb, uint32_t offA, uint32_t offAlo,
                                            uint32_t bHi, uint32_t bLo,
                                            int mbase, int ks0, int lane, float acc[][4]) {
    int arow = mbase + (lane & 7) + (((lane >> 3) & 1) << 3);
    uint32_t aBase   = sb + offA + ((uint32_t)arow << SHA);
    uint32_t aBaseLo = sb + offAlo + ((uint32_t)arow << SHA);
    int a7 = arow & 7, agrp = (lane >> 4) & 1;
    int brow0 = (lane & 7) + ((lane >> 4) << 3);
    int b7 = lane & 7, bkb = (lane >> 3) & 1;
#pragma unroll
    for (int ks = 0; ks < NKS; ++ks) {
        uint32_t ak = (uint32_t)(((((ks0 + ks) << 1) | agrp) ^ a7) << 4);
        uint32_t Ah[4], Al[4];
        ldsm4(Ah, aBase + ak);
        ldsm4(Al, aBaseLo + ak);
        uint32_t bk = (uint32_t)((((ks << 1) | bkb) ^ b7) << 4);
#pragma unroll
        for (int tp = 0; tp < NTP; ++tp) {
            uint32_t brow = (uint32_t)(brow0 + (tp << 4)) << SHB;
            uint32_t Bh[4], Bl[4];
            ldsm4(Bh, bHi + brow + bk);
            ldsm4(Bl, bLo + brow + bk);
            mma_bf16(acc[2*tp],     Ah, Bh[0], Bh[1]);
            mma_bf16(acc[2*tp],     Al, Bh[0], Bh[1]);
            mma_bf16(acc[2*tp],     Ah, Bl[0], Bl[1]);
            mma_bf16(acc[2*tp + 1], Ah, Bh[2], Bh[3]);
            mma_bf16(acc[2*tp + 1], Al, Bh[2], Bh[3]);
            mma_bf16(acc[2*tp + 1], Ah, Bl[2], Bl[3]);
        }
    }
}

// ===================== persistent device scratch ==============================
__device__ float g_e   [(size_t)BB*NN*NN*CD];
__device__ float g_mbuf[(size_t)BB*NN*NN*CD];
__device__ float g_h   [BB*NN*CD];
__device__ float g_hp  [BB*NN*512];             // [hwl+bl1 | hvl | hwm+bm | hvm]
__device__ float g_ms  [BB*NN*CD];
__device__ float g_gi  [BB*NN*384];
__device__ float g_gh  [BB*NN*384];
__device__ int   g_iu  [PP];
__device__ int   g_ju  [PP];
// 4 edge weights; per matrix: 2 k-halves; per half: [hi 16KB][lo 16KB], swz<7>(n, k&63)
__device__ unsigned short g_wt[4*32768];
// Wr1 in 4 n-chunks; per chunk: 2 k-halves; per half: [hi 16KB][lo 16KB], swz<8>(r, k&127)
__device__ unsigned short g_wr[4*32768];

// ===================== init / prep kernels ====================================
__global__ void k_init_e(const int* __restrict__ eids, const float* __restrict__ emb) {
    size_t t = (size_t)blockIdx.x * blockDim.x + threadIdx.x;
    size_t total = (size_t)BB*NN*NN*(CD/4);
    if (t >= total) return;
    size_t edge = t >> 5;
    int c4 = (int)(t & 31);
    int id = eids[edge];
    ((float4*)g_e)[t] = ((const float4*)emb)[id*(CD/4) + c4];
}

__global__ void k_copy_h(const float* __restrict__ nf) {
    int t = blockIdx.x * blockDim.x + threadIdx.x;
    if (t < BB*NN*CD/4) ((float4*)g_h)[t] = ((const float4*)nf)[t];
}

__global__ void k_prep_w(const float* __restrict__ Wl_e, const float* __restrict__ Wm_e,
                         const float* __restrict__ Wu_e, const float* __restrict__ Wu_m) {
    int idx = blockIdx.x * blockDim.x + threadIdx.x;
    if (idx >= 4*16384) return;
    int m = idx >> 14, r = idx & 16383, n = r >> 7, k = r & 127;
    const float* W = (m == 0) ? Wl_e : (m == 1) ? Wm_e : (m == 2) ? Wu_e : Wu_m;
    float v = W[k*128 + n];
    __nv_bfloat16 hi = __float2bfloat16(v);
    __nv_bfloat16 lo = __float2bfloat16(v - __bfloat162float(hi));
    int half = k >> 6, kk = k & 63;
    uint32_t o = (uint32_t)m*65536u + (uint32_t)half*32768u + swz<7>(n, kk);
    *(__nv_bfloat16*)((char*)g_wt + o) = hi;
    *(__nv_bfloat16*)((char*)g_wt + o + 16384) = lo;
}

// also builds the pair index table
__global__ void k_prep_wr(const float* __restrict__ Wr1) {   // [256 k][256 n]
    int idx = blockIdx.x * blockDim.x + threadIdx.x;
    if (idx < NN*NN) {
        int i = idx / NN, j = idx % NN;
        if (j > i) {
            int p = i*(NN-1) - i*(i-1)/2 + (j - i - 1);
            g_iu[p] = i; g_ju[p] = j;
        }
    }
    if (idx >= 65536) return;
    int n = idx >> 8, k = idx & 255;
    float v = Wr1[k*256 + n];
    __nv_bfloat16 hi = __float2bfloat16(v);
    __nv_bfloat16 lo = __float2bfloat16(v - __bfloat162float(hi));
    int cc = n >> 6, r = n & 63;
    int half = k >> 7, kk = k & 127;
    uint32_t o = (uint32_t)cc*65536u + (uint32_t)half*32768u + swz<8>(r, kk);
    *(__nv_bfloat16*)((char*)g_wr + o) = hi;
    *(__nv_bfloat16*)((char*)g_wr + o + 16384) = lo;
}

// ===================== merged node-level GEMMs ================================
// all four h-projections in one launch: grid (128, 4). Reads g_h DEVICE-SIDE.
__global__ __launch_bounds__(256)
void k_hp(const float* __restrict__ Wl_w, const float* __restrict__ Wl_v,
          const float* __restrict__ Wm_w, const float* __restrict__ Wm_v,
          const float* __restrict__ bl1,  const float* __restrict__ bm) {
    __shared__ float sA[32*128];
    int row0 = blockIdx.x * 32;
    int sel = blockIdx.y;
    const float* W = (sel == 0) ? Wl_w : (sel == 1) ? Wl_v : (sel == 2) ? Wm_w : Wm_v;
    const float* bias = (sel == 0) ? bl1 : (sel == 2) ? bm : nullptr;
    int colOff = sel << 7;
    for (int t = threadIdx.x; t < 1024; t += 256)
        ((float4*)sA)[t] = ((const float4*)(g_h + (size_t)row0*128))[t];
    __syncthreads();
    int col = threadIdx.x & 127;
    int half = threadIdx.x >> 7;
    float acc[16];
#pragma unroll
    for (int r = 0; r < 16; ++r) acc[r] = 0.f;
    const float* sAr = sA + half*16*128;
    for (int k = 0; k < 128; ++k) {
        float w = W[(size_t)k*128 + col];
#pragma unroll
        for (int r = 0; r < 16; ++r) acc[r] = fmaf(sAr[r*128 + k], w, acc[r]);
    }
    float bv = bias ? bias[col] : 0.f;
    for (int r = 0; r < 16; ++r)
        g_hp[(size_t)(row0 + half*16 + r)*512 + colOff + col] = acc[r] + bv;
}

// gi and gh in one launch: grid (128, 3, 2)
__global__ __launch_bounds__(256)
void k_gig(const float* __restrict__ Wih, const float* __restrict__ Whh,
           const float* __restrict__ bih, const float* __restrict__ bhh) {
    __shared__ float sA[32*128];
    int row0 = blockIdx.x * 32;
    int c0 = blockIdx.y * 128;
    int z = blockIdx.z;
    const float* A = z ? g_h : g_ms;
    const float* W = z ? Whh : Wih;
    const float* bias = z ? bhh : bih;
    float* C = z ? g_gh : g_gi;
    for (int t = threadIdx.x; t < 1024; t += 256)
        ((float4*)sA)[t] = ((const float4*)(A + (size_t)row0*128))[t];
    __syncthreads();
    int col = c0 + (threadIdx.x & 127);
    int half = threadIdx.x >> 7;
    float acc[16];
#pragma unroll
    for (int r = 0; r < 16; ++r) acc[r] = 0.f;
    const float* sAr = sA + half*16*128;
    for (int k = 0; k < 128; ++k) {
        float w = W[(size_t)k*384 + col];
#pragma unroll
        for (int r = 0; r < 16; ++r) acc[r] = fmaf(sAr[r*128 + k], w, acc[r]);
    }
    float bv = bias[col];
    for (int r = 0; r < 16; ++r)
        C[(size_t)(row0 + half*16 + r)*384 + col] = acc[r] + bv;
}

// ===================== fused edge kernel (HMMA, cp.async pipelined) ===========
// smem: [Ehi 32K][Elo 32K][Mhi 32K][Mlo 32K][Wbuf0 32K][Wbuf1 32K] = 192KB
#define EOF_EHI 0u
#define EOF_ELO 32768u
#define EOF_MHI 65536u
#define EOF_MLO 98304u
#define EOF_W0  131072u
#define EOF_W1  163840u
#define EDGE_SMEM 196608

__global__ __launch_bounds__(256, 1)
void k_edge_mma(const float* __restrict__ wl2, const float* __restrict__ bl2,
                const float* __restrict__ bu,  const int* __restrict__ ev) {
    extern __shared__ char smem[];
    uint32_t sb = smem_u32(smem);
    int tid = threadIdx.x, warp = tid >> 5, l = tid & 31, q = l & 3;
    int bi = blockIdx.x, b = bi >> 7, i = bi & 127;
    int vn = ev[b];
    bool pmi = (i < vn);
    const char* wsrc = (const char*)g_wt;

    // prologue: async-prefetch W chunks 0,1 (Wl_e k-halves)
#pragma unroll
    for (int t = 0; t < 8; ++t)
        cp16(sb + EOF_W0 + (uint32_t)(tid + t*256)*16u, wsrc + (size_t)(tid + t*256)*16);
    CP_COMMIT();
#pragma unroll
    for (int t = 0; t < 8; ++t)
        cp16(sb + EOF_W1 + (uint32_t)(tid + t*256)*16u, wsrc + 32768 + (size_t)(tid + t*256)*16);
    CP_COMMIT();

    // load + split E tile (overlaps with the async W copies)
    const float4* er4 = (const float4*)(g_e + (size_t)bi*NN*CD);
    for (int t = tid; t < 4096; t += 256) {
        float4 v = er4[t];
        int j = t >> 5, k0 = (t & 31) << 2;
        uint32_t h01, l01, h23, l23;
        split_pair(v.x, v.y, h01, l01);
        split_pair(v.z, v.w, h23, l23);
        uint32_t off = swz<8>(j, k0);
        *(uint2*)(smem + EOF_EHI + off) = make_uint2(h01, h23);
        *(uint2*)(smem + EOF_ELO + off) = make_uint2(l01, l23);
    }

    int rA = (warp << 4) + (l >> 2), rB = rA + 8;
    bool pA = pmi && (rA < vn), pB = pmi && (rB < vn);
    const float* hpi = g_hp + (size_t)bi*512;
    float acc[16][4];
    float sSigA = 0.f, sSigB = 0.f;

    // pipelined mainloop: chunk c = (GEMM c>>1, k-half c&1)
#pragma unroll
    for (int c = 0; c < 8; ++c) {
        if (c == 7) { CP_WAIT0(); } else { CP_WAIT1(); }
        __syncthreads();
        if (c == 0 || c == 2 || c == 4) {
#pragma unroll
            for (int t = 0; t < 16; ++t)
#pragma unroll
                for (int e = 0; e < 4; ++e) acc[t][e] = 0.f;
        }
        uint32_t wb = sb + EOF_W0 + (uint32_t)(c & 1)*32768u;
        uint32_t offA  = (c >= 6) ? EOF_MHI : EOF_EHI;
        uint32_t offAl = (c >= 6) ? EOF_MLO : EOF_ELO;
        gemm_split2<8,7,4,8>(sb, offA, offAl, wb, wb + 16384u, warp << 4, (c & 1)*4, l, acc);

        if (c == 1) {
            // epi1: z -> adj -> sigmoid
            const float* hv1A = g_hp + ((size_t)(b*NN + rA))*512 + 128;
            const float* hv1B = g_hp + ((size_t)(b*NN + rB))*512 + 128;
            float pa = 0.f, pb = 0.f;
#pragma unroll
            for (int t = 0; t < 16; ++t) {
                int cc = (t << 3) + (q << 1);
                float2 hw = *(const float2*)(hpi + cc);
                float2 w2 = *(const float2*)(wl2 + cc);
                float2 vA = *(const float2*)(hv1A + cc);
                float2 vB = *(const float2*)(hv1B + cc);
                pa = fmaf(fmaxf(acc[t][0] + hw.x + vA.x, 0.f), w2.x, pa);
                pa = fmaf(fmaxf(acc[t][1] + hw.y + vA.y, 0.f), w2.y, pa);
                pb = fmaf(fmaxf(acc[t][2] + hw.x + vB.x, 0.f), w2.x, pb);
                pb = fmaf(fmaxf(acc[t][3] + hw.y + vB.y, 0.f), w2.y, pb);
            }
            pa += __shfl_xor_sync(~0u, pa, 1); pa += __shfl_xor_sync(~0u, pa, 2);
            pb += __shfl_xor_sync(~0u, pb, 1); pb += __shfl_xor_sync(~0u, pb, 2);
            float bl2v = bl2[0];
            sSigA = pA ? (1.f/(1.f + expf(-(pa + bl2v)))) : 0.f;
            sSigB = pB ? (1.f/(1.f + expf(-(pb + bl2v)))) : 0.f;
        }
        if (c == 3) {
            // epi2: m -> sM (bf16 split) + g_mbuf (fp32)
            const float* hv2A = g_hp + ((size_t)(b*NN + rA))*512 + 384;
            const float* hv2B = g_hp + ((size_t)(b*NN + rB))*512 + 384;
            float* mb = g_mbuf + (size_t)bi*NN*CD;
#pragma unroll
            for (int t = 0; t < 16; ++t) {
                int cc = (t << 3) + (q << 1);
                float2 hw = *(const float2*)(hpi + 256 + cc);
                float2 vA = *(const float2*)(hv2A + cc);
                float2 vB = *(const float2*)(hv2B + cc);
                float mA0 = fmaxf(acc[t][0] + hw.x + vA.x, 0.f) * sSigA;
                float mA1 = fmaxf(acc[t][1] + hw.y + vA.y, 0.f) * sSigA;
                float mB0 = fmaxf(acc[t][2] + hw.x + vB.x, 0.f) * sSigB;
                float mB1 = fmaxf(acc[t][3] + hw.y + vB.y, 0.f) * sSigB;
                *(float2*)(mb + (size_t)rA*CD + cc) = make_float2(mA0, mA1);
                *(float2*)(mb + (size_t)rB*CD + cc) = make_float2(mB0, mB1);
                uint32_t hA, lA, hB, lB;
                split_pair(mA0, mA1, hA, lA);
                split_pair(mB0, mB1, hB, lB);
                uint32_t oA = swz<8>(rA, cc), oB = swz<8>(rB, cc);
                *(uint32_t*)(smem + EOF_MHI + oA) = hA;
                *(uint32_t*)(smem + EOF_MLO + oA) = lA;
                *(uint32_t*)(smem + EOF_MHI + oB) = hB;
                *(uint32_t*)(smem + EOF_MLO + oB) = lB;
            }
        }
        __syncthreads();
        if (c + 2 < 8) {
            uint32_t db = sb + EOF_W0 + (uint32_t)(c & 1)*32768u;
            const char* src = wsrc + (size_t)(c + 2)*32768;
#pragma unroll
            for (int t = 0; t < 8; ++t)
                cp16(db + (uint32_t)(tid + t*256)*16u, src + (size_t)(tid + t*256)*16);
            CP_COMMIT();
        }
    }

    // epi3: e_new = pm ? relu(acc + bu) : e_old
    float* eo = g_e + (size_t)bi*NN*CD;
#pragma unroll
    for (int t = 0; t < 16; ++t) {
        int cc = (t << 3) + (q << 1);
        float2 b2 = *(const float2*)(bu + cc);
        float eA0, eA1, eB0, eB1;
        if (pA) {
            eA0 = fmaxf(acc[t][0] + b2.x, 0.f);
            eA1 = fmaxf(acc[t][1] + b2.y, 0.f);
        } else {
            uint32_t o = swz<8>(rA, cc);
            __nv_bfloat162 hh = *(__nv_bfloat162*)(smem + EOF_EHI + o);
            __nv_bfloat162 ll = *(__nv_bfloat162*)(smem + EOF_ELO + o);
            eA0 = __bfloat162float(hh.x) + __bfloat162float(ll.x);
            eA1 = __bfloat162float(hh.y) + __bfloat162float(ll.y);
        }
        if (pB) {
            eB0 = fmaxf(acc[t][2] + b2.x, 0.f);
            eB1 = fmaxf(acc[t][3] + b2.y, 0.f);
        } else {
            uint32_t o = swz<8>(rB, cc);
            __nv_bfloat162 hh = *(__nv_bfloat162*)(smem + EOF_EHI + o);
            __nv_bfloat162 ll = *(__nv_bfloat162*)(smem + EOF_ELO + o);
            eB0 = __bfloat162float(hh.x) + __bfloat162float(ll.x);
            eB1 = __bfloat162float(hh.y) + __bfloat162float(ll.y);
        }
        *(float2*)(eo + (size_t)rA*CD + cc) = make_float2(eA0, eA1);
        *(float2*)(eo + (size_t)rB*CD + cc) = make_float2(eB0, eB1);
    }
}

// ===================== ms reduce / GRU ========================================
__global__ void k_reduce_ms() {
    int t = blockIdx.x * blockDim.x + threadIdx.x;
    if (t >= BB*NN*CD) return;
    int b  = t / (NN*CD);
    int jk = t % (NN*CD);
    const float* base = g_mbuf + (size_t)b*NN*NN*CD + jk;
    float s = 0.f;
#pragma unroll 4
    for (int i = 0; i < NN; ++i) s += base[(size_t)i*NN*CD];
    g_ms[t] = s;
}

__global__ void k_gru(const int* __restrict__ ev) {
    int t = blockIdx.x * blockDim.x + threadIdx.x;
    if (t >= BB*NN*CD) return;
    int row = t / CD, c = t % CD;
    int b = row / NN, n = row % NN;
    if (n >= ev[b]) return;
    const float* gi = g_gi + (size_t)row*384;
    const float* gh = g_gh + (size_t)row*384;
    float ir = gi[c], iz = gi[CD+c], in = gi[2*CD+c];
    float hr = gh[c], hz = gh[CD+c], hn = gh[2*CD+c];
    float r  = 1.f/(1.f + expf(-(ir+hr)));
    float z  = 1.f/(1.f + expf(-(iz+hz)));
    float nn = tanhf(in + r*hn);
    float hold = g_h[t];
    g_h[t] = (1.f - z)*nn + z*hold;
}

// ===================== readout (HMMA, cp.async pipelined) =====================
// smem: [Ahi 64K][Alo 64K][Wbuf0 32K][Wbuf1 32K] = 192KB dynamic
#define ROF_AHI 0u
#define ROF_ALO 65536u
#define ROF_W0  131072u
#define ROF_W1  163840u
#define RO_SMEM 196608

__global__ __launch_bounds__(256, 1)
void k_readout_mma(const float* __restrict__ br1, const float* __restrict__ Wr2g,
                   const float* __restrict__ br2, const int* __restrict__ ev,
                   float* __restrict__ out) {
    extern __shared__ char smem[];
    __shared__ float sWr2[2560];
    __shared__ float sBr1[256];
    uint32_t sb = smem_u32(smem);
    int tid = threadIdx.x, warp = tid >> 5, l = tid & 31, q = l & 3;
    int b = blockIdx.y, p0 = blockIdx.x * 128;
    int vn = ev[b];
    const char* wsrc = (const char*)g_wr;

    // prologue W prefetch
#pragma unroll
    for (int t = 0; t < 8; ++t)
        cp16(sb + ROF_W0 + (uint32_t)(tid + t*256)*16u, wsrc + (size_t)(tid + t*256)*16);
    CP_COMMIT();
#pragma unroll
    for (int t = 0; t < 8; ++t)
        cp16(sb + ROF_W1 + (uint32_t)(tid + t*256)*16u, wsrc + 32768 + (size_t)(tid + t*256)*16);
    CP_COMMIT();

    for (int t = tid; t < 2560; t += 256) sWr2[t] = Wr2g[t];
    if (tid < 256) sBr1[tid] = br1[tid];

    // gather + split feat [128 pairs][256]
    for (int t = tid; t < 8192; t += 256) {
        int lp = t >> 6, c = (t & 63) << 2;
        int p = p0 + lp; if (p >= PP) p = PP - 1;
        int iu = g_iu[p], ju = g_ju[p];
        const float* src = (c < 128)
            ? &g_e[(((size_t)(b*NN + iu))*NN + ju)*CD + c]
            : &g_e[(((size_t)(b*NN + ju))*NN + iu)*CD + (c - 128)];
        float4 v = *(const float4*)src;
        uint32_t h01, l01, h23, l23;
        split_pair(v.x, v.y, h01, l01);
        split_pair(v.z, v.w, h23, l23);
        uint32_t off = swz<9>(lp, c);
        *(uint2*)(smem + ROF_AHI + off) = make_uint2(h01, h23);
        *(uint2*)(smem + ROF_ALO + off) = make_uint2(l01, l23);
    }

    int rA = (warp << 4) + (l >> 2), rB = rA + 8;
    float outA[10], outB[10];
#pragma unroll
    for (int t5 = 0; t5 < 10; ++t5) { outA[t5] = 0.f; outB[t5] = 0.f; }
    float acc[8][4];

#pragma unroll
    for (int c = 0; c < 8; ++c) {
        if (c == 7) { CP_WAIT0(); } else { CP_WAIT1(); }
        __syncthreads();
        if ((c & 1) == 0) {
#pragma unroll
            for (int t = 0; t < 8; ++t)
#pragma unroll
                for (int e = 0; e < 4; ++e) acc[t][e] = 0.f;
        }
        uint32_t wb = sb + ROF_W0 + (uint32_t)(c & 1)*32768u;
        gemm_split2<9,8,8,4>(sb, ROF_AHI, ROF_ALO, wb, wb + 16384u, warp << 4, (c & 1)*8, l, acc);
        if (c & 1) {
            int cc = c >> 1;
#pragma unroll
            for (int t = 0; t < 8; ++t) {
                int n0 = (cc << 6) + (t << 3) + (q << 1);
#pragma unroll
                for (int e = 0; e < 4; ++e) {
                    int n = n0 + (e & 1);
                    float h = fmaxf(acc[t][e] + sBr1[n], 0.f);
                    float* o = (e < 2) ? outA : outB;
                    const float* w = sWr2 + n*10;
#pragma unroll
                    for (int t5 = 0; t5 < 10; ++t5) o[t5] = fmaf(h, w[t5], o[t5]);
                }
            }
        }
        __syncthreads();
        if (c + 2 < 8) {
            uint32_t db = sb + ROF_W0 + (uint32_t)(c & 1)*32768u;
            const char* src = wsrc + (size_t)(c + 2)*32768;
#pragma unroll
            for (int t = 0; t < 8; ++t)
                cp16(db + (uint32_t)(tid + t*256)*16u, src + (size_t)(tid + t*256)*16);
            CP_COMMIT();
        }
    }

#pragma unroll
    for (int t5 = 0; t5 < 10; ++t5) {
        outA[t5] += __shfl_xor_sync(~0u, outA[t5], 1);
        outA[t5] += __shfl_xor_sync(~0u, outA[t5], 2);
        outB[t5] += __shfl_xor_sync(~0u, outB[t5], 1);
        outB[t5] += __shfl_xor_sync(~0u, outB[t5], 2);
    }
    if (q == 0) {
#pragma unroll
        for (int h2 = 0; h2 < 2; ++h2) {
            int r = h2 ? rB : rA;
            float* o = h2 ? outB : outA;
            int p = p0 + r;
            if (p < PP) {
                int iu = g_iu[p], ju = g_ju[p];
                if (ju < vn) {
                    int idx = iu*vn - iu*(iu+1)/2 + (ju - iu - 1);
#pragma unroll
                    for (int t5 = 0; t5 < 10; ++t5)
                        out[(((size_t)b*5 + (t5 >> 1))*PP + idx)*2 + (t5 & 1)] = o[t5] + br2[t5];
                }
            }
        }
    }
}

// ===================== host orchestration =====================================
extern "C" void kernel_launch(void* const* d_in, const int* in_sizes, int n_in,
                              void* d_out, int out_size) {
    const int*   edge_ids      = (const int*)  d_in[0];
    const float* node_features = (const float*)d_in[1];
    const int*   ev            = (const int*)  d_in[3];
    const float* emb           = (const float*)d_in[4];
    const float* Wl_e = (const float*)d_in[5];
    const float* Wl_w = (const float*)d_in[6];
    const float* Wl_v = (const float*)d_in[7];
    const float* bl1  = (const float*)d_in[8];
    const float* wl2  = (const float*)d_in[9];
    const float* bl2  = (const float*)d_in[10];
    const float* Wm_w = (const float*)d_in[11];
    const float* Wm_v = (const float*)d_in[12];
    const float* Wm_e = (const float*)d_in[13];
    const float* bm   = (const float*)d_in[14];
    const float* Wu_e = (const float*)d_in[15];
    const float* Wu_m = (const float*)d_in[16];
    const float* bu   = (const float*)d_in[17];
    const float* W_ih = (const float*)d_in[18];
    const float* W_hh = (const float*)d_in[19];
    const float* b_ih = (const float*)d_in[20];
    const float* b_hh = (const float*)d_in[21];
    const float* Wr1  = (const float*)d_in[22];
    const float* br1  = (const float*)d_in[23];
    const float* Wr2  = (const float*)d_in[24];
    const float* br2  = (const float*)d_in[25];

    cudaFuncSetAttribute(k_edge_mma,    cudaFuncAttributeMaxDynamicSharedMemorySize, EDGE_SMEM);
    cudaFuncSetAttribute(k_readout_mma, cudaFuncAttributeMaxDynamicSharedMemorySize, RO_SMEM);

    // launches 0..3: init/prep (so launch #5 = first k_edge_mma for ncu -s 5 -c 1)
    k_init_e<<<65536, 256>>>(edge_ids, emb);
    k_copy_h<<<(BB*NN*CD/4 + 255)/256, 256>>>(node_features);
    k_prep_w<<<256, 256>>>(Wl_e, Wm_e, Wu_e, Wu_m);
    k_prep_wr<<<256, 256>>>(Wr1);

    for (int r = 0; r < RNDS; ++r) {
        k_hp<<<dim3(128, 4), 256>>>(Wl_w, Wl_v, Wm_w, Wm_v, bl1, bm);
        k_edge_mma<<<BB*NN, 256, EDGE_SMEM>>>(wl2, bl2, bu, ev);
        k_reduce_ms<<<(BB*NN*CD + 255)/256, 256>>>();
        k_gig<<<dim3(128, 3, 2), 256>>>(W_ih, W_hh, b_ih, b_hh);
        k_gru<<<(BB*NN*CD + 255)/256, 256>>>(ev);
    }

    cudaMemsetAsync(d_out, 0, (size_t)out_size * sizeof(float));
    k_readout_mma<<<dim3(64, BB), 256, RO_SMEM>>>(br1, Wr2, br2, ev, (float*)d_out);
}

// round 9
// speedup vs baseline: 3.2220x; 1.3391x over previous
#include <cuda_runtime.h>
#include <cuda_bf16.h>
#include <math.h>
#include <stdint.h>

#define BB 32
#define NN 128
#define CD 128
#define PP 8128
#define RNDS 3

// ===================== low-level helpers (base ISA only) ======================
__device__ __forceinline__ uint32_t smem_u32(const void* p) {
    uint32_t a;
    asm("{ .reg .u64 t; cvta.to.shared.u64 t, %1; cvt.u32.u64 %0, t; }" : "=r"(a) : "l"(p));
    return a;
}
__device__ __forceinline__ void ldsm4(uint32_t r[4], uint32_t addr) {
    asm volatile("ldmatrix.sync.aligned.m8n8.x4.shared.b16 {%0,%1,%2,%3}, [%4];"
        : "=r"(r[0]), "=r"(r[1]), "=r"(r[2]), "=r"(r[3]) : "r"(addr));
}
__device__ __forceinline__ void mma_bf16(float c[4], const uint32_t a[4],
                                         uint32_t b0, uint32_t b1) {
    asm volatile("mma.sync.aligned.m16n8k16.row.col.f32.bf16.bf16.f32 "
        "{%0,%1,%2,%3}, {%4,%5,%6,%7}, {%8,%9}, {%0,%1,%2,%3};"
        : "+f"(c[0]), "+f"(c[1]), "+f"(c[2]), "+f"(c[3])
        : "r"(a[0]), "r"(a[1]), "r"(a[2]), "r"(a[3]), "r"(b0), "r"(b1));
}
__device__ __forceinline__ void cp16(uint32_t dst, const void* src) {
    asm volatile("cp.async.cg.shared.global [%0], [%1], 16;" :: "r"(dst), "l"(src));
}
#define CP_COMMIT() asm volatile("cp.async.commit_group;" ::: "memory")
#define CP_WAIT1()  asm volatile("cp.async.wait_group 1;" ::: "memory")
#define CP_WAIT0()  asm volatile("cp.async.wait_group 0;" ::: "memory")

// split (x,y) into packed bf16 hi pair + bf16 residual pair
__device__ __forceinline__ void split_pair(float x, float y, uint32_t& hi, uint32_t& lo) {
    __nv_bfloat16 hx = __float2bfloat16(x), hy = __float2bfloat16(y);
    float rx = x - __bfloat162float(hx), ry = y - __bfloat162float(hy);
    __nv_bfloat16 lx = __float2bfloat16(rx), ly = __float2bfloat16(ry);
    hi = (uint32_t)*(uint16_t*)&hx | ((uint32_t)*(uint16_t*)&hy << 16);
    lo = (uint32_t)*(uint16_t*)&lx | ((uint32_t)*(uint16_t*)&ly << 16);
}
// XOR-swizzled byte offset for bf16 element (r, k); row stride = 1<<SH bytes
template<int SH>
__device__ __host__ __forceinline__ uint32_t swz(int r, int k) {
    return ((uint32_t)r << SH) + ((uint32_t)(((k >> 3) ^ (r & 7))) << 4) + ((uint32_t)(k & 7) << 1);
}

// 3-pass split GEMM over NKS k16-steps: acc += Ahi*Bhi + Alo*Bhi + Ahi*Blo.
template<int SHA, int SHB, int NKS, int NTP>
__device__ __forceinline__ void gemm_split2(uint32_t sb, uint32_t offA, uint32_t offAlo,
                                            uint32_t bHi, uint32_t bLo,
                                            int mbase, int ks0, int lane, float acc[][4]) {
    int arow = mbase + (lane & 7) + (((lane >> 3) & 1) << 3);
    uint32_t aBase   = sb + offA + ((uint32_t)arow << SHA);
    uint32_t aBaseLo = sb + offAlo + ((uint32_t)arow << SHA);
    int a7 = arow & 7, agrp = (lane >> 4) & 1;
    int brow0 = (lane & 7) + ((lane >> 4) << 3);
    int b7 = lane & 7, bkb = (lane >> 3) & 1;
#pragma unroll
    for (int ks = 0; ks < NKS; ++ks) {
        uint32_t ak = (uint32_t)(((((ks0 + ks) << 1) | agrp) ^ a7) << 4);
        uint32_t Ah[4], Al[4];
        ldsm4(Ah, aBase + ak);
        ldsm4(Al, aBaseLo + ak);
        uint32_t bk = (uint32_t)((((ks << 1) | bkb) ^ b7) << 4);
#pragma unroll
        for (int tp = 0; tp < NTP; ++tp) {
            uint32_t brow = (uint32_t)(brow0 + (tp << 4)) << SHB;
            uint32_t Bh[4], Bl[4];
            ldsm4(Bh, bHi + brow + bk);
            ldsm4(Bl, bLo + brow + bk);
            mma_bf16(acc[2*tp],     Ah, Bh[0], Bh[1]);
            mma_bf16(acc[2*tp],     Al, Bh[0], Bh[1]);
            mma_bf16(acc[2*tp],     Ah, Bl[0], Bl[1]);
            mma_bf16(acc[2*tp + 1], Ah, Bh[2], Bh[3]);
            mma_bf16(acc[2*tp + 1], Al, Bh[2], Bh[3]);
            mma_bf16(acc[2*tp + 1], Ah, Bl[2], Bl[3]);
        }
    }
}

// ===================== persistent device scratch ==============================
// edge state: per (b,i) tile 64KB = [hi 32768B swizzled swz<8>(j,k)][lo 32768B]
__device__ unsigned short g_ebf[(size_t)BB*NN*32768];
__device__ float g_mbuf[(size_t)BB*NN*NN*CD];
__device__ float g_h   [BB*NN*CD];
__device__ float g_hp  [BB*NN*512];             // [hwl+bl1 | hvl | hwm+bm | hvm]
__device__ float g_ms  [BB*NN*CD];
__device__ float g_gi  [BB*NN*384];
__device__ float g_gh  [BB*NN*384];
__device__ int   g_iu  [PP];
__device__ int   g_ju  [PP];
// 4 edge weights; per matrix: 2 k-halves; per half: [hi 16KB][lo 16KB], swz<7>(n, k&63)
__device__ unsigned short g_wt[4*32768];
// Wr1 in 4 n-chunks; per chunk: 2 k-halves; per half: [hi 16KB][lo 16KB], swz<8>(r, k&127)
__device__ unsigned short g_wr[4*32768];

// ===================== merged prep kernel (weights + pair table) ==============
__global__ void k_prep(const float* __restrict__ Wl_e, const float* __restrict__ Wm_e,
                       const float* __restrict__ Wu_e, const float* __restrict__ Wu_m,
                       const float* __restrict__ Wr1) {
    int idx = blockIdx.x * blockDim.x + threadIdx.x;    // 0..131071
    if (idx < NN*NN) {
        int i = idx / NN, j = idx % NN;
        if (j > i) {
            int p = i*(NN-1) - i*(i-1)/2 + (j - i - 1);
            g_iu[p] = i; g_ju[p] = j;
        }
    }
    if (idx < 65536) {
        int m = idx >> 14, r = idx & 16383, n = r >> 7, k = r & 127;
        const float* W = (m == 0) ? Wl_e : (m == 1) ? Wm_e : (m == 2) ? Wu_e : Wu_m;
        float v = W[k*128 + n];
        __nv_bfloat16 hi = __float2bfloat16(v);
        __nv_bfloat16 lo = __float2bfloat16(v - __bfloat162float(hi));
        uint32_t o = (uint32_t)m*65536u + (uint32_t)(k >> 6)*32768u + swz<7>(n, k & 63);
        *(__nv_bfloat16*)((char*)g_wt + o) = hi;
        *(__nv_bfloat16*)((char*)g_wt + o + 16384) = lo;
    } else {
        int r2 = idx - 65536;                           // 0..65535
        int n = r2 >> 8, k = r2 & 255;
        float v = Wr1[k*256 + n];
        __nv_bfloat16 hi = __float2bfloat16(v);
        __nv_bfloat16 lo = __float2bfloat16(v - __bfloat162float(hi));
        uint32_t o = (uint32_t)(n >> 6)*65536u + (uint32_t)(k >> 7)*32768u + swz<8>(n & 63, k & 127);
        *(__nv_bfloat16*)((char*)g_wr + o) = hi;
        *(__nv_bfloat16*)((char*)g_wr + o + 16384) = lo;
    }
}

// ===================== node projections (+ first-round h copy) ================
__global__ __launch_bounds__(256)
void k_hp(const float* __restrict__ nf,
          const float* __restrict__ Wl_w, const float* __restrict__ Wl_v,
          const float* __restrict__ Wm_w, const float* __restrict__ Wm_v,
          const float* __restrict__ bl1,  const float* __restrict__ bm, int first) {
    __shared__ float sA[32*128];
    int row0 = blockIdx.x * 32;
    int sel = blockIdx.y;
    const float* W = (sel == 0) ? Wl_w : (sel == 1) ? Wl_v : (sel == 2) ? Wm_w : Wm_v;
    const float* bias = (sel == 0) ? bl1 : (sel == 2) ? bm : nullptr;
    int colOff = sel << 7;
    const float* hsrc = first ? nf : g_h;
    for (int t = threadIdx.x; t < 1024; t += 256) {
        float4 v = ((const float4*)(hsrc + (size_t)row0*128))[t];
        ((float4*)sA)[t] = v;
        if (first && sel == 0) ((float4*)(g_h + (size_t)row0*128))[t] = v;
    }
    __syncthreads();
    int col = threadIdx.x & 127;
    int half = threadIdx.x >> 7;
    float acc[16];
#pragma unroll
    for (int r = 0; r < 16; ++r) acc[r] = 0.f;
    const float* sAr = sA + half*16*128;
    for (int k = 0; k < 128; ++k) {
        float w = W[(size_t)k*128 + col];
#pragma unroll
        for (int r = 0; r < 16; ++r) acc[r] = fmaf(sAr[r*128 + k], w, acc[r]);
    }
    float bv = bias ? bias[col] : 0.f;
    for (int r = 0; r < 16; ++r)
        g_hp[(size_t)(row0 + half*16 + r)*512 + colOff + col] = acc[r] + bv;
}

// ===================== edge-state init (emb gather, bf16 split, swizzled) =====
__global__ void k_init_e(const int* __restrict__ eids, const float* __restrict__ emb) {
    size_t t = (size_t)blockIdx.x * blockDim.x + threadIdx.x;   // B*N*N*32
    if (t >= (size_t)BB*NN*NN*32) return;
    size_t edge = t >> 5;
    int c4 = (int)(t & 31);
    int id = eids[edge];
    float4 v = ((const float4*)emb)[id*32 + c4];
    int j = (int)(edge & 127);
    size_t tile = edge >> 7;
    uint32_t h01, l01, h23, l23;
    split_pair(v.x, v.y, h01, l01);
    split_pair(v.z, v.w, h23, l23);
    char* base = (char*)g_ebf + tile*65536;
    uint32_t o = swz<8>(j, c4 << 2);
    *(uint2*)(base + o)         = make_uint2(h01, h23);
    *(uint2*)(base + 32768 + o) = make_uint2(l01, l23);
}

// gi and gh in one launch: grid (128, 3, 2)
__global__ __launch_bounds__(256)
void k_gig(const float* __restrict__ Wih, const float* __restrict__ Whh,
           const float* __restrict__ bih, const float* __restrict__ bhh) {
    __shared__ float sA[32*128];
    int row0 = blockIdx.x * 32;
    int c0 = blockIdx.y * 128;
    int z = blockIdx.z;
    const float* A = z ? g_h : g_ms;
    const float* W = z ? Whh : Wih;
    const float* bias = z ? bhh : bih;
    float* C = z ? g_gh : g_gi;
    for (int t = threadIdx.x; t < 1024; t += 256)
        ((float4*)sA)[t] = ((const float4*)(A + (size_t)row0*128))[t];
    __syncthreads();
    int col = c0 + (threadIdx.x & 127);
    int half = threadIdx.x >> 7;
    float acc[16];
#pragma unroll
    for (int r = 0; r < 16; ++r) acc[r] = 0.f;
    const float* sAr = sA + half*16*128;
    for (int k = 0; k < 128; ++k) {
        float w = W[(size_t)k*384 + col];
#pragma unroll
        for (int r = 0; r < 16; ++r) acc[r] = fmaf(sAr[r*128 + k], w, acc[r]);
    }
    float bv = bias[col];
    for (int r = 0; r < 16; ++r)
        C[(size_t)(row0 + half*16 + r)*384 + col] = acc[r] + bv;
}

// ===================== fused edge kernel (HMMA, cp.async pipelined) ===========
// smem: [Ehi 32K][Elo 32K][Mhi 32K][Mlo 32K][Wbuf0 32K][Wbuf1 32K] = 192KB
#define EOF_EHI 0u
#define EOF_ELO 32768u
#define EOF_MHI 65536u
#define EOF_MLO 98304u
#define EOF_W0  131072u
#define EOF_W1  163840u
#define EDGE_SMEM 196608

__global__ __launch_bounds__(256, 1)
void k_edge_mma(const float* __restrict__ wl2, const float* __restrict__ bl2,
                const float* __restrict__ bu,  const int* __restrict__ ev) {
    extern __shared__ char smem[];
    uint32_t sb = smem_u32(smem);
    int tid = threadIdx.x, warp = tid >> 5, l = tid & 31, q = l & 3;
    int bi = blockIdx.x, b = bi >> 7, i = bi & 127;
    int vn = ev[b];
    bool pmi = (i < vn);
    const char* wsrc = (const char*)g_wt;
    char* eb = (char*)g_ebf + (size_t)bi*65536;

    // group 0: E tile (hi+lo contiguous 64KB, already swizzled)
#pragma unroll
    for (int t = 0; t < 16; ++t)
        cp16(sb + EOF_EHI + (uint32_t)(tid + t*256)*16u, eb + (size_t)(tid + t*256)*16);
    CP_COMMIT();
    // groups 1,2: W chunks 0,1
#pragma unroll
    for (int t = 0; t < 8; ++t)
        cp16(sb + EOF_W0 + (uint32_t)(tid + t*256)*16u, wsrc + (size_t)(tid + t*256)*16);
    CP_COMMIT();
#pragma unroll
    for (int t = 0; t < 8; ++t)
        cp16(sb + EOF_W1 + (uint32_t)(tid + t*256)*16u, wsrc + 32768 + (size_t)(tid + t*256)*16);
    CP_COMMIT();

    int rA = (warp << 4) + (l >> 2), rB = rA + 8;
    bool pA = pmi && (rA < vn), pB = pmi && (rB < vn);
    const float* hpi = g_hp + (size_t)bi*512;
    float acc[16][4];
    float sSigA = 0.f, sSigB = 0.f;

    // pipelined mainloop: chunk c = (GEMM c>>1, k-half c&1)
#pragma unroll
    for (int c = 0; c < 8; ++c) {
        if (c == 7) { CP_WAIT0(); } else { CP_WAIT1(); }
        __syncthreads();
        if (c == 0 || c == 2 || c == 4) {
#pragma unroll
            for (int t = 0; t < 16; ++t)
#pragma unroll
                for (int e = 0; e < 4; ++e) acc[t][e] = 0.f;
        }
        uint32_t wb = sb + EOF_W0 + (uint32_t)(c & 1)*32768u;
        uint32_t offA  = (c >= 6) ? EOF_MHI : EOF_EHI;
        uint32_t offAl = (c >= 6) ? EOF_MLO : EOF_ELO;
        gemm_split2<8,7,4,8>(sb, offA, offAl, wb, wb + 16384u, warp << 4, (c & 1)*4, l, acc);

        if (c == 1) {
            // epi1: z -> adj -> sigmoid
            const float* hv1A = g_hp + ((size_t)(b*NN + rA))*512 + 128;
            const float* hv1B = g_hp + ((size_t)(b*NN + rB))*512 + 128;
            float pa = 0.f, pb = 0.f;
#pragma unroll
            for (int t = 0; t < 16; ++t) {
                int cc = (t << 3) + (q << 1);
                float2 hw = *(const float2*)(hpi + cc);
                float2 w2 = *(const float2*)(wl2 + cc);
                float2 vA = *(const float2*)(hv1A + cc);
                float2 vB = *(const float2*)(hv1B + cc);
                pa = fmaf(fmaxf(acc[t][0] + hw.x + vA.x, 0.f), w2.x, pa);
                pa = fmaf(fmaxf(acc[t][1] + hw.y + vA.y, 0.f), w2.y, pa);
                pb = fmaf(fmaxf(acc[t][2] + hw.x + vB.x, 0.f), w2.x, pb);
                pb = fmaf(fmaxf(acc[t][3] + hw.y + vB.y, 0.f), w2.y, pb);
            }
            pa += __shfl_xor_sync(~0u, pa, 1); pa += __shfl_xor_sync(~0u, pa, 2);
            pb += __shfl_xor_sync(~0u, pb, 1); pb += __shfl_xor_sync(~0u, pb, 2);
            float bl2v = bl2[0];
            sSigA = pA ? (1.f/(1.f + expf(-(pa + bl2v)))) : 0.f;
            sSigB = pB ? (1.f/(1.f + expf(-(pb + bl2v)))) : 0.f;
        }
        if (c == 3) {
            // epi2: m -> sM (bf16 split) + g_mbuf (fp32)
            const float* hv2A = g_hp + ((size_t)(b*NN + rA))*512 + 384;
            const float* hv2B = g_hp + ((size_t)(b*NN + rB))*512 + 384;
            float* mb = g_mbuf + (size_t)bi*NN*CD;
#pragma unroll
            for (int t = 0; t < 16; ++t) {
                int cc = (t << 3) + (q << 1);
                float2 hw = *(const float2*)(hpi + 256 + cc);
                float2 vA = *(const float2*)(hv2A + cc);
                float2 vB = *(const float2*)(hv2B + cc);
                float mA0 = fmaxf(acc[t][0] + hw.x + vA.x, 0.f) * sSigA;
                float mA1 = fmaxf(acc[t][1] + hw.y + vA.y, 0.f) * sSigA;
                float mB0 = fmaxf(acc[t][2] + hw.x + vB.x, 0.f) * sSigB;
                float mB1 = fmaxf(acc[t][3] + hw.y + vB.y, 0.f) * sSigB;
                *(float2*)(mb + (size_t)rA*CD + cc) = make_float2(mA0, mA1);
                *(float2*)(mb + (size_t)rB*CD + cc) = make_float2(mB0, mB1);
                uint32_t hA, lA, hB, lB;
                split_pair(mA0, mA1, hA, lA);
                split_pair(mB0, mB1, hB, lB);
                uint32_t oA = swz<8>(rA, cc), oB = swz<8>(rB, cc);
                *(uint32_t*)(smem + EOF_MHI + oA) = hA;
                *(uint32_t*)(smem + EOF_MLO + oA) = lA;
                *(uint32_t*)(smem + EOF_MHI + oB) = hB;
                *(uint32_t*)(smem + EOF_MLO + oB) = lB;
            }
        }
        __syncthreads();
        if (c + 2 < 8) {
            uint32_t db = sb + EOF_W0 + (uint32_t)(c & 1)*32768u;
            const char* src = wsrc + (size_t)(c + 2)*32768;
#pragma unroll
            for (int t = 0; t < 8; ++t)
                cp16(db + (uint32_t)(tid + t*256)*16u, src + (size_t)(tid + t*256)*16);
            CP_COMMIT();
        }
    }

    // epi3: e_new = relu(acc + bu) where pm; invalid rows keep old state (no store)
#pragma unroll
    for (int t = 0; t < 16; ++t) {
        int cc = (t << 3) + (q << 1);
        float2 b2 = *(const float2*)(bu + cc);
        if (pA) {
            float e0 = fmaxf(acc[t][0] + b2.x, 0.f);
            float e1 = fmaxf(acc[t][1] + b2.y, 0.f);
            uint32_t h, lo2;
            split_pair(e0, e1, h, lo2);
            uint32_t o = swz<8>(rA, cc);
            *(uint32_t*)(eb + o) = h;
            *(uint32_t*)(eb + 32768 + o) = lo2;
        }
        if (pB) {
            float e0 = fmaxf(acc[t][2] + b2.x, 0.f);
            float e1 = fmaxf(acc[t][3] + b2.y, 0.f);
            uint32_t h, lo2;
            split_pair(e0, e1, h, lo2);
            uint32_t o = swz<8>(rB, cc);
            *(uint32_t*)(eb + o) = h;
            *(uint32_t*)(eb + 32768 + o) = lo2;
        }
    }
}

// ===================== ms reduce (float4) / GRU ===============================
__global__ void k_reduce_ms() {
    int t = blockIdx.x * blockDim.x + threadIdx.x;      // B*N*CD/4
    if (t >= BB*NN*CD/4) return;
    int b   = t / (NN*CD/4);
    int jk4 = t % (NN*CD/4);
    const float4* base = (const float4*)g_mbuf + (size_t)b*NN*(NN*CD/4) + jk4;
    float4 s = make_float4(0.f, 0.f, 0.f, 0.f);
#pragma unroll 4
    for (int i = 0; i < NN; ++i) {
        float4 v = base[(size_t)i*(NN*CD/4)];
        s.x += v.x; s.y += v.y; s.z += v.z; s.w += v.w;
    }
    ((float4*)g_ms)[t] = s;
}

__global__ void k_gru(const int* __restrict__ ev) {
    int t = blockIdx.x * blockDim.x + threadIdx.x;
    if (t >= BB*NN*CD) return;
    int row = t / CD, c = t % CD;
    int b = row / NN, n = row % NN;
    if (n >= ev[b]) return;
    const float* gi = g_gi + (size_t)row*384;
    const float* gh = g_gh + (size_t)row*384;
    float ir = gi[c], iz = gi[CD+c], in = gi[2*CD+c];
    float hr = gh[c], hz = gh[CD+c], hn = gh[2*CD+c];
    float r  = 1.f/(1.f + expf(-(ir+hr)));
    float z  = 1.f/(1.f + expf(-(iz+hz)));
    float nn = tanhf(in + r*hn);
    float hold = g_h[t];
    g_h[t] = (1.f - z)*nn + z*hold;
}

// ===================== readout (HMMA, cp.async pipelined) =====================
// smem: [Ahi 64K][Alo 64K][Wbuf0 32K][Wbuf1 32K] = 192KB dynamic
#define ROF_AHI 0u
#define ROF_ALO 65536u
#define ROF_W0  131072u
#define ROF_W1  163840u
#define RO_SMEM 196608

__global__ __launch_bounds__(256, 1)
void k_readout_mma(const float* __restrict__ br1, const float* __restrict__ Wr2g,
                   const float* __restrict__ br2, const int* __restrict__ ev,
                   float* __restrict__ out) {
    extern __shared__ char smem[];
    __shared__ float sWr2[2560];
    __shared__ float sBr1[256];
    uint32_t sb = smem_u32(smem);
    int tid = threadIdx.x, warp = tid >> 5, l = tid & 31, q = l & 3;
    int b = blockIdx.y, p0 = blockIdx.x * 128;
    int vn = ev[b];
    const char* wsrc = (const char*)g_wr;

    // prologue W prefetch
#pragma unroll
    for (int t = 0; t < 8; ++t)
        cp16(sb + ROF_W0 + (uint32_t)(tid + t*256)*16u, wsrc + (size_t)(tid + t*256)*16);
    CP_COMMIT();
#pragma unroll
    for (int t = 0; t < 8; ++t)
        cp16(sb + ROF_W1 + (uint32_t)(tid + t*256)*16u, wsrc + 32768 + (size_t)(tid + t*256)*16);
    CP_COMMIT();

    for (int t = tid; t < 2560; t += 256) sWr2[t] = Wr2g[t];
    if (tid < 256) sBr1[tid] = br1[tid];

    // gather feat [128 pairs][256]: direct uint2 copies of pre-split planes
    for (int t = tid; t < 8192; t += 256) {
        int lp = t >> 6, c = (t & 63) << 2;
        int p = p0 + lp; if (p >= PP) p = PP - 1;
        int iu = g_iu[p], ju = g_ju[p];
        const char* base; uint32_t o;
        if (c < 128) {
            base = (const char*)g_ebf + (size_t)(b*NN + iu)*65536;
            o = swz<8>(ju, c);
        } else {
            base = (const char*)g_ebf + (size_t)(b*NN + ju)*65536;
            o = swz<8>(iu, c - 128);
        }
        uint2 hi = *(const uint2*)(base + o);
        uint2 lo = *(const uint2*)(base + 32768 + o);
        uint32_t off = swz<9>(lp, c);
        *(uint2*)(smem + ROF_AHI + off) = hi;
        *(uint2*)(smem + ROF_ALO + off) = lo;
    }

    int rA = (warp << 4) + (l >> 2), rB = rA + 8;
    float outA[10], outB[10];
#pragma unroll
    for (int t5 = 0; t5 < 10; ++t5) { outA[t5] = 0.f; outB[t5] = 0.f; }
    float acc[8][4];

#pragma unroll
    for (int c = 0; c < 8; ++c) {
        if (c == 7) { CP_WAIT0(); } else { CP_WAIT1(); }
        __syncthreads();
        if ((c & 1) == 0) {
#pragma unroll
            for (int t = 0; t < 8; ++t)
#pragma unroll
                for (int e = 0; e < 4; ++e) acc[t][e] = 0.f;
        }
        uint32_t wb = sb + ROF_W0 + (uint32_t)(c & 1)*32768u;
        gemm_split2<9,8,8,4>(sb, ROF_AHI, ROF_ALO, wb, wb + 16384u, warp << 4, (c & 1)*8, l, acc);
        if (c & 1) {
            int cc = c >> 1;
#pragma unroll
            for (int t = 0; t < 8; ++t) {
                int n0 = (cc << 6) + (t << 3) + (q << 1);
#pragma unroll
                for (int e = 0; e < 4; ++e) {
                    int n = n0 + (e & 1);
                    float h = fmaxf(acc[t][e] + sBr1[n], 0.f);
                    float* o = (e < 2) ? outA : outB;
                    const float* w = sWr2 + n*10;
#pragma unroll
                    for (int t5 = 0; t5 < 10; ++t5) o[t5] = fmaf(h, w[t5], o[t5]);
                }
            }
        }
        __syncthreads();
        if (c + 2 < 8) {
            uint32_t db = sb + ROF_W0 + (uint32_t)(c & 1)*32768u;
            const char* src = wsrc + (size_t)(c + 2)*32768;
#pragma unroll
            for (int t = 0; t < 8; ++t)
                cp16(db + (uint32_t)(tid + t*256)*16u, src + (size_t)(tid + t*256)*16);
            CP_COMMIT();
        }
    }

#pragma unroll
    for (int t5 = 0; t5 < 10; ++t5) {
        outA[t5] += __shfl_xor_sync(~0u, outA[t5], 1);
        outA[t5] += __shfl_xor_sync(~0u, outA[t5], 2);
        outB[t5] += __shfl_xor_sync(~0u, outB[t5], 1);
        outB[t5] += __shfl_xor_sync(~0u, outB[t5], 2);
    }
    if (q == 0) {
#pragma unroll
        for (int h2 = 0; h2 < 2; ++h2) {
            int r = h2 ? rB : rA;
            float* o = h2 ? outB : outA;
            int p = p0 + r;
            if (p < PP) {
                int iu = g_iu[p], ju = g_ju[p];
                if (ju < vn) {
                    int idx = iu*vn - iu*(iu+1)/2 + (ju - iu - 1);
#pragma unroll
                    for (int t5 = 0; t5 < 10; ++t5)
                        out[(((size_t)b*5 + (t5 >> 1))*PP + idx)*2 + (t5 & 1)] = o[t5] + br2[t5];
                }
            }
        }
    }
}

// ===================== host orchestration =====================================
extern "C" void kernel_launch(void* const* d_in, const int* in_sizes, int n_in,
                              void* d_out, int out_size) {
    const int*   edge_ids      = (const int*)  d_in[0];
    const float* node_features = (const float*)d_in[1];
    const int*   ev            = (const int*)  d_in[3];
    const float* emb           = (const float*)d_in[4];
    const float* Wl_e = (const float*)d_in[5];
    const float* Wl_w = (const float*)d_in[6];
    const float* Wl_v = (const float*)d_in[7];
    const float* bl1  = (const float*)d_in[8];
    const float* wl2  = (const float*)d_in[9];
    const float* bl2  = (const float*)d_in[10];
    const float* Wm_w = (const float*)d_in[11];
    const float* Wm_v = (const float*)d_in[12];
    const float* Wm_e = (const float*)d_in[13];
    const float* bm   = (const float*)d_in[14];
    const float* Wu_e = (const float*)d_in[15];
    const float* Wu_m = (const float*)d_in[16];
    const float* bu   = (const float*)d_in[17];
    const float* W_ih = (const float*)d_in[18];
    const float* W_hh = (const float*)d_in[19];
    const float* b_ih = (const float*)d_in[20];
    const float* b_hh = (const float*)d_in[21];
    const float* Wr1  = (const float*)d_in[22];
    const float* br1  = (const float*)d_in[23];
    const float* Wr2  = (const float*)d_in[24];
    const float* br2  = (const float*)d_in[25];

    cudaFuncSetAttribute(k_edge_mma,    cudaFuncAttributeMaxDynamicSharedMemorySize, EDGE_SMEM);
    cudaFuncSetAttribute(k_readout_mma, cudaFuncAttributeMaxDynamicSharedMemorySize, RO_SMEM);

    // launch 0,1,2 prep; launch 3 = k_edge_mma (ncu captures launch index 3)
    k_prep<<<512, 256>>>(Wl_e, Wm_e, Wu_e, Wu_m, Wr1);
    k_hp<<<dim3(128, 4), 256>>>(node_features, Wl_w, Wl_v, Wm_w, Wm_v, bl1, bm, 1);
    k_init_e<<<65536, 256>>>(edge_ids, emb);

    for (int r = 0; r < RNDS; ++r) {
        if (r > 0)
            k_hp<<<dim3(128, 4), 256>>>(node_features, Wl_w, Wl_v, Wm_w, Wm_v, bl1, bm, 0);
        k_edge_mma<<<BB*NN, 256, EDGE_SMEM>>>(wl2, bl2, bu, ev);
        k_reduce_ms<<<(BB*NN*CD/4 + 255)/256, 256>>>();
        k_gig<<<dim3(128, 3, 2), 256>>>(W_ih, W_hh, b_ih, b_hh);
        k_gru<<<(BB*NN*CD + 255)/256, 256>>>(ev);
    }

    cudaMemsetAsync(d_out, 0, (size_t)out_size * sizeof(float));
    k_readout_mma<<<dim3(64, BB), 256, RO_SMEM>>>(br1, Wr2, br2, ev, (float*)d_out);
}

// round 10
// speedup vs baseline: 3.3404x; 1.0367x over previous
#include <cuda_runtime.h>
#include <cuda_bf16.h>
#include <math.h>
#include <stdint.h>

#define BB 32
#define NN 128
#define CD 128
#define PP 8128
#define RNDS 3

// ===================== low-level helpers (base ISA only) ======================
__device__ __forceinline__ uint32_t smem_u32(const void* p) {
    uint32_t a;
    asm("{ .reg .u64 t; cvta.to.shared.u64 t, %1; cvt.u32.u64 %0, t; }" : "=r"(a) : "l"(p));
    return a;
}
__device__ __forceinline__ void ldsm4(uint32_t r[4], uint32_t addr) {
    asm volatile("ldmatrix.sync.aligned.m8n8.x4.shared.b16 {%0,%1,%2,%3}, [%4];"
        : "=r"(r[0]), "=r"(r[1]), "=r"(r[2]), "=r"(r[3]) : "r"(addr));
}
__device__ __forceinline__ void mma_bf16(float c[4], const uint32_t a[4],
                                         uint32_t b0, uint32_t b1) {
    asm volatile("mma.sync.aligned.m16n8k16.row.col.f32.bf16.bf16.f32 "
        "{%0,%1,%2,%3}, {%4,%5,%6,%7}, {%8,%9}, {%0,%1,%2,%3};"
        : "+f"(c[0]), "+f"(c[1]), "+f"(c[2]), "+f"(c[3])
        : "r"(a[0]), "r"(a[1]), "r"(a[2]), "r"(a[3]), "r"(b0), "r"(b1));
}
__device__ __forceinline__ void cp16(uint32_t dst, const void* src) {
    asm volatile("cp.async.cg.shared.global [%0], [%1], 16;" :: "r"(dst), "l"(src));
}
#define CP_COMMIT() asm volatile("cp.async.commit_group;" ::: "memory")
#define CP_WAIT1()  asm volatile("cp.async.wait_group 1;" ::: "memory")
#define CP_WAIT0()  asm volatile("cp.async.wait_group 0;" ::: "memory")

// split (x,y) into packed bf16 hi pair + bf16 residual pair
__device__ __forceinline__ void split_pair(float x, float y, uint32_t& hi, uint32_t& lo) {
    __nv_bfloat16 hx = __float2bfloat16(x), hy = __float2bfloat16(y);
    float rx = x - __bfloat162float(hx), ry = y - __bfloat162float(hy);
    __nv_bfloat16 lx = __float2bfloat16(rx), ly = __float2bfloat16(ry);
    hi = (uint32_t)*(uint16_t*)&hx | ((uint32_t)*(uint16_t*)&hy << 16);
    lo = (uint32_t)*(uint16_t*)&lx | ((uint32_t)*(uint16_t*)&ly << 16);
}
// XOR-swizzled byte offset for bf16 element (r, k); row stride = 1<<SH bytes
template<int SH>
__device__ __host__ __forceinline__ uint32_t swz(int r, int k) {
    return ((uint32_t)r << SH) + ((uint32_t)(((k >> 3) ^ (r & 7))) << 4) + ((uint32_t)(k & 7) << 1);
}

// ---- readout GEMM: warp = M16 x N64 (NTP=4), 3-pass split ----
template<int SHA, int SHB, int NKS, int NTP>
__device__ __forceinline__ void gemm_split2(uint32_t sb, uint32_t offA, uint32_t offAlo,
                                            uint32_t bHi, uint32_t bLo,
                                            int mbase, int ks0, int lane, float acc[][4]) {
    int arow = mbase + (lane & 7) + (((lane >> 3) & 1) << 3);
    uint32_t aBase   = sb + offA + ((uint32_t)arow << SHA);
    uint32_t aBaseLo = sb + offAlo + ((uint32_t)arow << SHA);
    int a7 = arow & 7, agrp = (lane >> 4) & 1;
    int brow0 = (lane & 7) + ((lane >> 4) << 3);
    int b7 = lane & 7, bkb = (lane >> 3) & 1;
#pragma unroll
    for (int ks = 0; ks < NKS; ++ks) {
        uint32_t ak = (uint32_t)(((((ks0 + ks) << 1) | agrp) ^ a7) << 4);
        uint32_t Ah[4], Al[4];
        ldsm4(Ah, aBase + ak);
        ldsm4(Al, aBaseLo + ak);
        uint32_t bk = (uint32_t)((((ks << 1) | bkb) ^ b7) << 4);
#pragma unroll
        for (int tp = 0; tp < NTP; ++tp) {
            uint32_t brow = (uint32_t)(brow0 + (tp << 4)) << SHB;
            uint32_t Bh[4], Bl[4];
            ldsm4(Bh, bHi + brow + bk);
            ldsm4(Bl, bLo + brow + bk);
            mma_bf16(acc[2*tp],     Ah, Bh[0], Bh[1]);
            mma_bf16(acc[2*tp],     Al, Bh[0], Bh[1]);
            mma_bf16(acc[2*tp],     Ah, Bl[0], Bl[1]);
            mma_bf16(acc[2*tp + 1], Ah, Bh[2], Bh[3]);
            mma_bf16(acc[2*tp + 1], Al, Bh[2], Bh[3]);
            mma_bf16(acc[2*tp + 1], Ah, Bl[2], Bl[3]);
        }
    }
}

// ---- edge GEMM: warp = M32 x N64 (2 row-tiles, 4 n16-pairs), 3-pass split ----
// acc[rt*8 + tp*2 + s][e]; 12 ldsm / 48 mma per k-step (B reused across row tiles)
template<int SHA, int SHB, int NKS>
__device__ __forceinline__ void gemm_split42(uint32_t sb, uint32_t offA, uint32_t offAlo,
                                             uint32_t bHi, uint32_t bLo,
                                             int rbase, int ncol0, int ks0, int lane,
                                             float acc[][4]) {
    int arow = rbase + (lane & 7) + (((lane >> 3) & 1) << 3);
    uint32_t a0h = sb + offA   + ((uint32_t)arow << SHA);
    uint32_t a0l = sb + offAlo + ((uint32_t)arow << SHA);
    uint32_t a1h = a0h + (16u << SHA);
    uint32_t a1l = a0l + (16u << SHA);
    int a7 = lane & 7, agrp = (lane >> 4) & 1;
    int brow0 = (lane & 7) + ((lane >> 4) << 3) + ncol0;
    int b7 = lane & 7, bkb = (lane >> 3) & 1;
#pragma unroll
    for (int ks = 0; ks < NKS; ++ks) {
        uint32_t ak = (uint32_t)(((((ks0 + ks) << 1) | agrp) ^ a7) << 4);
        uint32_t A0h[4], A0l[4], A1h[4], A1l[4];
        ldsm4(A0h, a0h + ak); ldsm4(A0l, a0l + ak);
        ldsm4(A1h, a1h + ak); ldsm4(A1l, a1l + ak);
        uint32_t bk = (uint32_t)((((ks << 1) | bkb) ^ b7) << 4);
#pragma unroll
        for (int tp = 0; tp < 4; ++tp) {
            uint32_t brow = (uint32_t)(brow0 + (tp << 4)) << SHB;
            uint32_t Bh[4], Bl[4];
            ldsm4(Bh, bHi + brow + bk);
            ldsm4(Bl, bLo + brow + bk);
            mma_bf16(acc[tp*2],       A0h, Bh[0], Bh[1]);
            mma_bf16(acc[tp*2],       A0l, Bh[0], Bh[1]);
            mma_bf16(acc[tp*2],       A0h, Bl[0], Bl[1]);
            mma_bf16(acc[tp*2 + 1],   A0h, Bh[2], Bh[3]);
            mma_bf16(acc[tp*2 + 1],   A0l, Bh[2], Bh[3]);
            mma_bf16(acc[tp*2 + 1],   A0h, Bl[2], Bl[3]);
            mma_bf16(acc[8+tp*2],     A1h, Bh[0], Bh[1]);
            mma_bf16(acc[8+tp*2],     A1l, Bh[0], Bh[1]);
            mma_bf16(acc[8+tp*2],     A1h, Bl[0], Bl[1]);
            mma_bf16(acc[8+tp*2 + 1], A1h, Bh[2], Bh[3]);
            mma_bf16(acc[8+tp*2 + 1], A1l, Bh[2], Bh[3]);
            mma_bf16(acc[8+tp*2 + 1], A1h, Bl[2], Bl[3]);
        }
    }
}

// ===================== persistent device scratch ==============================
// edge state: per (b,i) tile 64KB = [hi 32768B swizzled swz<8>(j,k)][lo 32768B]
__device__ unsigned short g_ebf[(size_t)BB*NN*32768];
__device__ uint32_t g_mbuf[(size_t)BB*NN*NN*CD/2];     // m as packed bf16-hi pairs
__device__ float g_h   [BB*NN*CD];
__device__ float g_hp  [BB*NN*512];             // [hwl+bl1 | hvl | hwm+bm | hvm]
__device__ float g_ms  [BB*NN*CD];
__device__ float g_gi  [BB*NN*384];
__device__ float g_gh  [BB*NN*384];
__device__ int   g_iu  [PP];
__device__ int   g_ju  [PP];
// 4 edge weights; per matrix: 2 k-halves; per half: [hi 16KB][lo 16KB], swz<7>(n, k&63)
__device__ unsigned short g_wt[4*32768];
// Wr1 in 4 n-chunks; per chunk: 2 k-halves; per half: [hi 16KB][lo 16KB], swz<8>(r, k&127)
__device__ unsigned short g_wr[4*32768];

// ===================== prep kernels ===========================================
__global__ void k_prep_w(const float* __restrict__ Wl_e, const float* __restrict__ Wm_e,
                         const float* __restrict__ Wu_e, const float* __restrict__ Wu_m) {
    int idx = blockIdx.x * blockDim.x + threadIdx.x;
    if (idx >= 65536) return;
    int m = idx >> 14, r = idx & 16383, n = r >> 7, k = r & 127;
    const float* W = (m == 0) ? Wl_e : (m == 1) ? Wm_e : (m == 2) ? Wu_e : Wu_m;
    float v = W[k*128 + n];
    __nv_bfloat16 hi = __float2bfloat16(v);
    __nv_bfloat16 lo = __float2bfloat16(v - __bfloat162float(hi));
    uint32_t o = (uint32_t)m*65536u + (uint32_t)(k >> 6)*32768u + swz<7>(n, k & 63);
    *(__nv_bfloat16*)((char*)g_wt + o) = hi;
    *(__nv_bfloat16*)((char*)g_wt + o + 16384) = lo;
}

__global__ void k_prep_wr(const float* __restrict__ Wr1) {   // [256 k][256 n] + pairs
    int idx = blockIdx.x * blockDim.x + threadIdx.x;
    if (idx < NN*NN) {
        int i = idx / NN, j = idx % NN;
        if (j > i) {
            int p = i*(NN-1) - i*(i-1)/2 + (j - i - 1);
            g_iu[p] = i; g_ju[p] = j;
        }
    }
    if (idx >= 65536) return;
    int n = idx >> 8, k = idx & 255;
    float v = Wr1[k*256 + n];
    __nv_bfloat16 hi = __float2bfloat16(v);
    __nv_bfloat16 lo = __float2bfloat16(v - __bfloat162float(hi));
    uint32_t o = (uint32_t)(n >> 6)*65536u + (uint32_t)(k >> 7)*32768u + swz<8>(n & 63, k & 127);
    *(__nv_bfloat16*)((char*)g_wr + o) = hi;
    *(__nv_bfloat16*)((char*)g_wr + o + 16384) = lo;
}

// ===================== node projections (+ first-round h copy) ================
__global__ __launch_bounds__(256)
void k_hp(const float* __restrict__ nf,
          const float* __restrict__ Wl_w, const float* __restrict__ Wl_v,
          const float* __restrict__ Wm_w, const float* __restrict__ Wm_v,
          const float* __restrict__ bl1,  const float* __restrict__ bm, int first) {
    __shared__ float sA[32*128];
    int row0 = blockIdx.x * 32;
    int sel = blockIdx.y;
    const float* W = (sel == 0) ? Wl_w : (sel == 1) ? Wl_v : (sel == 2) ? Wm_w : Wm_v;
    const float* bias = (sel == 0) ? bl1 : (sel == 2) ? bm : nullptr;
    int colOff = sel << 7;
    const float* hsrc = first ? nf : g_h;
    for (int t = threadIdx.x; t < 1024; t += 256) {
        float4 v = ((const float4*)(hsrc + (size_t)row0*128))[t];
        ((float4*)sA)[t] = v;
        if (first && sel == 0) ((float4*)(g_h + (size_t)row0*128))[t] = v;
    }
    __syncthreads();
    int col = threadIdx.x & 127;
    int half = threadIdx.x >> 7;
    float acc[16];
#pragma unroll
    for (int r = 0; r < 16; ++r) acc[r] = 0.f;
    const float* sAr = sA + half*16*128;
    for (int k = 0; k < 128; ++k) {
        float w = W[(size_t)k*128 + col];
#pragma unroll
        for (int r = 0; r < 16; ++r) acc[r] = fmaf(sAr[r*128 + k], w, acc[r]);
    }
    float bv = bias ? bias[col] : 0.f;
    for (int r = 0; r < 16; ++r)
        g_hp[(size_t)(row0 + half*16 + r)*512 + colOff + col] = acc[r] + bv;
}

// gi and gh in one launch: grid (128, 3, 2)
__global__ __launch_bounds__(256)
void k_gig(const float* __restrict__ Wih, const float* __restrict__ Whh,
           const float* __restrict__ bih, const float* __restrict__ bhh) {
    __shared__ float sA[32*128];
    int row0 = blockIdx.x * 32;
    int c0 = blockIdx.y * 128;
    int z = blockIdx.z;
    const float* A = z ? g_h : g_ms;
    const float* W = z ? Whh : Wih;
    const float* bias = z ? bhh : bih;
    float* C = z ? g_gh : g_gi;
    for (int t = threadIdx.x; t < 1024; t += 256)
        ((float4*)sA)[t] = ((const float4*)(A + (size_t)row0*128))[t];
    __syncthreads();
    int col = c0 + (threadIdx.x & 127);
    int half = threadIdx.x >> 7;
    float acc[16];
#pragma unroll
    for (int r = 0; r < 16; ++r) acc[r] = 0.f;
    const float* sAr = sA + half*16*128;
    for (int k = 0; k < 128; ++k) {
        float w = W[(size_t)k*384 + col];
#pragma unroll
        for (int r = 0; r < 16; ++r) acc[r] = fmaf(sAr[r*128 + k], w, acc[r]);
    }
    float bv = bias[col];
    for (int r = 0; r < 16; ++r)
        C[(size_t)(row0 + half*16 + r)*384 + col] = acc[r] + bv;
}

// ===================== fused edge kernel (HMMA, cp.async pipelined) ===========
// smem: [Ehi 32K][Elo 32K][Mhi 32K][Mlo 32K][Wbuf0 32K][Wbuf1 32K] = 192KB
#define EOF_EHI 0u
#define EOF_ELO 32768u
#define EOF_MHI 65536u
#define EOF_MLO 98304u
#define EOF_W0  131072u
#define EOF_W1  163840u
#define EDGE_SMEM 196608

__global__ __launch_bounds__(256, 1)
void k_edge_mma(const float* __restrict__ wl2, const float* __restrict__ bl2,
                const float* __restrict__ bu,  const int* __restrict__ ev,
                const int* __restrict__ eids,  const float* __restrict__ emb, int first) {
    extern __shared__ char smem[];
    uint32_t sb = smem_u32(smem);
    int tid = threadIdx.x, warp = tid >> 5, l = tid & 31, q = l & 3;
    int bi = blockIdx.x, b = bi >> 7, i = bi & 127;
    int vn = ev[b];
    bool pmi = (i < vn);
    const char* wsrc = (const char*)g_wt;
    char* eb = (char*)g_ebf + (size_t)bi*65536;

    if (!first) {
#pragma unroll
        for (int t = 0; t < 16; ++t)
            cp16(sb + EOF_EHI + (uint32_t)(tid + t*256)*16u, eb + (size_t)(tid + t*256)*16);
        CP_COMMIT();
    }
#pragma unroll
    for (int t = 0; t < 8; ++t)
        cp16(sb + EOF_W0 + (uint32_t)(tid + t*256)*16u, wsrc + (size_t)(tid + t*256)*16);
    CP_COMMIT();
#pragma unroll
    for (int t = 0; t < 8; ++t)
        cp16(sb + EOF_W1 + (uint32_t)(tid + t*256)*16u, wsrc + 32768 + (size_t)(tid + t*256)*16);
    CP_COMMIT();

    if (first) {
        // build E tile from edge_ids + emb; persist init values for invalid rows
        int* sEid = (int*)(smem + EOF_MHI);
        if (tid < 128) sEid[tid] = eids[((size_t)bi << 7) + tid];
        __syncthreads();
        for (int t = tid; t < 4096; t += 256) {
            int j = t >> 5, c4 = t & 31;
            int id = sEid[j];
            float4 v = ((const float4*)emb)[id*32 + c4];
            uint32_t h01, l01, h23, l23;
            split_pair(v.x, v.y, h01, l01);
            split_pair(v.z, v.w, h23, l23);
            uint32_t o = swz<8>(j, c4 << 2);
            *(uint2*)(smem + EOF_EHI + o) = make_uint2(h01, h23);
            *(uint2*)(smem + EOF_ELO + o) = make_uint2(l01, l23);
            if (!(pmi && j < vn)) {
                *(uint2*)(eb + o)         = make_uint2(h01, h23);
                *(uint2*)(eb + 32768 + o) = make_uint2(l01, l23);
            }
        }
    }

    // warp tile: wg = row block (M32), nh = N-half (N64)
    int wg = warp >> 1, nh = warp & 1;
    int rbase = wg << 5, ncol0 = nh << 6;
    int r0 = l >> 2;
    int Rs[4] = { rbase + r0, rbase + r0 + 8, rbase + r0 + 16, rbase + r0 + 24 };
    bool vs[4];
#pragma unroll
    for (int k2 = 0; k2 < 4; ++k2) vs[k2] = pmi && (Rs[k2] < vn);
    const float* hpi = g_hp + (size_t)bi*512;
    float acc[16][4];
    float sig[4];

#pragma unroll
    for (int c = 0; c < 8; ++c) {
        if (c == 7) { CP_WAIT0(); } else { CP_WAIT1(); }
        __syncthreads();
        if (c == 0 || c == 2 || c == 4) {
#pragma unroll
            for (int t = 0; t < 16; ++t)
#pragma unroll
                for (int e = 0; e < 4; ++e) acc[t][e] = 0.f;
        }
        uint32_t wb = sb + EOF_W0 + (uint32_t)(c & 1)*32768u;
        uint32_t offA  = (c >= 6) ? EOF_MHI : EOF_EHI;
        uint32_t offAl = (c >= 6) ? EOF_MLO : EOF_ELO;
        gemm_split42<8,7,4>(sb, offA, offAl, wb, wb + 16384u, rbase, ncol0, (c & 1)*4, l, acc);

        if (c == 1) {
            // epi1: z -> partial adj over this warp's N-half, cross-warp combine, sigmoid
            float par[4] = {0.f, 0.f, 0.f, 0.f};
#pragma unroll
            for (int rt = 0; rt < 2; ++rt) {
                const float* hvA = g_hp + ((size_t)(b*NN + Rs[rt*2]))*512 + 128;
                const float* hvB = g_hp + ((size_t)(b*NN + Rs[rt*2+1]))*512 + 128;
#pragma unroll
                for (int nt = 0; nt < 8; ++nt) {
                    int cc = ncol0 + (nt << 3) + (q << 1);
                    float2 hw = *(const float2*)(hpi + cc);
                    float2 w2 = *(const float2*)(wl2 + cc);
                    float2 vA = *(const float2*)(hvA + cc);
                    float2 vB = *(const float2*)(hvB + cc);
                    const float* a = acc[rt*8 + nt];
                    par[rt*2]   = fmaf(fmaxf(a[0] + hw.x + vA.x, 0.f), w2.x, par[rt*2]);
                    par[rt*2]   = fmaf(fmaxf(a[1] + hw.y + vA.y, 0.f), w2.y, par[rt*2]);
                    par[rt*2+1] = fmaf(fmaxf(a[2] + hw.x + vB.x, 0.f), w2.x, par[rt*2+1]);
                    par[rt*2+1] = fmaf(fmaxf(a[3] + hw.y + vB.y, 0.f), w2.y, par[rt*2+1]);
                }
            }
#pragma unroll
            for (int k2 = 0; k2 < 4; ++k2) {
                par[k2] += __shfl_xor_sync(~0u, par[k2], 1);
                par[k2] += __shfl_xor_sync(~0u, par[k2], 2);
            }
            float* sPart = (float*)(smem + EOF_MHI);
            if (q == 0) {
#pragma unroll
                for (int k2 = 0; k2 < 4; ++k2) sPart[Rs[k2]*2 + nh] = par[k2];
            }
            __syncthreads();
            float bl2v = bl2[0];
#pragma unroll
            for (int k2 = 0; k2 < 4; ++k2) {
                float adj = sPart[Rs[k2]*2] + sPart[Rs[k2]*2 + 1] + bl2v;
                sig[k2] = vs[k2] ? (1.f/(1.f + expf(-adj))) : 0.f;
            }
        }
        if (c == 3) {
            // epi2: m -> M smem planes (bf16 split) + g_mbuf (packed bf16-hi)
            uint32_t* mbu = g_mbuf + (size_t)bi*NN*(CD/2);
#pragma unroll
            for (int rt = 0; rt < 2; ++rt) {
                int RA = Rs[rt*2], RB = Rs[rt*2+1];
                const float* hvA = g_hp + ((size_t)(b*NN + RA))*512 + 384;
                const float* hvB = g_hp + ((size_t)(b*NN + RB))*512 + 384;
#pragma unroll
                for (int nt = 0; nt < 8; ++nt) {
                    int cc = ncol0 + (nt << 3) + (q << 1);
                    float2 hw = *(const float2*)(hpi + 256 + cc);
                    float2 vA = *(const float2*)(hvA + cc);
                    float2 vB = *(const float2*)(hvB + cc);
                    const float* a = acc[rt*8 + nt];
                    float mA0 = fmaxf(a[0] + hw.x + vA.x, 0.f) * sig[rt*2];
                    float mA1 = fmaxf(a[1] + hw.y + vA.y, 0.f) * sig[rt*2];
                    float mB0 = fmaxf(a[2] + hw.x + vB.x, 0.f) * sig[rt*2+1];
                    float mB1 = fmaxf(a[3] + hw.y + vB.y, 0.f) * sig[rt*2+1];
                    uint32_t hA, lA, hB, lB;
                    split_pair(mA0, mA1, hA, lA);
                    split_pair(mB0, mB1, hB, lB);
                    mbu[RA*(CD/2) + (cc >> 1)] = hA;
                    mbu[RB*(CD/2) + (cc >> 1)] = hB;
                    uint32_t oA = swz<8>(RA, cc), oB = swz<8>(RB, cc);
                    *(uint32_t*)(smem + EOF_MHI + oA) = hA;
                    *(uint32_t*)(smem + EOF_MLO + oA) = lA;
                    *(uint32_t*)(smem + EOF_MHI + oB) = hB;
                    *(uint32_t*)(smem + EOF_MLO + oB) = lB;
                }
            }
        }
        __syncthreads();
        if (c + 2 < 8) {
            uint32_t db = sb + EOF_W0 + (uint32_t)(c & 1)*32768u;
            const char* src = wsrc + (size_t)(c + 2)*32768;
#pragma unroll
            for (int t = 0; t < 8; ++t)
                cp16(db + (uint32_t)(tid + t*256)*16u, src + (size_t)(tid + t*256)*16);
            CP_COMMIT();
        }
    }

    // epi3: e_new = relu(acc + bu) where pm; invalid rows keep old state (no store)
#pragma unroll
    for (int rt = 0; rt < 2; ++rt) {
        int RA = Rs[rt*2], RB = Rs[rt*2+1];
#pragma unroll
        for (int nt = 0; nt < 8; ++nt) {
            int cc = ncol0 + (nt << 3) + (q << 1);
            float2 b2 = *(const float2*)(bu + cc);
            const float* a = acc[rt*8 + nt];
            if (vs[rt*2]) {
                uint32_t h, lo2;
                split_pair(fmaxf(a[0] + b2.x, 0.f), fmaxf(a[1] + b2.y, 0.f), h, lo2);
                uint32_t o = swz<8>(RA, cc);
                *(uint32_t*)(eb + o) = h;
                *(uint32_t*)(eb + 32768 + o) = lo2;
            }
            if (vs[rt*2+1]) {
                uint32_t h, lo2;
                split_pair(fmaxf(a[2] + b2.x, 0.f), fmaxf(a[3] + b2.y, 0.f), h, lo2);
                uint32_t o = swz<8>(RB, cc);
                *(uint32_t*)(eb + o) = h;
                *(uint32_t*)(eb + 32768 + o) = lo2;
            }
        }
    }
}

// ===================== ms reduce (packed bf16) / GRU ==========================
__global__ void k_reduce_ms() {
    int t = blockIdx.x * blockDim.x + threadIdx.x;      // B*N*CD/4
    if (t >= BB*NN*CD/4) return;
    int b   = t / (NN*CD/4);
    int jk4 = t % (NN*CD/4);
    const uint2* base = (const uint2*)g_mbuf + (size_t)b*NN*(NN*CD/4) + jk4;
    float4 s = make_float4(0.f, 0.f, 0.f, 0.f);
#pragma unroll 4
    for (int i = 0; i < NN; ++i) {
        uint2 u = base[(size_t)i*(NN*CD/4)];
        __nv_bfloat162 p0 = *(__nv_bfloat162*)&u.x;
        __nv_bfloat162 p1 = *(__nv_bfloat162*)&u.y;
        s.x += __bfloat162float(p0.x); s.y += __bfloat162float(p0.y);
        s.z += __bfloat162float(p1.x); s.w += __bfloat162float(p1.y);
    }
    ((float4*)g_ms)[t] = s;
}

__global__ void k_gru(const int* __restrict__ ev) {
    int t = blockIdx.x * blockDim.x + threadIdx.x;
    if (t >= BB*NN*CD) return;
    int row = t / CD, c = t % CD;
    int b = row / NN, n = row % NN;
    if (n >= ev[b]) return;
    const float* gi = g_gi + (size_t)row*384;
    const float* gh = g_gh + (size_t)row*384;
    float ir = gi[c], iz = gi[CD+c], in = gi[2*CD+c];
    float hr = gh[c], hz = gh[CD+c], hn = gh[2*CD+c];
    float r  = 1.f/(1.f + expf(-(ir+hr)));
    float z  = 1.f/(1.f + expf(-(iz+hz)));
    float nn = tanhf(in + r*hn);
    float hold = g_h[t];
    g_h[t] = (1.f - z)*nn + z*hold;
}

// ===================== readout (HMMA, cp.async pipelined) =====================
// smem: [Ahi 64K][Alo 64K][Wbuf0 32K][Wbuf1 32K] = 192KB dynamic
#define ROF_AHI 0u
#define ROF_ALO 65536u
#define ROF_W0  131072u
#define ROF_W1  163840u
#define RO_SMEM 196608

__global__ __launch_bounds__(256, 1)
void k_readout_mma(const float* __restrict__ br1, const float* __restrict__ Wr2g,
                   const float* __restrict__ br2, const int* __restrict__ ev,
                   float* __restrict__ out) {
    extern __shared__ char smem[];
    __shared__ float sWr2[2560];
    __shared__ float sBr1[256];
    uint32_t sb = smem_u32(smem);
    int tid = threadIdx.x, warp = tid >> 5, l = tid & 31, q = l & 3;
    int b = blockIdx.y, p0 = blockIdx.x * 128;
    int vn = ev[b];
    const char* wsrc = (const char*)g_wr;

#pragma unroll
    for (int t = 0; t < 8; ++t)
        cp16(sb + ROF_W0 + (uint32_t)(tid + t*256)*16u, wsrc + (size_t)(tid + t*256)*16);
    CP_COMMIT();
#pragma unroll
    for (int t = 0; t < 8; ++t)
        cp16(sb + ROF_W1 + (uint32_t)(tid + t*256)*16u, wsrc + 32768 + (size_t)(tid + t*256)*16);
    CP_COMMIT();

    for (int t = tid; t < 2560; t += 256) sWr2[t] = Wr2g[t];
    if (tid < 256) sBr1[tid] = br1[tid];

    // gather feat [128 pairs][256]: direct uint2 copies of pre-split planes
    for (int t = tid; t < 8192; t += 256) {
        int lp = t >> 6, c = (t & 63) << 2;
        int p = p0 + lp; if (p >= PP) p = PP - 1;
        int iu = g_iu[p], ju = g_ju[p];
        const char* base; uint32_t o;
        if (c < 128) {
            base = (const char*)g_ebf + (size_t)(b*NN + iu)*65536;
            o = swz<8>(ju, c);
        } else {
            base = (const char*)g_ebf + (size_t)(b*NN + ju)*65536;
            o = swz<8>(iu, c - 128);
        }
        uint2 hi = *(const uint2*)(base + o);
        uint2 lo = *(const uint2*)(base + 32768 + o);
        uint32_t off = swz<9>(lp, c);
        *(uint2*)(smem + ROF_AHI + off) = hi;
        *(uint2*)(smem + ROF_ALO + off) = lo;
    }

    int rA = (warp << 4) + (l >> 2), rB = rA + 8;
    float outA[10], outB[10];
#pragma unroll
    for (int t5 = 0; t5 < 10; ++t5) { outA[t5] = 0.f; outB[t5] = 0.f; }
    float acc[8][4];

#pragma unroll
    for (int c = 0; c < 8; ++c) {
        if (c == 7) { CP_WAIT0(); } else { CP_WAIT1(); }
        __syncthreads();
        if ((c & 1) == 0) {
#pragma unroll
            for (int t = 0; t < 8; ++t)
#pragma unroll
                for (int e = 0; e < 4; ++e) acc[t][e] = 0.f;
        }
        uint32_t wb = sb + ROF_W0 + (uint32_t)(c & 1)*32768u;
        gemm_split2<9,8,8,4>(sb, ROF_AHI, ROF_ALO, wb, wb + 16384u, warp << 4, (c & 1)*8, l, acc);
        if (c & 1) {
            int cc = c >> 1;
#pragma unroll
            for (int t = 0; t < 8; ++t) {
                int n0 = (cc << 6) + (t << 3) + (q << 1);
#pragma unroll
                for (int e = 0; e < 4; ++e) {
                    int n = n0 + (e & 1);
                    float h = fmaxf(acc[t][e] + sBr1[n], 0.f);
                    float* o = (e < 2) ? outA : outB;
                    const float* w = sWr2 + n*10;
#pragma unroll
                    for (int t5 = 0; t5 < 10; ++t5) o[t5] = fmaf(h, w[t5], o[t5]);
                }
            }
        }
        __syncthreads();
        if (c + 2 < 8) {
            uint32_t db = sb + ROF_W0 + (uint32_t)(c & 1)*32768u;
            const char* src = wsrc + (size_t)(c + 2)*32768;
#pragma unroll
            for (int t = 0; t < 8; ++t)
                cp16(db + (uint32_t)(tid + t*256)*16u, src + (size_t)(tid + t*256)*16);
            CP_COMMIT();
        }
    }

#pragma unroll
    for (int t5 = 0; t5 < 10; ++t5) {
        outA[t5] += __shfl_xor_sync(~0u, outA[t5], 1);
        outA[t5] += __shfl_xor_sync(~0u, outA[t5], 2);
        outB[t5] += __shfl_xor_sync(~0u, outB[t5], 1);
        outB[t5] += __shfl_xor_sync(~0u, outB[t5], 2);
    }
    if (q == 0) {
#pragma unroll
        for (int h2 = 0; h2 < 2; ++h2) {
            int r = h2 ? rB : rA;
            float* o = h2 ? outB : outA;
            int p = p0 + r;
            if (p < PP) {
                int iu = g_iu[p], ju = g_ju[p];
                if (ju < vn) {
                    int idx = iu*vn - iu*(iu+1)/2 + (ju - iu - 1);
#pragma unroll
                    for (int t5 = 0; t5 < 10; ++t5)
                        out[(((size_t)b*5 + (t5 >> 1))*PP + idx)*2 + (t5 & 1)] = o[t5] + br2[t5];
                }
            }
        }
    }
}

// ===================== host orchestration =====================================
extern "C" void kernel_launch(void* const* d_in, const int* in_sizes, int n_in,
                              void* d_out, int out_size) {
    const int*   edge_ids      = (const int*)  d_in[0];
    const float* node_features = (const float*)d_in[1];
    const int*   ev            = (const int*)  d_in[3];
    const float* emb           = (const float*)d_in[4];
    const float* Wl_e = (const float*)d_in[5];
    const float* Wl_w = (const float*)d_in[6];
    const float* Wl_v = (const float*)d_in[7];
    const float* bl1  = (const float*)d_in[8];
    const float* wl2  = (const float*)d_in[9];
    const float* bl2  = (const float*)d_in[10];
    const float* Wm_w = (const float*)d_in[11];
    const float* Wm_v = (const float*)d_in[12];
    const float* Wm_e = (const float*)d_in[13];
    const float* bm   = (const float*)d_in[14];
    const float* Wu_e = (const float*)d_in[15];
    const float* Wu_m = (const float*)d_in[16];
    const float* bu   = (const float*)d_in[17];
    const float* W_ih = (const float*)d_in[18];
    const float* W_hh = (const float*)d_in[19];
    const float* b_ih = (const float*)d_in[20];
    const float* b_hh = (const float*)d_in[21];
    const float* Wr1  = (const float*)d_in[22];
    const float* br1  = (const float*)d_in[23];
    const float* Wr2  = (const float*)d_in[24];
    const float* br2  = (const float*)d_in[25];

    cudaFuncSetAttribute(k_edge_mma,    cudaFuncAttributeMaxDynamicSharedMemorySize, EDGE_SMEM);
    cudaFuncSetAttribute(k_readout_mma, cudaFuncAttributeMaxDynamicSharedMemorySize, RO_SMEM);

    // launches: prep_w(0), prep_wr(1), hp(2), edge(3) — ncu captures index 3
    k_prep_w<<<256, 256>>>(Wl_e, Wm_e, Wu_e, Wu_m);
    k_prep_wr<<<256, 256>>>(Wr1);
    k_hp<<<dim3(128, 4), 256>>>(node_features, Wl_w, Wl_v, Wm_w, Wm_v, bl1, bm, 1);

    for (int r = 0; r < RNDS; ++r) {
        if (r > 0)
            k_hp<<<dim3(128, 4), 256>>>(node_features, Wl_w, Wl_v, Wm_w, Wm_v, bl1, bm, 0);
        k_edge_mma<<<BB*NN, 256, EDGE_SMEM>>>(wl2, bl2, bu, ev, edge_ids, emb, r == 0);
        k_reduce_ms<<<(BB*NN*CD/4 + 255)/256, 256>>>();
        k_gig<<<dim3(128, 3, 2), 256>>>(W_ih, W_hh, b_ih, b_hh);
        k_gru<<<(BB*NN*CD + 255)/256, 256>>>(ev);
    }

    cudaMemsetAsync(d_out, 0, (size_t)out_size * sizeof(float));
    k_readout_mma<<<dim3(64, BB), 256, RO_SMEM>>>(br1, Wr2, br2, ev, (float*)d_out);
}

// round 11
// speedup vs baseline: 3.6168x; 1.0827x over previous
#include <cuda_runtime.h>
#include <cuda_bf16.h>
#include <cuda_fp16.h>
#include <math.h>
#include <stdint.h>

#define BB 32
#define NN 128
#define CD 128
#define PP 8128
#define RNDS 3

// ===================== low-level helpers (base ISA only) ======================
__device__ __forceinline__ uint32_t smem_u32(const void* p) {
    uint32_t a;
    asm("{ .reg .u64 t; cvta.to.shared.u64 t, %1; cvt.u32.u64 %0, t; }" : "=r"(a) : "l"(p));
    return a;
}
__device__ __forceinline__ void ldsm4(uint32_t r[4], uint32_t addr) {
    asm volatile("ldmatrix.sync.aligned.m8n8.x4.shared.b16 {%0,%1,%2,%3}, [%4];"
        : "=r"(r[0]), "=r"(r[1]), "=r"(r[2]), "=r"(r[3]) : "r"(addr));
}
__device__ __forceinline__ void mma_bf16(float c[4], const uint32_t a[4],
                                         uint32_t b0, uint32_t b1) {
    asm volatile("mma.sync.aligned.m16n8k16.row.col.f32.bf16.bf16.f32 "
        "{%0,%1,%2,%3}, {%4,%5,%6,%7}, {%8,%9}, {%0,%1,%2,%3};"
        : "+f"(c[0]), "+f"(c[1]), "+f"(c[2]), "+f"(c[3])
        : "r"(a[0]), "r"(a[1]), "r"(a[2]), "r"(a[3]), "r"(b0), "r"(b1));
}
__device__ __forceinline__ void cp16(uint32_t dst, const void* src) {
    asm volatile("cp.async.cg.shared.global [%0], [%1], 16;" :: "r"(dst), "l"(src));
}
#define CP_COMMIT() asm volatile("cp.async.commit_group;" ::: "memory")
#define CP_WAIT1()  asm volatile("cp.async.wait_group 1;" ::: "memory")
#define CP_WAIT0()  asm volatile("cp.async.wait_group 0;" ::: "memory")

// split (x,y) into packed bf16 hi pair + bf16 residual pair
__device__ __forceinline__ void split_pair(float x, float y, uint32_t& hi, uint32_t& lo) {
    __nv_bfloat16 hx = __float2bfloat16(x), hy = __float2bfloat16(y);
    float rx = x - __bfloat162float(hx), ry = y - __bfloat162float(hy);
    __nv_bfloat16 lx = __float2bfloat16(rx), ly = __float2bfloat16(ry);
    hi = (uint32_t)*(uint16_t*)&hx | ((uint32_t)*(uint16_t*)&hy << 16);
    lo = (uint32_t)*(uint16_t*)&lx | ((uint32_t)*(uint16_t*)&ly << 16);
}
// XOR-swizzled byte offset for bf16 element (r, k); row stride = 1<<SH bytes
template<int SH>
__device__ __host__ __forceinline__ uint32_t swz(int r, int k) {
    return ((uint32_t)r << SH) + ((uint32_t)(((k >> 3) ^ (r & 7))) << 4) + ((uint32_t)(k & 7) << 1);
}

// ---- readout GEMM: warp = M16 x N64 (NTP=4), 3-pass split ----
template<int SHA, int SHB, int NKS, int NTP>
__device__ __forceinline__ void gemm_split2(uint32_t sb, uint32_t offA, uint32_t offAlo,
                                            uint32_t bHi, uint32_t bLo,
                                            int mbase, int ks0, int lane, float acc[][4]) {
    int arow = mbase + (lane & 7) + (((lane >> 3) & 1) << 3);
    uint32_t aBase   = sb + offA + ((uint32_t)arow << SHA);
    uint32_t aBaseLo = sb + offAlo + ((uint32_t)arow << SHA);
    int a7 = arow & 7, agrp = (lane >> 4) & 1;
    int brow0 = (lane & 7) + ((lane >> 4) << 3);
    int b7 = lane & 7, bkb = (lane >> 3) & 1;
#pragma unroll
    for (int ks = 0; ks < NKS; ++ks) {
        uint32_t ak = (uint32_t)(((((ks0 + ks) << 1) | agrp) ^ a7) << 4);
        uint32_t Ah[4], Al[4];
        ldsm4(Ah, aBase + ak);
        ldsm4(Al, aBaseLo + ak);
        uint32_t bk = (uint32_t)((((ks << 1) | bkb) ^ b7) << 4);
#pragma unroll
        for (int tp = 0; tp < NTP; ++tp) {
            uint32_t brow = (uint32_t)(brow0 + (tp << 4)) << SHB;
            uint32_t Bh[4], Bl[4];
            ldsm4(Bh, bHi + brow + bk);
            ldsm4(Bl, bLo + brow + bk);
            mma_bf16(acc[2*tp],     Ah, Bh[0], Bh[1]);
            mma_bf16(acc[2*tp],     Al, Bh[0], Bh[1]);
            mma_bf16(acc[2*tp],     Ah, Bl[0], Bl[1]);
            mma_bf16(acc[2*tp + 1], Ah, Bh[2], Bh[3]);
            mma_bf16(acc[2*tp + 1], Al, Bh[2], Bh[3]);
            mma_bf16(acc[2*tp + 1], Ah, Bl[2], Bl[3]);
        }
    }
}

// ---- edge GEMM: warp = M32 x N64 (2 row-tiles, 4 n16-pairs), 3-pass split ----
template<int SHA, int SHB, int NKS>
__device__ __forceinline__ void gemm_split42(uint32_t sb, uint32_t offA, uint32_t offAlo,
                                             uint32_t bHi, uint32_t bLo,
                                             int rbase, int ncol0, int ks0, int lane,
                                             float acc[][4]) {
    int arow = rbase + (lane & 7) + (((lane >> 3) & 1) << 3);
    uint32_t a0h = sb + offA   + ((uint32_t)arow << SHA);
    uint32_t a0l = sb + offAlo + ((uint32_t)arow << SHA);
    uint32_t a1h = a0h + (16u << SHA);
    uint32_t a1l = a0l + (16u << SHA);
    int a7 = lane & 7, agrp = (lane >> 4) & 1;
    int brow0 = (lane & 7) + ((lane >> 4) << 3) + ncol0;
    int b7 = lane & 7, bkb = (lane >> 3) & 1;
#pragma unroll
    for (int ks = 0; ks < NKS; ++ks) {
        uint32_t ak = (uint32_t)(((((ks0 + ks) << 1) | agrp) ^ a7) << 4);
        uint32_t A0h[4], A0l[4], A1h[4], A1l[4];
        ldsm4(A0h, a0h + ak); ldsm4(A0l, a0l + ak);
        ldsm4(A1h, a1h + ak); ldsm4(A1l, a1l + ak);
        uint32_t bk = (uint32_t)((((ks << 1) | bkb) ^ b7) << 4);
#pragma unroll
        for (int tp = 0; tp < 4; ++tp) {
            uint32_t brow = (uint32_t)(brow0 + (tp << 4)) << SHB;
            uint32_t Bh[4], Bl[4];
            ldsm4(Bh, bHi + brow + bk);
            ldsm4(Bl, bLo + brow + bk);
            mma_bf16(acc[tp*2],       A0h, Bh[0], Bh[1]);
            mma_bf16(acc[tp*2],       A0l, Bh[0], Bh[1]);
            mma_bf16(acc[tp*2],       A0h, Bl[0], Bl[1]);
            mma_bf16(acc[tp*2 + 1],   A0h, Bh[2], Bh[3]);
            mma_bf16(acc[tp*2 + 1],   A0l, Bh[2], Bh[3]);
            mma_bf16(acc[tp*2 + 1],   A0h, Bl[2], Bl[3]);
            mma_bf16(acc[8+tp*2],     A1h, Bh[0], Bh[1]);
            mma_bf16(acc[8+tp*2],     A1l, Bh[0], Bh[1]);
            mma_bf16(acc[8+tp*2],     A1h, Bl[0], Bl[1]);
            mma_bf16(acc[8+tp*2 + 1], A1h, Bh[2], Bh[3]);
            mma_bf16(acc[8+tp*2 + 1], A1l, Bh[2], Bh[3]);
            mma_bf16(acc[8+tp*2 + 1], A1h, Bl[2], Bl[3]);
        }
    }
}

// ===================== persistent device scratch ==============================
// edge state: per (b,i) tile 64KB = [hi 32768B swizzled swz<8>(j,k)][lo 32768B]
__device__ unsigned short g_ebf[(size_t)BB*NN*32768];
__device__ uint32_t g_mbuf[(size_t)BB*NN*NN*CD/2];     // m as packed fp16 pairs
__device__ float g_h   [BB*NN*CD];
__device__ float g_hp  [BB*NN*512];             // [hwl+bl1 | hvl | hwm+bm | hvm]
__device__ float g_ms  [BB*NN*CD];
__device__ float g_gi  [BB*NN*384];
__device__ float g_gh  [BB*NN*384];
__device__ int   g_iu  [PP];
__device__ int   g_ju  [PP];
// 4 edge weights; per matrix: 2 k-halves; per half: [hi 16KB][lo 16KB], swz<7>(n, k&63)
__device__ unsigned short g_wt[4*32768];
// Wr1 in 4 n-chunks; per chunk: 2 k-halves; per half: [hi 16KB][lo 16KB], swz<8>(r, k&127)
__device__ unsigned short g_wr[4*32768];

// ===================== prep kernels ===========================================
__global__ void k_prep_w(const float* __restrict__ Wl_e, const float* __restrict__ Wm_e,
                         const float* __restrict__ Wu_e, const float* __restrict__ Wu_m) {
    int idx = blockIdx.x * blockDim.x + threadIdx.x;
    if (idx >= 65536) return;
    int m = idx >> 14, r = idx & 16383, n = r >> 7, k = r & 127;
    const float* W = (m == 0) ? Wl_e : (m == 1) ? Wm_e : (m == 2) ? Wu_e : Wu_m;
    float v = W[k*128 + n];
    __nv_bfloat16 hi = __float2bfloat16(v);
    __nv_bfloat16 lo = __float2bfloat16(v - __bfloat162float(hi));
    uint32_t o = (uint32_t)m*65536u + (uint32_t)(k >> 6)*32768u + swz<7>(n, k & 63);
    *(__nv_bfloat16*)((char*)g_wt + o) = hi;
    *(__nv_bfloat16*)((char*)g_wt + o + 16384) = lo;
}

__global__ void k_prep_wr(const float* __restrict__ Wr1) {   // [256 k][256 n] + pairs
    int idx = blockIdx.x * blockDim.x + threadIdx.x;
    if (idx < NN*NN) {
        int i = idx / NN, j = idx % NN;
        if (j > i) {
            int p = i*(NN-1) - i*(i-1)/2 + (j - i - 1);
            g_iu[p] = i; g_ju[p] = j;
        }
    }
    if (idx >= 65536) return;
    int n = idx >> 8, k = idx & 255;
    float v = Wr1[k*256 + n];
    __nv_bfloat16 hi = __float2bfloat16(v);
    __nv_bfloat16 lo = __float2bfloat16(v - __bfloat162float(hi));
    uint32_t o = (uint32_t)(n >> 6)*65536u + (uint32_t)(k >> 7)*32768u + swz<8>(n & 63, k & 127);
    *(__nv_bfloat16*)((char*)g_wr + o) = hi;
    *(__nv_bfloat16*)((char*)g_wr + o + 16384) = lo;
}

// ===================== node projections (+ first-round h copy) ================
__global__ __launch_bounds__(256)
void k_hp(const float* __restrict__ nf,
          const float* __restrict__ Wl_w, const float* __restrict__ Wl_v,
          const float* __restrict__ Wm_w, const float* __restrict__ Wm_v,
          const float* __restrict__ bl1,  const float* __restrict__ bm, int first) {
    __shared__ float sA[32*128];
    int row0 = blockIdx.x * 32;
    int sel = blockIdx.y;
    const float* W = (sel == 0) ? Wl_w : (sel == 1) ? Wl_v : (sel == 2) ? Wm_w : Wm_v;
    const float* bias = (sel == 0) ? bl1 : (sel == 2) ? bm : nullptr;
    int colOff = sel << 7;
    const float* hsrc = first ? nf : g_h;
    for (int t = threadIdx.x; t < 1024; t += 256) {
        float4 v = ((const float4*)(hsrc + (size_t)row0*128))[t];
        ((float4*)sA)[t] = v;
        if (first && sel == 0) ((float4*)(g_h + (size_t)row0*128))[t] = v;
    }
    __syncthreads();
    int col = threadIdx.x & 127;
    int half = threadIdx.x >> 7;
    float acc[16];
#pragma unroll
    for (int r = 0; r < 16; ++r) acc[r] = 0.f;
    const float* sAr = sA + half*16*128;
    for (int k = 0; k < 128; ++k) {
        float w = W[(size_t)k*128 + col];
#pragma unroll
        for (int r = 0; r < 16; ++r) acc[r] = fmaf(sAr[r*128 + k], w, acc[r]);
    }
    float bv = bias ? bias[col] : 0.f;
    for (int r = 0; r < 16; ++r)
        g_hp[(size_t)(row0 + half*16 + r)*512 + colOff + col] = acc[r] + bv;
}

// gi and gh in one launch: grid (128, 3, 2)
__global__ __launch_bounds__(256)
void k_gig(const float* __restrict__ Wih, const float* __restrict__ Whh,
           const float* __restrict__ bih, const float* __restrict__ bhh) {
    __shared__ float sA[32*128];
    int row0 = blockIdx.x * 32;
    int c0 = blockIdx.y * 128;
    int z = blockIdx.z;
    const float* A = z ? g_h : g_ms;
    const float* W = z ? Whh : Wih;
    const float* bias = z ? bhh : bih;
    float* C = z ? g_gh : g_gi;
    for (int t = threadIdx.x; t < 1024; t += 256)
        ((float4*)sA)[t] = ((const float4*)(A + (size_t)row0*128))[t];
    __syncthreads();
    int col = c0 + (threadIdx.x & 127);
    int half = threadIdx.x >> 7;
    float acc[16];
#pragma unroll
    for (int r = 0; r < 16; ++r) acc[r] = 0.f;
    const float* sAr = sA + half*16*128;
    for (int k = 0; k < 128; ++k) {
        float w = W[(size_t)k*384 + col];
#pragma unroll
        for (int r = 0; r < 16; ++r) acc[r] = fmaf(sAr[r*128 + k], w, acc[r]);
    }
    float bv = bias[col];
    for (int r = 0; r < 16; ++r)
        C[(size_t)(row0 + half*16 + r)*384 + col] = acc[r] + bv;
}

// ===================== fused edge kernel: j-split, occupancy 2 ================
// CTA = (b, i, jhalf): 64 j-rows, 128 threads, 4 warps (M32 x N64 each).
// GEMM order G1(Wl_e), G3(Wu_e->accU), G2(Wm_e->m overwrites E planes), G4(Wu_m->accU).
// smem: [Ehi 16K][Elo 16K][W0 32K][W1 32K][scratch 1K] = 97KB -> 2 CTAs/SM
#define EHI 0u
#define ELO 16384u
#define EW0 32768u
#define EW1 65536u
#define ESCR 98304u
#define EDGE_SMEM 99328

__global__ __launch_bounds__(128, 2)
void k_edge_mma(const float* __restrict__ wl2, const float* __restrict__ bl2,
                const float* __restrict__ bu,  const int* __restrict__ ev,
                const int* __restrict__ eids,  const float* __restrict__ emb, int first) {
    extern __shared__ char smem[];
    uint32_t sb = smem_u32(smem);
    int tid = threadIdx.x, warp = tid >> 5, l = tid & 31, q = l & 3;
    int cta = blockIdx.x;
    int bi = cta >> 1, jh = cta & 1;
    int b = bi >> 7, i = bi & 127;
    int vn = ev[b];
    bool pmi = (i < vn);
    const char* wsrc = (const char*)g_wt;
    char* eb = (char*)g_ebf + (size_t)bi*65536;

    // chunk -> weight matrix: G1,G1,G3,G3,G2,G2,G4,G4
    const int mats[8] = {0, 0, 2, 2, 1, 1, 3, 3};

    if (!first) {
        // E half-tile: hi rows [jh*64, +64) contiguous 16KB, same for lo
#pragma unroll
        for (int t = 0; t < 8; ++t)
            cp16(sb + EHI + (uint32_t)(tid + t*128)*16u,
                 eb + (uint32_t)jh*16384u + (size_t)(tid + t*128)*16);
#pragma unroll
        for (int t = 0; t < 8; ++t)
            cp16(sb + ELO + (uint32_t)(tid + t*128)*16u,
                 eb + 32768u + (uint32_t)jh*16384u + (size_t)(tid + t*128)*16);
        CP_COMMIT();
    }
#pragma unroll
    for (int t = 0; t < 16; ++t)
        cp16(sb + EW0 + (uint32_t)(tid + t*128)*16u, wsrc + (size_t)(tid + t*128)*16);
    CP_COMMIT();
#pragma unroll
    for (int t = 0; t < 16; ++t)
        cp16(sb + EW1 + (uint32_t)(tid + t*128)*16u, wsrc + 32768 + (size_t)(tid + t*128)*16);
    CP_COMMIT();

    if (first) {
        // build E half-tile from edge_ids + emb; persist init values for invalid rows
        int* sEid = (int*)(smem + ESCR);
        if (tid < 64) sEid[tid] = eids[((size_t)bi << 7) + jh*64 + tid];
        __syncthreads();
        for (int t = tid; t < 2048; t += 128) {
            int lr = t >> 5, c4 = t & 31;
            int id = sEid[lr];
            float4 v = ((const float4*)emb)[id*32 + c4];
            uint32_t h01, l01, h23, l23;
            split_pair(v.x, v.y, h01, l01);
            split_pair(v.z, v.w, h23, l23);
            uint32_t o = swz<8>(lr, c4 << 2);
            *(uint2*)(smem + EHI + o) = make_uint2(h01, h23);
            *(uint2*)(smem + ELO + o) = make_uint2(l01, l23);
            int gj = jh*64 + lr;
            if (!(pmi && gj < vn)) {
                uint32_t go = swz<8>(gj, c4 << 2);
                *(uint2*)(eb + go)          = make_uint2(h01, h23);
                *(uint2*)(eb + 32768u + go) = make_uint2(l01, l23);
            }
        }
    }

    int wg = warp >> 1, nh = warp & 1;
    int rbase = wg << 5, ncol0 = nh << 6;
    int r0 = l >> 2;
    int Ls[4] = { rbase + r0, rbase + r0 + 8, rbase + r0 + 16, rbase + r0 + 24 };
    bool vs[4];
#pragma unroll
    for (int k2 = 0; k2 < 4; ++k2) vs[k2] = pmi && (jh*64 + Ls[k2] < vn);
    const float* hpi = g_hp + (size_t)bi*512;
    float acc[16][4], accU[16][4];
    float sig[4];

#pragma unroll
    for (int c = 0; c < 8; ++c) {
        if (c == 7) { CP_WAIT0(); } else { CP_WAIT1(); }
        __syncthreads();
        if (c == 0 || c == 4) {
#pragma unroll
            for (int t = 0; t < 16; ++t)
#pragma unroll
                for (int e = 0; e < 4; ++e) acc[t][e] = 0.f;
        }
        if (c == 2) {
#pragma unroll
            for (int t = 0; t < 16; ++t)
#pragma unroll
                for (int e = 0; e < 4; ++e) accU[t][e] = 0.f;
        }
        uint32_t wb = sb + EW0 + (uint32_t)(c & 1)*32768u;
        float (*tg)[4] = (c == 2 || c == 3 || c >= 6) ? accU : acc;
        gemm_split42<8,7,4>(sb, EHI, ELO, wb, wb + 16384u, rbase, ncol0, (c & 1)*4, l, tg);

        if (c == 1) {
            // epi1: z -> partial adj over this warp's N-half -> cross-warp combine -> sigmoid
            float par[4] = {0.f, 0.f, 0.f, 0.f};
#pragma unroll
            for (int rt = 0; rt < 2; ++rt) {
                const float* hvA = g_hp + ((size_t)(b*NN + jh*64 + Ls[rt*2]))*512 + 128;
                const float* hvB = g_hp + ((size_t)(b*NN + jh*64 + Ls[rt*2+1]))*512 + 128;
#pragma unroll
                for (int nt = 0; nt < 8; ++nt) {
                    int cc = ncol0 + (nt << 3) + (q << 1);
                    float2 hw = *(const float2*)(hpi + cc);
                    float2 w2 = *(const float2*)(wl2 + cc);
                    float2 vA = *(const float2*)(hvA + cc);
                    float2 vB = *(const float2*)(hvB + cc);
                    const float* a = acc[rt*8 + nt];
                    par[rt*2]   = fmaf(fmaxf(a[0] + hw.x + vA.x, 0.f), w2.x, par[rt*2]);
                    par[rt*2]   = fmaf(fmaxf(a[1] + hw.y + vA.y, 0.f), w2.y, par[rt*2]);
                    par[rt*2+1] = fmaf(fmaxf(a[2] + hw.x + vB.x, 0.f), w2.x, par[rt*2+1]);
                    par[rt*2+1] = fmaf(fmaxf(a[3] + hw.y + vB.y, 0.f), w2.y, par[rt*2+1]);
                }
            }
#pragma unroll
            for (int k2 = 0; k2 < 4; ++k2) {
                par[k2] += __shfl_xor_sync(~0u, par[k2], 1);
                par[k2] += __shfl_xor_sync(~0u, par[k2], 2);
            }
            float* sPart = (float*)(smem + ESCR);
            if (q == 0) {
#pragma unroll
                for (int k2 = 0; k2 < 4; ++k2) sPart[Ls[k2]*2 + nh] = par[k2];
            }
            __syncthreads();
            float bl2v = bl2[0];
#pragma unroll
            for (int k2 = 0; k2 < 4; ++k2) {
                float adj = sPart[Ls[k2]*2] + sPart[Ls[k2]*2 + 1] + bl2v;
                sig[k2] = vs[k2] ? (1.f/(1.f + expf(-adj))) : 0.f;
            }
        }
        if (c == 5) {
            __syncthreads();   // all warps done reading E planes (G2) before m overwrites them
            // epi2: m -> E planes (bf16 split) + g_mbuf (packed fp16)
            uint32_t* mbu = g_mbuf + (size_t)bi*NN*(CD/2);
#pragma unroll
            for (int rt = 0; rt < 2; ++rt) {
                int RA = Ls[rt*2], RB = Ls[rt*2+1];
                int gA = jh*64 + RA, gB = jh*64 + RB;
                const float* hvA = g_hp + ((size_t)(b*NN + gA))*512 + 384;
                const float* hvB = g_hp + ((size_t)(b*NN + gB))*512 + 384;
#pragma unroll
                for (int nt = 0; nt < 8; ++nt) {
                    int cc = ncol0 + (nt << 3) + (q << 1);
                    float2 hw = *(const float2*)(hpi + 256 + cc);
                    float2 vA = *(const float2*)(hvA + cc);
                    float2 vB = *(const float2*)(hvB + cc);
                    const float* a = acc[rt*8 + nt];
                    float mA0 = fmaxf(a[0] + hw.x + vA.x, 0.f) * sig[rt*2];
                    float mA1 = fmaxf(a[1] + hw.y + vA.y, 0.f) * sig[rt*2];
                    float mB0 = fmaxf(a[2] + hw.x + vB.x, 0.f) * sig[rt*2+1];
                    float mB1 = fmaxf(a[3] + hw.y + vB.y, 0.f) * sig[rt*2+1];
                    *(__half2*)&mbu[gA*(CD/2) + (cc >> 1)] = __floats2half2_rn(mA0, mA1);
                    *(__half2*)&mbu[gB*(CD/2) + (cc >> 1)] = __floats2half2_rn(mB0, mB1);
                    uint32_t hA, lA, hB, lB;
                    split_pair(mA0, mA1, hA, lA);
                    split_pair(mB0, mB1, hB, lB);
                    uint32_t oA = swz<8>(RA, cc), oB = swz<8>(RB, cc);
                    *(uint32_t*)(smem + EHI + oA) = hA;
                    *(uint32_t*)(smem + ELO + oA) = lA;
                    *(uint32_t*)(smem + EHI + oB) = hB;
                    *(uint32_t*)(smem + ELO + oB) = lB;
                }
            }
        }
        __syncthreads();
        if (c + 2 < 8) {
            uint32_t db = sb + EW0 + (uint32_t)(c & 1)*32768u;
            const char* src = wsrc + (size_t)mats[c + 2]*65536 + (size_t)(c & 1)*32768;
#pragma unroll
            for (int t = 0; t < 16; ++t)
                cp16(db + (uint32_t)(tid + t*128)*16u, src + (size_t)(tid + t*128)*16);
            CP_COMMIT();
        }
    }

    // epi3: e_new = relu(accU + bu) where pm; invalid rows keep old state
#pragma unroll
    for (int rt = 0; rt < 2; ++rt) {
        int gA = jh*64 + Ls[rt*2], gB = jh*64 + Ls[rt*2+1];
#pragma unroll
        for (int nt = 0; nt < 8; ++nt) {
            int cc = ncol0 + (nt << 3) + (q << 1);
            float2 b2 = *(const float2*)(bu + cc);
            const float* a = accU[rt*8 + nt];
            if (vs[rt*2]) {
                uint32_t h, lo2;
                split_pair(fmaxf(a[0] + b2.x, 0.f), fmaxf(a[1] + b2.y, 0.f), h, lo2);
                uint32_t o = swz<8>(gA, cc);
                *(uint32_t*)(eb + o) = h;
                *(uint32_t*)(eb + 32768u + o) = lo2;
            }
            if (vs[rt*2+1]) {
                uint32_t h, lo2;
                split_pair(fmaxf(a[2] + b2.x, 0.f), fmaxf(a[3] + b2.y, 0.f), h, lo2);
                uint32_t o = swz<8>(gB, cc);
                *(uint32_t*)(eb + o) = h;
                *(uint32_t*)(eb + 32768u + o) = lo2;
            }
        }
    }
}

// ===================== ms reduce (packed fp16) / GRU ==========================
__global__ void k_reduce_ms() {
    int t = blockIdx.x * blockDim.x + threadIdx.x;      // B*N*CD/4
    if (t >= BB*NN*CD/4) return;
    int b   = t / (NN*CD/4);
    int jk4 = t % (NN*CD/4);
    const uint2* base = (const uint2*)g_mbuf + (size_t)b*NN*(NN*CD/4) + jk4;
    float4 s = make_float4(0.f, 0.f, 0.f, 0.f);
#pragma unroll 4
    for (int i = 0; i < NN; ++i) {
        uint2 u = base[(size_t)i*(NN*CD/4)];
        float2 p0 = __half22float2(*(__half2*)&u.x);
        float2 p1 = __half22float2(*(__half2*)&u.y);
        s.x += p0.x; s.y += p0.y; s.z += p1.x; s.w += p1.y;
    }
    ((float4*)g_ms)[t] = s;
}

__global__ void k_gru(const int* __restrict__ ev) {
    int t = blockIdx.x * blockDim.x + threadIdx.x;
    if (t >= BB*NN*CD) return;
    int row = t / CD, c = t % CD;
    int b = row / NN, n = row % NN;
    if (n >= ev[b]) return;
    const float* gi = g_gi + (size_t)row*384;
    const float* gh = g_gh + (size_t)row*384;
    float ir = gi[c], iz = gi[CD+c], in = gi[2*CD+c];
    float hr = gh[c], hz = gh[CD+c], hn = gh[2*CD+c];
    float r  = 1.f/(1.f + expf(-(ir+hr)));
    float z  = 1.f/(1.f + expf(-(iz+hz)));
    float nn = tanhf(in + r*hn);
    float hold = g_h[t];
    g_h[t] = (1.f - z)*nn + z*hold;
}

// ===================== readout (HMMA, cp.async pipelined) =====================
// smem: [Ahi 64K][Alo 64K][Wbuf0 32K][Wbuf1 32K] = 192KB dynamic
#define ROF_AHI 0u
#define ROF_ALO 65536u
#define ROF_W0  131072u
#define ROF_W1  163840u
#define RO_SMEM 196608

__global__ __launch_bounds__(256, 1)
void k_readout_mma(const float* __restrict__ br1, const float* __restrict__ Wr2g,
                   const float* __restrict__ br2, const int* __restrict__ ev,
                   float* __restrict__ out) {
    extern __shared__ char smem[];
    __shared__ float sWr2[2560];
    __shared__ float sBr1[256];
    uint32_t sb = smem_u32(smem);
    int tid = threadIdx.x, warp = tid >> 5, l = tid & 31, q = l & 3;
    int b = blockIdx.y, p0 = blockIdx.x * 128;
    int vn = ev[b];
    const char* wsrc = (const char*)g_wr;

#pragma unroll
    for (int t = 0; t < 8; ++t)
        cp16(sb + ROF_W0 + (uint32_t)(tid + t*256)*16u, wsrc + (size_t)(tid + t*256)*16);
    CP_COMMIT();
#pragma unroll
    for (int t = 0; t < 8; ++t)
        cp16(sb + ROF_W1 + (uint32_t)(tid + t*256)*16u, wsrc + 32768 + (size_t)(tid + t*256)*16);
    CP_COMMIT();

    for (int t = tid; t < 2560; t += 256) sWr2[t] = Wr2g[t];
    if (tid < 256) sBr1[tid] = br1[tid];

    // gather feat [128 pairs][256]: direct uint2 copies of pre-split planes
    for (int t = tid; t < 8192; t += 256) {
        int lp = t >> 6, c = (t & 63) << 2;
        int p = p0 + lp; if (p >= PP) p = PP - 1;
        int iu = g_iu[p], ju = g_ju[p];
        const char* base; uint32_t o;
        if (c < 128) {
            base = (const char*)g_ebf + (size_t)(b*NN + iu)*65536;
            o = swz<8>(ju, c);
        } else {
            base = (const char*)g_ebf + (size_t)(b*NN + ju)*65536;
            o = swz<8>(iu, c - 128);
        }
        uint2 hi = *(const uint2*)(base + o);
        uint2 lo = *(const uint2*)(base + 32768 + o);
        uint32_t off = swz<9>(lp, c);
        *(uint2*)(smem + ROF_AHI + off) = hi;
        *(uint2*)(smem + ROF_ALO + off) = lo;
    }

    int rA = (warp << 4) + (l >> 2), rB = rA + 8;
    float outA[10], outB[10];
#pragma unroll
    for (int t5 = 0; t5 < 10; ++t5) { outA[t5] = 0.f; outB[t5] = 0.f; }
    float acc[8][4];

#pragma unroll
    for (int c = 0; c < 8; ++c) {
        if (c == 7) { CP_WAIT0(); } else { CP_WAIT1(); }
        __syncthreads();
        if ((c & 1) == 0) {
#pragma unroll
            for (int t = 0; t < 8; ++t)
#pragma unroll
                for (int e = 0; e < 4; ++e) acc[t][e] = 0.f;
        }
        uint32_t wb = sb + ROF_W0 + (uint32_t)(c & 1)*32768u;
        gemm_split2<9,8,8,4>(sb, ROF_AHI, ROF_ALO, wb, wb + 16384u, warp << 4, (c & 1)*8, l, acc);
        if (c & 1) {
            int cc = c >> 1;
#pragma unroll
            for (int t = 0; t < 8; ++t) {
                int n0 = (cc << 6) + (t << 3) + (q << 1);
#pragma unroll
                for (int e = 0; e < 4; ++e) {
                    int n = n0 + (e & 1);
                    float h = fmaxf(acc[t][e] + sBr1[n], 0.f);
                    float* o = (e < 2) ? outA : outB;
                    const float* w = sWr2 + n*10;
#pragma unroll
                    for (int t5 = 0; t5 < 10; ++t5) o[t5] = fmaf(h, w[t5], o[t5]);
                }
            }
        }
        __syncthreads();
        if (c + 2 < 8) {
            uint32_t db = sb + ROF_W0 + (uint32_t)(c & 1)*32768u;
            const char* src = wsrc + (size_t)(c + 2)*32768;
#pragma unroll
            for (int t = 0; t < 8; ++t)
                cp16(db + (uint32_t)(tid + t*256)*16u, src + (size_t)(tid + t*256)*16);
            CP_COMMIT();
        }
    }

#pragma unroll
    for (int t5 = 0; t5 < 10; ++t5) {
        outA[t5] += __shfl_xor_sync(~0u, outA[t5], 1);
        outA[t5] += __shfl_xor_sync(~0u, outA[t5], 2);
        outB[t5] += __shfl_xor_sync(~0u, outB[t5], 1);
        outB[t5] += __shfl_xor_sync(~0u, outB[t5], 2);
    }
    if (q == 0) {
#pragma unroll
        for (int h2 = 0; h2 < 2; ++h2) {
            int r = h2 ? rB : rA;
            float* o = h2 ? outB : outA;
            int p = p0 + r;
            if (p < PP) {
                int iu = g_iu[p], ju = g_ju[p];
                if (ju < vn) {
                    int idx = iu*vn - iu*(iu+1)/2 + (ju - iu - 1);
#pragma unroll
                    for (int t5 = 0; t5 < 10; ++t5)
                        out[(((size_t)b*5 + (t5 >> 1))*PP + idx)*2 + (t5 & 1)] = o[t5] + br2[t5];
                }
            }
        }
    }
}

// ===================== host orchestration =====================================
extern "C" void kernel_launch(void* const* d_in, const int* in_sizes, int n_in,
                              void* d_out, int out_size) {
    const int*   edge_ids      = (const int*)  d_in[0];
    const float* node_features = (const float*)d_in[1];
    const int*   ev            = (const int*)  d_in[3];
    const float* emb           = (const float*)d_in[4];
    const float* Wl_e = (const float*)d_in[5];
    const float* Wl_w = (const float*)d_in[6];
    const float* Wl_v = (const float*)d_in[7];
    const float* bl1  = (const float*)d_in[8];
    const float* wl2  = (const float*)d_in[9];
    const float* bl2  = (const float*)d_in[10];
    const float* Wm_w = (const float*)d_in[11];
    const float* Wm_v = (const float*)d_in[12];
    const float* Wm_e = (const float*)d_in[13];
    const float* bm   = (const float*)d_in[14];
    const float* Wu_e = (const float*)d_in[15];
    const float* Wu_m = (const float*)d_in[16];
    const float* bu   = (const float*)d_in[17];
    const float* W_ih = (const float*)d_in[18];
    const float* W_hh = (const float*)d_in[19];
    const float* b_ih = (const float*)d_in[20];
    const float* b_hh = (const float*)d_in[21];
    const float* Wr1  = (const float*)d_in[22];
    const float* br1  = (const float*)d_in[23];
    const float* Wr2  = (const float*)d_in[24];
    const float* br2  = (const float*)d_in[25];

    cudaFuncSetAttribute(k_edge_mma,    cudaFuncAttributeMaxDynamicSharedMemorySize, EDGE_SMEM);
    cudaFuncSetAttribute(k_readout_mma, cudaFuncAttributeMaxDynamicSharedMemorySize, RO_SMEM);

    // launches: prep_w(0), prep_wr(1), hp(2), edge(3) — ncu captures index 3
    k_prep_w<<<256, 256>>>(Wl_e, Wm_e, Wu_e, Wu_m);
    k_prep_wr<<<256, 256>>>(Wr1);
    k_hp<<<dim3(128, 4), 256>>>(node_features, Wl_w, Wl_v, Wm_w, Wm_v, bl1, bm, 1);

    for (int r = 0; r < RNDS; ++r) {
        if (r > 0)
            k_hp<<<dim3(128, 4), 256>>>(node_features, Wl_w, Wl_v, Wm_w, Wm_v, bl1, bm, 0);
        k_edge_mma<<<BB*NN*2, 128, EDGE_SMEM>>>(wl2, bl2, bu, ev, edge_ids, emb, r == 0);
        k_reduce_ms<<<(BB*NN*CD/4 + 255)/256, 256>>>();
        k_gig<<<dim3(128, 3, 2), 256>>>(W_ih, W_hh, b_ih, b_hh);
        k_gru<<<(BB*NN*CD + 255)/256, 256>>>(ev);
    }

    cudaMemsetAsync(d_out, 0, (size_t)out_size * sizeof(float));
    k_readout_mma<<<dim3(64, BB), 256, RO_SMEM>>>(br1, Wr2, br2, ev, (float*)d_out);
}

// round 12
// speedup vs baseline: 6.1869x; 1.7106x over previous
#include <cuda_runtime.h>
#include <cuda_bf16.h>
#include <cuda_fp16.h>
#include <math.h>
#include <stdint.h>

#define BB 32
#define NN 128
#define CD 128
#define PP 8128
#define RNDS 3

// ===================== low-level helpers (base ISA only) ======================
__device__ __forceinline__ uint32_t smem_u32(const void* p) {
    uint32_t a;
    asm("{ .reg .u64 t; cvta.to.shared.u64 t, %1; cvt.u32.u64 %0, t; }" : "=r"(a) : "l"(p));
    return a;
}
__device__ __forceinline__ void ldsm4(uint32_t r[4], uint32_t addr) {
    asm volatile("ldmatrix.sync.aligned.m8n8.x4.shared.b16 {%0,%1,%2,%3}, [%4];"
        : "=r"(r[0]), "=r"(r[1]), "=r"(r[2]), "=r"(r[3]) : "r"(addr));
}
__device__ __forceinline__ void mma_bf16(float c[4], const uint32_t a[4],
                                         uint32_t b0, uint32_t b1) {
    asm volatile("mma.sync.aligned.m16n8k16.row.col.f32.bf16.bf16.f32 "
        "{%0,%1,%2,%3}, {%4,%5,%6,%7}, {%8,%9}, {%0,%1,%2,%3};"
        : "+f"(c[0]), "+f"(c[1]), "+f"(c[2]), "+f"(c[3])
        : "r"(a[0]), "r"(a[1]), "r"(a[2]), "r"(a[3]), "r"(b0), "r"(b1));
}
__device__ __forceinline__ void cp16(uint32_t dst, const void* src) {
    asm volatile("cp.async.cg.shared.global [%0], [%1], 16;" :: "r"(dst), "l"(src));
}
#define CP_COMMIT() asm volatile("cp.async.commit_group;" ::: "memory")
#define CP_WAIT1()  asm volatile("cp.async.wait_group 1;" ::: "memory")
#define CP_WAIT0()  asm volatile("cp.async.wait_group 0;" ::: "memory")

// split (x,y) into packed bf16 hi pair + bf16 residual pair
__device__ __forceinline__ void split_pair(float x, float y, uint32_t& hi, uint32_t& lo) {
    __nv_bfloat16 hx = __float2bfloat16(x), hy = __float2bfloat16(y);
    float rx = x - __bfloat162float(hx), ry = y - __bfloat162float(hy);
    __nv_bfloat16 lx = __float2bfloat16(rx), ly = __float2bfloat16(ry);
    hi = (uint32_t)*(uint16_t*)&hx | ((uint32_t)*(uint16_t*)&hy << 16);
    lo = (uint32_t)*(uint16_t*)&lx | ((uint32_t)*(uint16_t*)&ly << 16);
}
template<int SH>
__device__ __host__ __forceinline__ uint32_t swz(int r, int k) {
    return ((uint32_t)r << SH) + ((uint32_t)(((k >> 3) ^ (r & 7))) << 4) + ((uint32_t)(k & 7) << 1);
}

// ---- readout GEMM: warp = M16 x N64 (NTP=4), 3-pass split, ILP-reordered ----
template<int SHA, int SHB, int NKS, int NTP>
__device__ __forceinline__ void gemm_split2(uint32_t sb, uint32_t offA, uint32_t offAlo,
                                            uint32_t bHi, uint32_t bLo,
                                            int mbase, int ks0, int lane, float acc[][4]) {
    int arow = mbase + (lane & 7) + (((lane >> 3) & 1) << 3);
    uint32_t aBase   = sb + offA + ((uint32_t)arow << SHA);
    uint32_t aBaseLo = sb + offAlo + ((uint32_t)arow << SHA);
    int a7 = arow & 7, agrp = (lane >> 4) & 1;
    int brow0 = (lane & 7) + ((lane >> 4) << 3);
    int b7 = lane & 7, bkb = (lane >> 3) & 1;
#pragma unroll
    for (int ks = 0; ks < NKS; ++ks) {
        uint32_t ak = (uint32_t)(((((ks0 + ks) << 1) | agrp) ^ a7) << 4);
        uint32_t Ah[4], Al[4];
        ldsm4(Ah, aBase + ak);
        ldsm4(Al, aBaseLo + ak);
        uint32_t bk = (uint32_t)((((ks << 1) | bkb) ^ b7) << 4);
#pragma unroll
        for (int tp = 0; tp < NTP; ++tp) {
            uint32_t brow = (uint32_t)(brow0 + (tp << 4)) << SHB;
            uint32_t Bh[4], Bl[4];
            ldsm4(Bh, bHi + brow + bk);
            ldsm4(Bl, bLo + brow + bk);
            mma_bf16(acc[2*tp],     Ah, Bh[0], Bh[1]);
            mma_bf16(acc[2*tp + 1], Ah, Bh[2], Bh[3]);
            mma_bf16(acc[2*tp],     Al, Bh[0], Bh[1]);
            mma_bf16(acc[2*tp + 1], Al, Bh[2], Bh[3]);
            mma_bf16(acc[2*tp],     Ah, Bl[0], Bl[1]);
            mma_bf16(acc[2*tp + 1], Ah, Bl[2], Bl[3]);
        }
    }
}

// ---- edge GEMM: warp = M32 x N64, 3-pass split, ILP-reordered (dist 4) ----
template<int SHA, int SHB, int NKS>
__device__ __forceinline__ void gemm_split42(uint32_t sb, uint32_t offA, uint32_t offAlo,
                                             uint32_t bHi, uint32_t bLo,
                                             int rbase, int ncol0, int ks0, int lane,
                                             float acc[][4]) {
    int arow = rbase + (lane & 7) + (((lane >> 3) & 1) << 3);
    uint32_t a0h = sb + offA   + ((uint32_t)arow << SHA);
    uint32_t a0l = sb + offAlo + ((uint32_t)arow << SHA);
    uint32_t a1h = a0h + (16u << SHA);
    uint32_t a1l = a0l + (16u << SHA);
    int a7 = lane & 7, agrp = (lane >> 4) & 1;
    int brow0 = (lane & 7) + ((lane >> 4) << 3) + ncol0;
    int b7 = lane & 7, bkb = (lane >> 3) & 1;
#pragma unroll
    for (int ks = 0; ks < NKS; ++ks) {
        uint32_t ak = (uint32_t)(((((ks0 + ks) << 1) | agrp) ^ a7) << 4);
        uint32_t A0h[4], A0l[4], A1h[4], A1l[4];
        ldsm4(A0h, a0h + ak); ldsm4(A0l, a0l + ak);
        ldsm4(A1h, a1h + ak); ldsm4(A1l, a1l + ak);
        uint32_t bk = (uint32_t)((((ks << 1) | bkb) ^ b7) << 4);
#pragma unroll
        for (int tp = 0; tp < 4; ++tp) {
            uint32_t brow = (uint32_t)(brow0 + (tp << 4)) << SHB;
            uint32_t Bh[4], Bl[4];
            ldsm4(Bh, bHi + brow + bk);
            ldsm4(Bl, bLo + brow + bk);
            mma_bf16(acc[tp*2],       A0h, Bh[0], Bh[1]);
            mma_bf16(acc[tp*2 + 1],   A0h, Bh[2], Bh[3]);
            mma_bf16(acc[8+tp*2],     A1h, Bh[0], Bh[1]);
            mma_bf16(acc[8+tp*2 + 1], A1h, Bh[2], Bh[3]);
            mma_bf16(acc[tp*2],       A0l, Bh[0], Bh[1]);
            mma_bf16(acc[tp*2 + 1],   A0l, Bh[2], Bh[3]);
            mma_bf16(acc[8+tp*2],     A1l, Bh[0], Bh[1]);
            mma_bf16(acc[8+tp*2 + 1], A1l, Bh[2], Bh[3]);
            mma_bf16(acc[tp*2],       A0h, Bl[0], Bl[1]);
            mma_bf16(acc[tp*2 + 1],   A0h, Bl[2], Bl[3]);
            mma_bf16(acc[8+tp*2],     A1h, Bl[0], Bl[1]);
            mma_bf16(acc[8+tp*2 + 1], A1h, Bl[2], Bl[3]);
        }
    }
}

// ===================== persistent device scratch ==============================
__device__ unsigned short g_ebf[(size_t)BB*NN*32768];
__device__ uint32_t g_mbuf[(size_t)BB*NN*NN*CD/2];     // m as packed fp16 pairs
__device__ float g_h   [BB*NN*CD];
__device__ float g_hp  [BB*NN*512];
__device__ float g_ms  [BB*NN*CD];
__device__ float g_gi  [BB*NN*384];
__device__ float g_gh  [BB*NN*384];
__device__ int   g_iu  [PP];
__device__ int   g_ju  [PP];
__device__ unsigned short g_wt[4*32768];
__device__ unsigned short g_wr[4*32768];

// ===================== prep kernels ===========================================
__global__ void k_prep_w(const float* __restrict__ Wl_e, const float* __restrict__ Wm_e,
                         const float* __restrict__ Wu_e, const float* __restrict__ Wu_m) {
    int idx = blockIdx.x * blockDim.x + threadIdx.x;
    if (idx >= 65536) return;
    int m = idx >> 14, r = idx & 16383, n = r >> 7, k = r & 127;
    const float* W = (m == 0) ? Wl_e : (m == 1) ? Wm_e : (m == 2) ? Wu_e : Wu_m;
    float v = W[k*128 + n];
    __nv_bfloat16 hi = __float2bfloat16(v);
    __nv_bfloat16 lo = __float2bfloat16(v - __bfloat162float(hi));
    uint32_t o = (uint32_t)m*65536u + (uint32_t)(k >> 6)*32768u + swz<7>(n, k & 63);
    *(__nv_bfloat16*)((char*)g_wt + o) = hi;
    *(__nv_bfloat16*)((char*)g_wt + o + 16384) = lo;
}

__global__ void k_prep_wr(const float* __restrict__ Wr1) {
    int idx = blockIdx.x * blockDim.x + threadIdx.x;
    if (idx < NN*NN) {
        int i = idx / NN, j = idx % NN;
        if (j > i) {
            int p = i*(NN-1) - i*(i-1)/2 + (j - i - 1);
            g_iu[p] = i; g_ju[p] = j;
        }
    }
    if (idx >= 65536) return;
    int n = idx >> 8, k = idx & 255;
    float v = Wr1[k*256 + n];
    __nv_bfloat16 hi = __float2bfloat16(v);
    __nv_bfloat16 lo = __float2bfloat16(v - __bfloat162float(hi));
    uint32_t o = (uint32_t)(n >> 6)*65536u + (uint32_t)(k >> 7)*32768u + swz<8>(n & 63, k & 127);
    *(__nv_bfloat16*)((char*)g_wr + o) = hi;
    *(__nv_bfloat16*)((char*)g_wr + o + 16384) = lo;
}

// ===================== node projections (+ first-round h copy) ================
__global__ __launch_bounds__(256)
void k_hp(const float* __restrict__ nf,
          const float* __restrict__ Wl_w, const float* __restrict__ Wl_v,
          const float* __restrict__ Wm_w, const float* __restrict__ Wm_v,
          const float* __restrict__ bl1,  const float* __restrict__ bm, int first) {
    __shared__ float sA[32*128];
    int row0 = blockIdx.x * 32;
    int sel = blockIdx.y;
    const float* W = (sel == 0) ? Wl_w : (sel == 1) ? Wl_v : (sel == 2) ? Wm_w : Wm_v;
    const float* bias = (sel == 0) ? bl1 : (sel == 2) ? bm : nullptr;
    int colOff = sel << 7;
    const float* hsrc = first ? nf : g_h;
    for (int t = threadIdx.x; t < 1024; t += 256) {
        float4 v = ((const float4*)(hsrc + (size_t)row0*128))[t];
        ((float4*)sA)[t] = v;
        if (first && sel == 0) ((float4*)(g_h + (size_t)row0*128))[t] = v;
    }
    __syncthreads();
    int col = threadIdx.x & 127;
    int half = threadIdx.x >> 7;
    float acc[16];
#pragma unroll
    for (int r = 0; r < 16; ++r) acc[r] = 0.f;
    const float* sAr = sA + half*16*128;
    for (int k = 0; k < 128; ++k) {
        float w = W[(size_t)k*128 + col];
#pragma unroll
        for (int r = 0; r < 16; ++r) acc[r] = fmaf(sAr[r*128 + k], w, acc[r]);
    }
    float bv = bias ? bias[col] : 0.f;
    for (int r = 0; r < 16; ++r)
        g_hp[(size_t)(row0 + half*16 + r)*512 + colOff + col] = acc[r] + bv;
}

__global__ __launch_bounds__(256)
void k_gig(const float* __restrict__ Wih, const float* __restrict__ Whh,
           const float* __restrict__ bih, const float* __restrict__ bhh) {
    __shared__ float sA[32*128];
    int row0 = blockIdx.x * 32;
    int c0 = blockIdx.y * 128;
    int z = blockIdx.z;
    const float* A = z ? g_h : g_ms;
    const float* W = z ? Whh : Wih;
    const float* bias = z ? bhh : bih;
    float* C = z ? g_gh : g_gi;
    for (int t = threadIdx.x; t < 1024; t += 256)
        ((float4*)sA)[t] = ((const float4*)(A + (size_t)row0*128))[t];
    __syncthreads();
    int col = c0 + (threadIdx.x & 127);
    int half = threadIdx.x >> 7;
    float acc[16];
#pragma unroll
    for (int r = 0; r < 16; ++r) acc[r] = 0.f;
    const float* sAr = sA + half*16*128;
    for (int k = 0; k < 128; ++k) {
        float w = W[(size_t)k*384 + col];
#pragma unroll
        for (int r = 0; r < 16; ++r) acc[r] = fmaf(sAr[r*128 + k], w, acc[r]);
    }
    float bv = bias[col];
    for (int r = 0; r < 16; ++r)
        C[(size_t)(row0 + half*16 + r)*384 + col] = acc[r] + bv;
}

// ===================== fused edge kernel: j-split, validity-skipped ===========
#define EHI 0u
#define ELO 16384u
#define EW0 32768u
#define EW1 65536u
#define ESCR 98304u
#define EDGE_SMEM 99328

__global__ __launch_bounds__(128, 2)
void k_edge_mma(const float* __restrict__ wl2, const float* __restrict__ bl2,
                const float* __restrict__ bu,  const int* __restrict__ ev,
                const int* __restrict__ eids,  const float* __restrict__ emb, int first) {
    extern __shared__ char smem[];
    uint32_t sb = smem_u32(smem);
    int tid = threadIdx.x, warp = tid >> 5, l = tid & 31, q = l & 3;
    int cta = blockIdx.x;
    int bi = cta >> 1, jh = cta & 1;
    int b = bi >> 7, i = bi & 127;
    int vn = ev[b];
    bool pmi = (i < vn);
    bool ctaValid = pmi && (jh*64 < vn);
    const char* wsrc = (const char*)g_wt;
    char* eb = (char*)g_ebf + (size_t)bi*65536;

    // ---- dead CTA: nothing to compute; round 0 must persist init e rows ----
    if (!ctaValid) {
        if (first) {
            for (int t = tid; t < 2048; t += 128) {
                int lr = t >> 5, c4 = t & 31;
                int gj = jh*64 + lr;
                int id = eids[((size_t)bi << 7) + gj];
                float4 v = ((const float4*)emb)[id*32 + c4];
                uint32_t h01, l01, h23, l23;
                split_pair(v.x, v.y, h01, l01);
                split_pair(v.z, v.w, h23, l23);
                uint32_t go = swz<8>(gj, c4 << 2);
                *(uint2*)(eb + go)          = make_uint2(h01, h23);
                *(uint2*)(eb + 32768u + go) = make_uint2(l01, l23);
            }
        }
        return;
    }

    const int mats[8] = {0, 0, 2, 2, 1, 1, 3, 3};   // G1,G1,G3,G3,G2,G2,G4,G4

    if (!first) {
#pragma unroll
        for (int t = 0; t < 8; ++t)
            cp16(sb + EHI + (uint32_t)(tid + t*128)*16u,
                 eb + (uint32_t)jh*16384u + (size_t)(tid + t*128)*16);
#pragma unroll
        for (int t = 0; t < 8; ++t)
            cp16(sb + ELO + (uint32_t)(tid + t*128)*16u,
                 eb + 32768u + (uint32_t)jh*16384u + (size_t)(tid + t*128)*16);
        CP_COMMIT();
    }
#pragma unroll
    for (int t = 0; t < 16; ++t)
        cp16(sb + EW0 + (uint32_t)(tid + t*128)*16u, wsrc + (size_t)(tid + t*128)*16);
    CP_COMMIT();
#pragma unroll
    for (int t = 0; t < 16; ++t)
        cp16(sb + EW1 + (uint32_t)(tid + t*128)*16u, wsrc + 32768 + (size_t)(tid + t*128)*16);
    CP_COMMIT();

    if (first) {
        int* sEid = (int*)(smem + ESCR);
        if (tid < 64) sEid[tid] = eids[((size_t)bi << 7) + jh*64 + tid];
        __syncthreads();
        for (int t = tid; t < 2048; t += 128) {
            int lr = t >> 5, c4 = t & 31;
            int id = sEid[lr];
            float4 v = ((const float4*)emb)[id*32 + c4];
            uint32_t h01, l01, h23, l23;
            split_pair(v.x, v.y, h01, l01);
            split_pair(v.z, v.w, h23, l23);
            uint32_t o = swz<8>(lr, c4 << 2);
            *(uint2*)(smem + EHI + o) = make_uint2(h01, h23);
            *(uint2*)(smem + ELO + o) = make_uint2(l01, l23);
            int gj = jh*64 + lr;
            if (gj >= vn) {
                uint32_t go = swz<8>(gj, c4 << 2);
                *(uint2*)(eb + go)          = make_uint2(h01, h23);
                *(uint2*)(eb + 32768u + go) = make_uint2(l01, l23);
            }
        }
    }

    int wg = warp >> 1, nh = warp & 1;
    int rbase = wg << 5, ncol0 = nh << 6;
    int r0 = l >> 2;
    int Ls[4] = { rbase + r0, rbase + r0 + 8, rbase + r0 + 16, rbase + r0 + 24 };
    bool vs[4];
#pragma unroll
    for (int k2 = 0; k2 < 4; ++k2) vs[k2] = (jh*64 + Ls[k2] < vn);
    const float* hpi = g_hp + (size_t)bi*512;
    float acc[16][4], accU[16][4];
    float sig[4];

#pragma unroll
    for (int c = 0; c < 8; ++c) {
        if (c == 7) { CP_WAIT0(); } else { CP_WAIT1(); }
        __syncthreads();
        if (c == 0 || c == 4) {
#pragma unroll
            for (int t = 0; t < 16; ++t)
#pragma unroll
                for (int e = 0; e < 4; ++e) acc[t][e] = 0.f;
        }
        if (c == 2) {
#pragma unroll
            for (int t = 0; t < 16; ++t)
#pragma unroll
                for (int e = 0; e < 4; ++e) accU[t][e] = 0.f;
        }
        uint32_t wb = sb + EW0 + (uint32_t)(c & 1)*32768u;
        float (*tg)[4] = (c == 2 || c == 3 || c >= 6) ? accU : acc;
        gemm_split42<8,7,4>(sb, EHI, ELO, wb, wb + 16384u, rbase, ncol0, (c & 1)*4, l, tg);

        if (c == 1) {
            float par[4] = {0.f, 0.f, 0.f, 0.f};
#pragma unroll
            for (int rt = 0; rt < 2; ++rt) {
                const float* hvA = g_hp + ((size_t)(b*NN + jh*64 + Ls[rt*2]))*512 + 128;
                const float* hvB = g_hp + ((size_t)(b*NN + jh*64 + Ls[rt*2+1]))*512 + 128;
#pragma unroll
                for (int nt = 0; nt < 8; ++nt) {
                    int cc = ncol0 + (nt << 3) + (q << 1);
                    float2 hw = *(const float2*)(hpi + cc);
                    float2 w2 = *(const float2*)(wl2 + cc);
                    float2 vA = *(const float2*)(hvA + cc);
                    float2 vB = *(const float2*)(hvB + cc);
                    const float* a = acc[rt*8 + nt];
                    par[rt*2]   = fmaf(fmaxf(a[0] + hw.x + vA.x, 0.f), w2.x, par[rt*2]);
                    par[rt*2]   = fmaf(fmaxf(a[1] + hw.y + vA.y, 0.f), w2.y, par[rt*2]);
                    par[rt*2+1] = fmaf(fmaxf(a[2] + hw.x + vB.x, 0.f), w2.x, par[rt*2+1]);
                    par[rt*2+1] = fmaf(fmaxf(a[3] + hw.y + vB.y, 0.f), w2.y, par[rt*2+1]);
                }
            }
#pragma unroll
            for (int k2 = 0; k2 < 4; ++k2) {
                par[k2] += __shfl_xor_sync(~0u, par[k2], 1);
                par[k2] += __shfl_xor_sync(~0u, par[k2], 2);
            }
            float* sPart = (float*)(smem + ESCR);
            if (q == 0) {
#pragma unroll
                for (int k2 = 0; k2 < 4; ++k2) sPart[Ls[k2]*2 + nh] = par[k2];
            }
            __syncthreads();
            float bl2v = bl2[0];
#pragma unroll
            for (int k2 = 0; k2 < 4; ++k2) {
                float adj = sPart[Ls[k2]*2] + sPart[Ls[k2]*2 + 1] + bl2v;
                sig[k2] = vs[k2] ? (1.f/(1.f + expf(-adj))) : 0.f;
            }
        }
        if (c == 5) {
            __syncthreads();
            uint32_t* mbu = g_mbuf + (size_t)bi*NN*(CD/2);
#pragma unroll
            for (int rt = 0; rt < 2; ++rt) {
                int RA = Ls[rt*2], RB = Ls[rt*2+1];
                int gA = jh*64 + RA, gB = jh*64 + RB;
                const float* hvA = g_hp + ((size_t)(b*NN + gA))*512 + 384;
                const float* hvB = g_hp + ((size_t)(b*NN + gB))*512 + 384;
#pragma unroll
                for (int nt = 0; nt < 8; ++nt) {
                    int cc = ncol0 + (nt << 3) + (q << 1);
                    float2 hw = *(const float2*)(hpi + 256 + cc);
                    float2 vA = *(const float2*)(hvA + cc);
                    float2 vB = *(const float2*)(hvB + cc);
                    const float* a = acc[rt*8 + nt];
                    float mA0 = fmaxf(a[0] + hw.x + vA.x, 0.f) * sig[rt*2];
                    float mA1 = fmaxf(a[1] + hw.y + vA.y, 0.f) * sig[rt*2];
                    float mB0 = fmaxf(a[2] + hw.x + vB.x, 0.f) * sig[rt*2+1];
                    float mB1 = fmaxf(a[3] + hw.y + vB.y, 0.f) * sig[rt*2+1];
                    *(__half2*)&mbu[gA*(CD/2) + (cc >> 1)] = __floats2half2_rn(mA0, mA1);
                    *(__half2*)&mbu[gB*(CD/2) + (cc >> 1)] = __floats2half2_rn(mB0, mB1);
                    uint32_t hA, lA, hB, lB;
                    split_pair(mA0, mA1, hA, lA);
                    split_pair(mB0, mB1, hB, lB);
                    uint32_t oA = swz<8>(RA, cc), oB = swz<8>(RB, cc);
                    *(uint32_t*)(smem + EHI + oA) = hA;
                    *(uint32_t*)(smem + ELO + oA) = lA;
                    *(uint32_t*)(smem + EHI + oB) = hB;
                    *(uint32_t*)(smem + ELO + oB) = lB;
                }
            }
        }
        __syncthreads();
        if (c + 2 < 8) {
            uint32_t db = sb + EW0 + (uint32_t)(c & 1)*32768u;
            const char* src = wsrc + (size_t)mats[c + 2]*65536 + (size_t)(c & 1)*32768;
#pragma unroll
            for (int t = 0; t < 16; ++t)
                cp16(db + (uint32_t)(tid + t*128)*16u, src + (size_t)(tid + t*128)*16);
            CP_COMMIT();
        }
    }

    // epi3: e_new = relu(accU + bu) where valid; invalid rows keep old state
#pragma unroll
    for (int rt = 0; rt < 2; ++rt) {
        int gA = jh*64 + Ls[rt*2], gB = jh*64 + Ls[rt*2+1];
#pragma unroll
        for (int nt = 0; nt < 8; ++nt) {
            int cc = ncol0 + (nt << 3) + (q << 1);
            float2 b2 = *(const float2*)(bu + cc);
            const float* a = accU[rt*8 + nt];
            if (vs[rt*2]) {
                uint32_t h, lo2;
                split_pair(fmaxf(a[0] + b2.x, 0.f), fmaxf(a[1] + b2.y, 0.f), h, lo2);
                uint32_t o = swz<8>(gA, cc);
                *(uint32_t*)(eb + o) = h;
                *(uint32_t*)(eb + 32768u + o) = lo2;
            }
            if (vs[rt*2+1]) {
                uint32_t h, lo2;
                split_pair(fmaxf(a[2] + b2.x, 0.f), fmaxf(a[3] + b2.y, 0.f), h, lo2);
                uint32_t o = swz<8>(gB, cc);
                *(uint32_t*)(eb + o) = h;
                *(uint32_t*)(eb + 32768u + o) = lo2;
            }
        }
    }
}

// ===================== ms reduce (packed fp16, i < vn) / GRU ==================
__global__ void k_reduce_ms(const int* __restrict__ ev) {
    int t = blockIdx.x * blockDim.x + threadIdx.x;
    if (t >= BB*NN*CD/4) return;
    int b   = t / (NN*CD/4);
    int jk4 = t % (NN*CD/4);
    int vn = ev[b];
    const uint2* base = (const uint2*)g_mbuf + (size_t)b*NN*(NN*CD/4) + jk4;
    float4 s = make_float4(0.f, 0.f, 0.f, 0.f);
    for (int i = 0; i < vn; ++i) {
        uint2 u = base[(size_t)i*(NN*CD/4)];
        float2 p0 = __half22float2(*(__half2*)&u.x);
        float2 p1 = __half22float2(*(__half2*)&u.y);
        s.x += p0.x; s.y += p0.y; s.z += p1.x; s.w += p1.y;
    }
    ((float4*)g_ms)[t] = s;
}

__global__ void k_gru(const int* __restrict__ ev) {
    int t = blockIdx.x * blockDim.x + threadIdx.x;
    if (t >= BB*NN*CD) return;
    int row = t / CD, c = t % CD;
    int b = row / NN, n = row % NN;
    if (n >= ev[b]) return;
    const float* gi = g_gi + (size_t)row*384;
    const float* gh = g_gh + (size_t)row*384;
    float ir = gi[c], iz = gi[CD+c], in = gi[2*CD+c];
    float hr = gh[c], hz = gh[CD+c], hn = gh[2*CD+c];
    float r  = 1.f/(1.f + expf(-(ir+hr)));
    float z  = 1.f/(1.f + expf(-(iz+hz)));
    float nn = tanhf(in + r*hn);
    float hold = g_h[t];
    g_h[t] = (1.f - z)*nn + z*hold;
}

// ===================== readout (HMMA, validity-skipped blocks) ================
#define ROF_AHI 0u
#define ROF_ALO 65536u
#define ROF_W0  131072u
#define ROF_W1  163840u
#define RO_SMEM 196608

__global__ __launch_bounds__(256, 1)
void k_readout_mma(const float* __restrict__ br1, const float* __restrict__ Wr2g,
                   const float* __restrict__ br2, const int* __restrict__ ev,
                   float* __restrict__ out) {
    extern __shared__ char smem[];
    __shared__ float sWr2[2560];
    __shared__ float sBr1[256];
    uint32_t sb = smem_u32(smem);
    int tid = threadIdx.x, warp = tid >> 5, l = tid & 31, q = l & 3;
    int b = blockIdx.y, p0 = blockIdx.x * 128;
    int vn = ev[b];
    const char* wsrc = (const char*)g_wr;

    // block-level validity: any pair with ju < vn?
    int myValid = 0;
    if (tid < 128) {
        int p = p0 + tid;
        if (p < PP && g_ju[p] < vn) myValid = 1;
    }
    if (!__syncthreads_or(myValid)) return;

#pragma unroll
    for (int t = 0; t < 8; ++t)
        cp16(sb + ROF_W0 + (uint32_t)(tid + t*256)*16u, wsrc + (size_t)(tid + t*256)*16);
    CP_COMMIT();
#pragma unroll
    for (int t = 0; t < 8; ++t)
        cp16(sb + ROF_W1 + (uint32_t)(tid + t*256)*16u, wsrc + 32768 + (size_t)(tid + t*256)*16);
    CP_COMMIT();

    for (int t = tid; t < 2560; t += 256) sWr2[t] = Wr2g[t];
    if (tid < 256) sBr1[tid] = br1[tid];

    for (int t = tid; t < 8192; t += 256) {
        int lp = t >> 6, c = (t & 63) << 2;
        int p = p0 + lp; if (p >= PP) p = PP - 1;
        int iu = g_iu[p], ju = g_ju[p];
        const char* base; uint32_t o;
        if (c < 128) {
            base = (const char*)g_ebf + (size_t)(b*NN + iu)*65536;
            o = swz<8>(ju, c);
        } else {
            base = (const char*)g_ebf + (size_t)(b*NN + ju)*65536;
            o = swz<8>(iu, c - 128);
        }
        uint2 hi = *(const uint2*)(base + o);
        uint2 lo = *(const uint2*)(base + 32768 + o);
        uint32_t off = swz<9>(lp, c);
        *(uint2*)(smem + ROF_AHI + off) = hi;
        *(uint2*)(smem + ROF_ALO + off) = lo;
    }

    int rA = (warp << 4) + (l >> 2), rB = rA + 8;
    float outA[10], outB[10];
#pragma unroll
    for (int t5 = 0; t5 < 10; ++t5) { outA[t5] = 0.f; outB[t5] = 0.f; }
    float acc[8][4];

#pragma unroll
    for (int c = 0; c < 8; ++c) {
        if (c == 7) { CP_WAIT0(); } else { CP_WAIT1(); }
        __syncthreads();
        if ((c & 1) == 0) {
#pragma unroll
            for (int t = 0; t < 8; ++t)
#pragma unroll
                for (int e = 0; e < 4; ++e) acc[t][e] = 0.f;
        }
        uint32_t wb = sb + ROF_W0 + (uint32_t)(c & 1)*32768u;
        gemm_split2<9,8,8,4>(sb, ROF_AHI, ROF_ALO, wb, wb + 16384u, warp << 4, (c & 1)*8, l, acc);
        if (c & 1) {
            int cc = c >> 1;
#pragma unroll
            for (int t = 0; t < 8; ++t) {
                int n0 = (cc << 6) + (t << 3) + (q << 1);
#pragma unroll
                for (int e = 0; e < 4; ++e) {
                    int n = n0 + (e & 1);
                    float h = fmaxf(acc[t][e] + sBr1[n], 0.f);
                    float* o = (e < 2) ? outA : outB;
                    const float* w = sWr2 + n*10;
#pragma unroll
                    for (int t5 = 0; t5 < 10; ++t5) o[t5] = fmaf(h, w[t5], o[t5]);
                }
            }
        }
        __syncthreads();
        if (c + 2 < 8) {
            uint32_t db = sb + ROF_W0 + (uint32_t)(c & 1)*32768u;
            const char* src = wsrc + (size_t)(c + 2)*32768;
#pragma unroll
            for (int t = 0; t < 8; ++t)
                cp16(db + (uint32_t)(tid + t*256)*16u, src + (size_t)(tid + t*256)*16);
            CP_COMMIT();
        }
    }

#pragma unroll
    for (int t5 = 0; t5 < 10; ++t5) {
        outA[t5] += __shfl_xor_sync(~0u, outA[t5], 1);
        outA[t5] += __shfl_xor_sync(~0u, outA[t5], 2);
        outB[t5] += __shfl_xor_sync(~0u, outB[t5], 1);
        outB[t5] += __shfl_xor_sync(~0u, outB[t5], 2);
    }
    if (q == 0) {
#pragma unroll
        for (int h2 = 0; h2 < 2; ++h2) {
            int r = h2 ? rB : rA;
            float* o = h2 ? outB : outA;
            int p = p0 + r;
            if (p < PP) {
                int iu = g_iu[p], ju = g_ju[p];
                if (ju < vn) {
                    int idx = iu*vn - iu*(iu+1)/2 + (ju - iu - 1);
#pragma unroll
                    for (int t5 = 0; t5 < 10; ++t5)
                        out[(((size_t)b*5 + (t5 >> 1))*PP + idx)*2 + (t5 & 1)] = o[t5] + br2[t5];
                }
            }
        }
    }
}

// ===================== host orchestration =====================================
extern "C" void kernel_launch(void* const* d_in, const int* in_sizes, int n_in,
                              void* d_out, int out_size) {
    const int*   edge_ids      = (const int*)  d_in[0];
    const float* node_features = (const float*)d_in[1];
    const int*   ev            = (const int*)  d_in[3];
    const float* emb           = (const float*)d_in[4];
    const float* Wl_e = (const float*)d_in[5];
    const float* Wl_w = (const float*)d_in[6];
    const float* Wl_v = (const float*)d_in[7];
    const float* bl1  = (const float*)d_in[8];
    const float* wl2  = (const float*)d_in[9];
    const float* bl2  = (const float*)d_in[10];
    const float* Wm_w = (const float*)d_in[11];
    const float* Wm_v = (const float*)d_in[12];
    const float* Wm_e = (const float*)d_in[13];
    const float* bm   = (const float*)d_in[14];
    const float* Wu_e = (const float*)d_in[15];
    const float* Wu_m = (const float*)d_in[16];
    const float* bu   = (const float*)d_in[17];
    const float* W_ih = (const float*)d_in[18];
    const float* W_hh = (const float*)d_in[19];
    const float* b_ih = (const float*)d_in[20];
    const float* b_hh = (const float*)d_in[21];
    const float* Wr1  = (const float*)d_in[22];
    const float* br1  = (const float*)d_in[23];
    const float* Wr2  = (const float*)d_in[24];
    const float* br2  = (const float*)d_in[25];

    cudaFuncSetAttribute(k_edge_mma,    cudaFuncAttributeMaxDynamicSharedMemorySize, EDGE_SMEM);
    cudaFuncSetAttribute(k_readout_mma, cudaFuncAttributeMaxDynamicSharedMemorySize, RO_SMEM);

    // launches: prep_w(0), prep_wr(1), hp(2), edge(3) — ncu captures index 3
    k_prep_w<<<256, 256>>>(Wl_e, Wm_e, Wu_e, Wu_m);
    k_prep_wr<<<256, 256>>>(Wr1);
    k_hp<<<dim3(128, 4), 256>>>(node_features, Wl_w, Wl_v, Wm_w, Wm_v, bl1, bm, 1);

    for (int r = 0; r < RNDS; ++r) {
        if (r > 0)
            k_hp<<<dim3(128, 4), 256>>>(node_features, Wl_w, Wl_v, Wm_w, Wm_v, bl1, bm, 0);
        k_edge_mma<<<BB*NN*2, 128, EDGE_SMEM>>>(wl2, bl2, bu, ev, edge_ids, emb, r == 0);
        k_reduce_ms<<<(BB*NN*CD/4 + 255)/256, 256>>>(ev);
        k_gig<<<dim3(128, 3, 2), 256>>>(W_ih, W_hh, b_ih, b_hh);
        k_gru<<<(BB*NN*CD + 255)/256, 256>>>(ev);
    }

    cudaMemsetAsync(d_out, 0, (size_t)out_size * sizeof(float));
    k_readout_mma<<<dim3(64, BB), 256, RO_SMEM>>>(br1, Wr2, br2, ev, (float*)d_out);
}

// round 13
// speedup vs baseline: 6.5250x; 1.0547x over previous
#include <cuda_runtime.h>
#include <cuda_bf16.h>
#include <cuda_fp16.h>
#include <math.h>
#include <stdint.h>

#define BB 32
#define NN 128
#define CD 128
#define PP 8128
#define RNDS 3

// ===================== low-level helpers (base ISA only) ======================
__device__ __forceinline__ uint32_t smem_u32(const void* p) {
    uint32_t a;
    asm("{ .reg .u64 t; cvta.to.shared.u64 t, %1; cvt.u32.u64 %0, t; }" : "=r"(a) : "l"(p));
    return a;
}
__device__ __forceinline__ void ldsm4(uint32_t r[4], uint32_t addr) {
    asm volatile("ldmatrix.sync.aligned.m8n8.x4.shared.b16 {%0,%1,%2,%3}, [%4];"
        : "=r"(r[0]), "=r"(r[1]), "=r"(r[2]), "=r"(r[3]) : "r"(addr));
}
__device__ __forceinline__ void mma_bf16(float c[4], const uint32_t a[4],
                                         uint32_t b0, uint32_t b1) {
    asm volatile("mma.sync.aligned.m16n8k16.row.col.f32.bf16.bf16.f32 "
        "{%0,%1,%2,%3}, {%4,%5,%6,%7}, {%8,%9}, {%0,%1,%2,%3};"
        : "+f"(c[0]), "+f"(c[1]), "+f"(c[2]), "+f"(c[3])
        : "r"(a[0]), "r"(a[1]), "r"(a[2]), "r"(a[3]), "r"(b0), "r"(b1));
}
__device__ __forceinline__ void cp16(uint32_t dst, const void* src) {
    asm volatile("cp.async.cg.shared.global [%0], [%1], 16;" :: "r"(dst), "l"(src));
}
#define CP_COMMIT() asm volatile("cp.async.commit_group;" ::: "memory")
#define CP_WAIT1()  asm volatile("cp.async.wait_group 1;" ::: "memory")
#define CP_WAIT0()  asm volatile("cp.async.wait_group 0;" ::: "memory")

__device__ __forceinline__ void split_pair(float x, float y, uint32_t& hi, uint32_t& lo) {
    __nv_bfloat16 hx = __float2bfloat16(x), hy = __float2bfloat16(y);
    float rx = x - __bfloat162float(hx), ry = y - __bfloat162float(hy);
    __nv_bfloat16 lx = __float2bfloat16(rx), ly = __float2bfloat16(ry);
    hi = (uint32_t)*(uint16_t*)&hx | ((uint32_t)*(uint16_t*)&hy << 16);
    lo = (uint32_t)*(uint16_t*)&lx | ((uint32_t)*(uint16_t*)&ly << 16);
}
template<int SH>
__device__ __host__ __forceinline__ uint32_t swz(int r, int k) {
    return ((uint32_t)r << SH) + ((uint32_t)(((k >> 3) ^ (r & 7))) << 4) + ((uint32_t)(k & 7) << 1);
}

// ---- readout GEMM: warp = M16 x N64 (NTP=4), 3-pass split, ILP-reordered ----
template<int SHA, int SHB, int NKS, int NTP>
__device__ __forceinline__ void gemm_split2(uint32_t sb, uint32_t offA, uint32_t offAlo,
                                            uint32_t bHi, uint32_t bLo,
                                            int mbase, int ks0, int lane, float acc[][4]) {
    int arow = mbase + (lane & 7) + (((lane >> 3) & 1) << 3);
    uint32_t aBase   = sb + offA + ((uint32_t)arow << SHA);
    uint32_t aBaseLo = sb + offAlo + ((uint32_t)arow << SHA);
    int a7 = arow & 7, agrp = (lane >> 4) & 1;
    int brow0 = (lane & 7) + ((lane >> 4) << 3);
    int b7 = lane & 7, bkb = (lane >> 3) & 1;
#pragma unroll
    for (int ks = 0; ks < NKS; ++ks) {
        uint32_t ak = (uint32_t)(((((ks0 + ks) << 1) | agrp) ^ a7) << 4);
        uint32_t Ah[4], Al[4];
        ldsm4(Ah, aBase + ak);
        ldsm4(Al, aBaseLo + ak);
        uint32_t bk = (uint32_t)((((ks << 1) | bkb) ^ b7) << 4);
#pragma unroll
        for (int tp = 0; tp < NTP; ++tp) {
            uint32_t brow = (uint32_t)(brow0 + (tp << 4)) << SHB;
            uint32_t Bh[4], Bl[4];
            ldsm4(Bh, bHi + brow + bk);
            ldsm4(Bl, bLo + brow + bk);
            mma_bf16(acc[2*tp],     Ah, Bh[0], Bh[1]);
            mma_bf16(acc[2*tp + 1], Ah, Bh[2], Bh[3]);
            mma_bf16(acc[2*tp],     Al, Bh[0], Bh[1]);
            mma_bf16(acc[2*tp + 1], Al, Bh[2], Bh[3]);
            mma_bf16(acc[2*tp],     Ah, Bl[0], Bl[1]);
            mma_bf16(acc[2*tp + 1], Ah, Bl[2], Bl[3]);
        }
    }
}

// ---- edge GEMM: warp = M32 x N32 (2 row-tiles, NTP=2), 3-pass split ----
// acc[rt*4 + tp*2 + s][4]; 8 ldsm / 24 mma per warp k-step
template<int SHA, int SHB, int NKS>
__device__ __forceinline__ void gemm_split22(uint32_t sb, uint32_t offA, uint32_t offAlo,
                                             uint32_t bHi, uint32_t bLo,
                                             int rbase, int ncol0, int ks0, int lane,
                                             float acc[][4]) {
    int arow = rbase + (lane & 7) + (((lane >> 3) & 1) << 3);
    uint32_t a0h = sb + offA   + ((uint32_t)arow << SHA);
    uint32_t a0l = sb + offAlo + ((uint32_t)arow << SHA);
    uint32_t a1h = a0h + (16u << SHA);
    uint32_t a1l = a0l + (16u << SHA);
    int a7 = lane & 7, agrp = (lane >> 4) & 1;
    int brow0 = (lane & 7) + ((lane >> 4) << 3) + ncol0;
    int b7 = lane & 7, bkb = (lane >> 3) & 1;
#pragma unroll
    for (int ks = 0; ks < NKS; ++ks) {
        uint32_t ak = (uint32_t)(((((ks0 + ks) << 1) | agrp) ^ a7) << 4);
        uint32_t A0h[4], A0l[4], A1h[4], A1l[4];
        ldsm4(A0h, a0h + ak); ldsm4(A0l, a0l + ak);
        ldsm4(A1h, a1h + ak); ldsm4(A1l, a1l + ak);
        uint32_t bk = (uint32_t)((((ks << 1) | bkb) ^ b7) << 4);
#pragma unroll
        for (int tp = 0; tp < 2; ++tp) {
            uint32_t brow = (uint32_t)(brow0 + (tp << 4)) << SHB;
            uint32_t Bh[4], Bl[4];
            ldsm4(Bh, bHi + brow + bk);
            ldsm4(Bl, bLo + brow + bk);
            mma_bf16(acc[tp*2],       A0h, Bh[0], Bh[1]);
            mma_bf16(acc[tp*2 + 1],   A0h, Bh[2], Bh[3]);
            mma_bf16(acc[4+tp*2],     A1h, Bh[0], Bh[1]);
            mma_bf16(acc[4+tp*2 + 1], A1h, Bh[2], Bh[3]);
            mma_bf16(acc[tp*2],       A0l, Bh[0], Bh[1]);
            mma_bf16(acc[tp*2 + 1],   A0l, Bh[2], Bh[3]);
            mma_bf16(acc[4+tp*2],     A1l, Bh[0], Bh[1]);
            mma_bf16(acc[4+tp*2 + 1], A1l, Bh[2], Bh[3]);
            mma_bf16(acc[tp*2],       A0h, Bl[0], Bl[1]);
            mma_bf16(acc[tp*2 + 1],   A0h, Bl[2], Bl[3]);
            mma_bf16(acc[4+tp*2],     A1h, Bl[0], Bl[1]);
            mma_bf16(acc[4+tp*2 + 1], A1h, Bl[2], Bl[3]);
        }
    }
}

// ===================== persistent device scratch ==============================
__device__ unsigned short g_ebf[(size_t)BB*NN*32768];
__device__ uint32_t g_mbuf[(size_t)BB*NN*NN*CD/2];
__device__ float g_h   [BB*NN*CD];
__device__ float g_hp  [BB*NN*512];
__device__ float g_ms  [BB*NN*CD];
__device__ float g_gi  [BB*NN*384];
__device__ float g_gh  [BB*NN*384];
__device__ int   g_iu  [PP];
__device__ int   g_ju  [PP];
__device__ unsigned short g_wt[4*32768];
__device__ unsigned short g_wr[4*32768];

// ===================== prep kernels ===========================================
__global__ void k_prep_w(const float* __restrict__ Wl_e, const float* __restrict__ Wm_e,
                         const float* __restrict__ Wu_e, const float* __restrict__ Wu_m) {
    int idx = blockIdx.x * blockDim.x + threadIdx.x;
    if (idx >= 65536) return;
    int m = idx >> 14, r = idx & 16383, n = r >> 7, k = r & 127;
    const float* W = (m == 0) ? Wl_e : (m == 1) ? Wm_e : (m == 2) ? Wu_e : Wu_m;
    float v = W[k*128 + n];
    __nv_bfloat16 hi = __float2bfloat16(v);
    __nv_bfloat16 lo = __float2bfloat16(v - __bfloat162float(hi));
    uint32_t o = (uint32_t)m*65536u + (uint32_t)(k >> 6)*32768u + swz<7>(n, k & 63);
    *(__nv_bfloat16*)((char*)g_wt + o) = hi;
    *(__nv_bfloat16*)((char*)g_wt + o + 16384) = lo;
}

__global__ void k_prep_wr(const float* __restrict__ Wr1) {
    int idx = blockIdx.x * blockDim.x + threadIdx.x;
    if (idx < NN*NN) {
        int i = idx / NN, j = idx % NN;
        if (j > i) {
            int p = i*(NN-1) - i*(i-1)/2 + (j - i - 1);
            g_iu[p] = i; g_ju[p] = j;
        }
    }
    if (idx >= 65536) return;
    int n = idx >> 8, k = idx & 255;
    float v = Wr1[k*256 + n];
    __nv_bfloat16 hi = __float2bfloat16(v);
    __nv_bfloat16 lo = __float2bfloat16(v - __bfloat162float(hi));
    uint32_t o = (uint32_t)(n >> 6)*65536u + (uint32_t)(k >> 7)*32768u + swz<8>(n & 63, k & 127);
    *(__nv_bfloat16*)((char*)g_wr + o) = hi;
    *(__nv_bfloat16*)((char*)g_wr + o + 16384) = lo;
}

// ===================== node projections (+ first-round h copy) ================
__global__ __launch_bounds__(256)
void k_hp(const float* __restrict__ nf,
          const float* __restrict__ Wl_w, const float* __restrict__ Wl_v,
          const float* __restrict__ Wm_w, const float* __restrict__ Wm_v,
          const float* __restrict__ bl1,  const float* __restrict__ bm, int first) {
    __shared__ float sA[32*128];
    int row0 = blockIdx.x * 32;
    int sel = blockIdx.y;
    const float* W = (sel == 0) ? Wl_w : (sel == 1) ? Wl_v : (sel == 2) ? Wm_w : Wm_v;
    const float* bias = (sel == 0) ? bl1 : (sel == 2) ? bm : nullptr;
    int colOff = sel << 7;
    const float* hsrc = first ? nf : g_h;
    for (int t = threadIdx.x; t < 1024; t += 256) {
        float4 v = ((const float4*)(hsrc + (size_t)row0*128))[t];
        ((float4*)sA)[t] = v;
        if (first && sel == 0) ((float4*)(g_h + (size_t)row0*128))[t] = v;
    }
    __syncthreads();
    int col = threadIdx.x & 127;
    int half = threadIdx.x >> 7;
    float acc[16];
#pragma unroll
    for (int r = 0; r < 16; ++r) acc[r] = 0.f;
    const float* sAr = sA + half*16*128;
    for (int k = 0; k < 128; ++k) {
        float w = W[(size_t)k*128 + col];
#pragma unroll
        for (int r = 0; r < 16; ++r) acc[r] = fmaf(sAr[r*128 + k], w, acc[r]);
    }
    float bv = bias ? bias[col] : 0.f;
    for (int r = 0; r < 16; ++r)
        g_hp[(size_t)(row0 + half*16 + r)*512 + colOff + col] = acc[r] + bv;
}

__global__ __launch_bounds__(256)
void k_gig(const float* __restrict__ Wih, const float* __restrict__ Whh,
           const float* __restrict__ bih, const float* __restrict__ bhh) {
    __shared__ float sA[32*128];
    int row0 = blockIdx.x * 32;
    int c0 = blockIdx.y * 128;
    int z = blockIdx.z;
    const float* A = z ? g_h : g_ms;
    const float* W = z ? Whh : Wih;
    const float* bias = z ? bhh : bih;
    float* C = z ? g_gh : g_gi;
    for (int t = threadIdx.x; t < 1024; t += 256)
        ((float4*)sA)[t] = ((const float4*)(A + (size_t)row0*128))[t];
    __syncthreads();
    int col = c0 + (threadIdx.x & 127);
    int half = threadIdx.x >> 7;
    float acc[16];
#pragma unroll
    for (int r = 0; r < 16; ++r) acc[r] = 0.f;
    const float* sAr = sA + half*16*128;
    for (int k = 0; k < 128; ++k) {
        float w = W[(size_t)k*384 + col];
#pragma unroll
        for (int r = 0; r < 16; ++r) acc[r] = fmaf(sAr[r*128 + k], w, acc[r]);
    }
    float bv = bias[col];
    for (int r = 0; r < 16; ++r)
        C[(size_t)(row0 + half*16 + r)*384 + col] = acc[r] + bv;
}

// ===================== fused edge kernel: 256 thr, M32xN32 warps ==============
#define EHI 0u
#define ELO 16384u
#define EW0 32768u
#define EW1 65536u
#define ESCR 98304u
#define EDGE_SMEM 99328

__global__ __launch_bounds__(256, 2)
void k_edge_mma(const float* __restrict__ wl2, const float* __restrict__ bl2,
                const float* __restrict__ bu,  const int* __restrict__ ev,
                const int* __restrict__ eids,  const float* __restrict__ emb, int first) {
    extern __shared__ char smem[];
    uint32_t sb = smem_u32(smem);
    int tid = threadIdx.x, warp = tid >> 5, l = tid & 31, q = l & 3;
    int cta = blockIdx.x;
    int bi = cta >> 1, jh = cta & 1;
    int b = bi >> 7, i = bi & 127;
    int vn = ev[b];
    bool pmi = (i < vn);
    bool ctaValid = pmi && (jh*64 < vn);
    const char* wsrc = (const char*)g_wt;
    char* eb = (char*)g_ebf + (size_t)bi*65536;

    if (!ctaValid) {
        if (first) {
            for (int t = tid; t < 2048; t += 256) {
                int lr = t >> 5, c4 = t & 31;
                int gj = jh*64 + lr;
                int id = eids[((size_t)bi << 7) + gj];
                float4 v = ((const float4*)emb)[id*32 + c4];
                uint32_t h01, l01, h23, l23;
                split_pair(v.x, v.y, h01, l01);
                split_pair(v.z, v.w, h23, l23);
                uint32_t go = swz<8>(gj, c4 << 2);
                *(uint2*)(eb + go)          = make_uint2(h01, h23);
                *(uint2*)(eb + 32768u + go) = make_uint2(l01, l23);
            }
        }
        return;
    }

    const int mats[8] = {0, 0, 2, 2, 1, 1, 3, 3};   // G1,G1,G3,G3,G2,G2,G4,G4

    if (!first) {
#pragma unroll
        for (int t = 0; t < 4; ++t)
            cp16(sb + EHI + (uint32_t)(tid + t*256)*16u,
                 eb + (uint32_t)jh*16384u + (size_t)(tid + t*256)*16);
#pragma unroll
        for (int t = 0; t < 4; ++t)
            cp16(sb + ELO + (uint32_t)(tid + t*256)*16u,
                 eb + 32768u + (uint32_t)jh*16384u + (size_t)(tid + t*256)*16);
        CP_COMMIT();
    }
#pragma unroll
    for (int t = 0; t < 8; ++t)
        cp16(sb + EW0 + (uint32_t)(tid + t*256)*16u, wsrc + (size_t)(tid + t*256)*16);
    CP_COMMIT();
#pragma unroll
    for (int t = 0; t < 8; ++t)
        cp16(sb + EW1 + (uint32_t)(tid + t*256)*16u, wsrc + 32768 + (size_t)(tid + t*256)*16);
    CP_COMMIT();

    if (first) {
        int* sEid = (int*)(smem + ESCR);
        if (tid < 64) sEid[tid] = eids[((size_t)bi << 7) + jh*64 + tid];
        __syncthreads();
        for (int t = tid; t < 2048; t += 256) {
            int lr = t >> 5, c4 = t & 31;
            int id = sEid[lr];
            float4 v = ((const float4*)emb)[id*32 + c4];
            uint32_t h01, l01, h23, l23;
            split_pair(v.x, v.y, h01, l01);
            split_pair(v.z, v.w, h23, l23);
            uint32_t o = swz<8>(lr, c4 << 2);
            *(uint2*)(smem + EHI + o) = make_uint2(h01, h23);
            *(uint2*)(smem + ELO + o) = make_uint2(l01, l23);
            int gj = jh*64 + lr;
            if (gj >= vn) {
                uint32_t go = swz<8>(gj, c4 << 2);
                *(uint2*)(eb + go)          = make_uint2(h01, h23);
                *(uint2*)(eb + 32768u + go) = make_uint2(l01, l23);
            }
        }
    }

    // warp tile: wg = row half (M32), nq = N-quarter (N32)
    int wg = warp >> 2, nq = warp & 3;
    int rbase = wg << 5, ncol0 = nq << 5;
    int r0 = l >> 2;
    int Ls[4] = { rbase + r0, rbase + r0 + 8, rbase + r0 + 16, rbase + r0 + 24 };
    bool vs[4];
#pragma unroll
    for (int k2 = 0; k2 < 4; ++k2) vs[k2] = (jh*64 + Ls[k2] < vn);
    const float* hpi = g_hp + (size_t)bi*512;
    float acc[8][4], accU[8][4];
    float sig[4];

#pragma unroll
    for (int c = 0; c < 8; ++c) {
        if (c == 7) { CP_WAIT0(); } else { CP_WAIT1(); }
        __syncthreads();
        if (c == 0 || c == 4) {
#pragma unroll
            for (int t = 0; t < 8; ++t)
#pragma unroll
                for (int e = 0; e < 4; ++e) acc[t][e] = 0.f;
        }
        if (c == 2) {
#pragma unroll
            for (int t = 0; t < 8; ++t)
#pragma unroll
                for (int e = 0; e < 4; ++e) accU[t][e] = 0.f;
        }
        uint32_t wb = sb + EW0 + (uint32_t)(c & 1)*32768u;
        float (*tg)[4] = (c == 2 || c == 3 || c >= 6) ? accU : acc;
        gemm_split22<8,7,4>(sb, EHI, ELO, wb, wb + 16384u, rbase, ncol0, (c & 1)*4, l, tg);

        if (c == 1) {
            // epi1: z -> partial adj over this warp's N-quarter -> combine 4 -> sigmoid
            float par[4] = {0.f, 0.f, 0.f, 0.f};
#pragma unroll
            for (int rt = 0; rt < 2; ++rt) {
                const float* hvA = g_hp + ((size_t)(b*NN + jh*64 + Ls[rt*2]))*512 + 128;
                const float* hvB = g_hp + ((size_t)(b*NN + jh*64 + Ls[rt*2+1]))*512 + 128;
#pragma unroll
                for (int nt = 0; nt < 4; ++nt) {
                    int cc = ncol0 + (nt << 3) + (q << 1);
                    float2 hw = *(const float2*)(hpi + cc);
                    float2 w2 = *(const float2*)(wl2 + cc);
                    float2 vA = *(const float2*)(hvA + cc);
                    float2 vB = *(const float2*)(hvB + cc);
                    const float* a = acc[rt*4 + nt];
                    par[rt*2]   = fmaf(fmaxf(a[0] + hw.x + vA.x, 0.f), w2.x, par[rt*2]);
                    par[rt*2]   = fmaf(fmaxf(a[1] + hw.y + vA.y, 0.f), w2.y, par[rt*2]);
                    par[rt*2+1] = fmaf(fmaxf(a[2] + hw.x + vB.x, 0.f), w2.x, par[rt*2+1]);
                    par[rt*2+1] = fmaf(fmaxf(a[3] + hw.y + vB.y, 0.f), w2.y, par[rt*2+1]);
                }
            }
#pragma unroll
            for (int k2 = 0; k2 < 4; ++k2) {
                par[k2] += __shfl_xor_sync(~0u, par[k2], 1);
                par[k2] += __shfl_xor_sync(~0u, par[k2], 2);
            }
            float* sPart = (float*)(smem + ESCR);
            if (q == 0) {
#pragma unroll
                for (int k2 = 0; k2 < 4; ++k2) sPart[Ls[k2]*4 + nq] = par[k2];
            }
            __syncthreads();
            float bl2v = bl2[0];
#pragma unroll
            for (int k2 = 0; k2 < 4; ++k2) {
                const float* sp = (const float*)(smem + ESCR) + Ls[k2]*4;
                float adj = sp[0] + sp[1] + sp[2] + sp[3] + bl2v;
                sig[k2] = vs[k2] ? (1.f/(1.f + expf(-adj))) : 0.f;
            }
        }
        if (c == 5) {
            __syncthreads();   // all warps done reading E planes before m overwrites
            uint32_t* mbu = g_mbuf + (size_t)bi*NN*(CD/2);
#pragma unroll
            for (int rt = 0; rt < 2; ++rt) {
                int RA = Ls[rt*2], RB = Ls[rt*2+1];
                int gA = jh*64 + RA, gB = jh*64 + RB;
                const float* hvA = g_hp + ((size_t)(b*NN + gA))*512 + 384;
                const float* hvB = g_hp + ((size_t)(b*NN + gB))*512 + 384;
#pragma unroll
                for (int nt = 0; nt < 4; ++nt) {
                    int cc = ncol0 + (nt << 3) + (q << 1);
                    float2 hw = *(const float2*)(hpi + 256 + cc);
                    float2 vA = *(const float2*)(hvA + cc);
                    float2 vB = *(const float2*)(hvB + cc);
                    const float* a = acc[rt*4 + nt];
                    float mA0 = fmaxf(a[0] + hw.x + vA.x, 0.f) * sig[rt*2];
                    float mA1 = fmaxf(a[1] + hw.y + vA.y, 0.f) * sig[rt*2];
                    float mB0 = fmaxf(a[2] + hw.x + vB.x, 0.f) * sig[rt*2+1];
                    float mB1 = fmaxf(a[3] + hw.y + vB.y, 0.f) * sig[rt*2+1];
                    *(__half2*)&mbu[gA*(CD/2) + (cc >> 1)] = __floats2half2_rn(mA0, mA1);
                    *(__half2*)&mbu[gB*(CD/2) + (cc >> 1)] = __floats2half2_rn(mB0, mB1);
                    uint32_t hA, lA, hB, lB;
                    split_pair(mA0, mA1, hA, lA);
                    split_pair(mB0, mB1, hB, lB);
                    uint32_t oA = swz<8>(RA, cc), oB = swz<8>(RB, cc);
                    *(uint32_t*)(smem + EHI + oA) = hA;
                    *(uint32_t*)(smem + ELO + oA) = lA;
                    *(uint32_t*)(smem + EHI + oB) = hB;
                    *(uint32_t*)(smem + ELO + oB) = lB;
                }
            }
        }
        __syncthreads();
        if (c + 2 < 8) {
            uint32_t db = sb + EW0 + (uint32_t)(c & 1)*32768u;
            const char* src = wsrc + (size_t)mats[c + 2]*65536 + (size_t)(c & 1)*32768;
#pragma unroll
            for (int t = 0; t < 8; ++t)
                cp16(db + (uint32_t)(tid + t*256)*16u, src + (size_t)(tid + t*256)*16);
            CP_COMMIT();
        }
    }

    // epi3: e_new = relu(accU + bu) where valid; invalid rows keep old state
#pragma unroll
    for (int rt = 0; rt < 2; ++rt) {
        int gA = jh*64 + Ls[rt*2], gB = jh*64 + Ls[rt*2+1];
#pragma unroll
        for (int nt = 0; nt < 4; ++nt) {
            int cc = ncol0 + (nt << 3) + (q << 1);
            float2 b2 = *(const float2*)(bu + cc);
            const float* a = accU[rt*4 + nt];
            if (vs[rt*2]) {
                uint32_t h, lo2;
                split_pair(fmaxf(a[0] + b2.x, 0.f), fmaxf(a[1] + b2.y, 0.f), h, lo2);
                uint32_t o = swz<8>(gA, cc);
                *(uint32_t*)(eb + o) = h;
                *(uint32_t*)(eb + 32768u + o) = lo2;
            }
            if (vs[rt*2+1]) {
                uint32_t h, lo2;
                split_pair(fmaxf(a[2] + b2.x, 0.f), fmaxf(a[3] + b2.y, 0.f), h, lo2);
                uint32_t o = swz<8>(gB, cc);
                *(uint32_t*)(eb + o) = h;
                *(uint32_t*)(eb + 32768u + o) = lo2;
            }
        }
    }
}

// ===================== ms reduce (packed fp16, i < vn) / GRU ==================
__global__ void k_reduce_ms(const int* __restrict__ ev) {
    int t = blockIdx.x * blockDim.x + threadIdx.x;
    if (t >= BB*NN*CD/4) return;
    int b   = t / (NN*CD/4);
    int jk4 = t % (NN*CD/4);
    int vn = ev[b];
    const uint2* base = (const uint2*)g_mbuf + (size_t)b*NN*(NN*CD/4) + jk4;
    float4 s = make_float4(0.f, 0.f, 0.f, 0.f);
    for (int i = 0; i < vn; ++i) {
        uint2 u = base[(size_t)i*(NN*CD/4)];
        float2 p0 = __half22float2(*(__half2*)&u.x);
        float2 p1 = __half22float2(*(__half2*)&u.y);
        s.x += p0.x; s.y += p0.y; s.z += p1.x; s.w += p1.y;
    }
    ((float4*)g_ms)[t] = s;
}

__global__ void k_gru(const int* __restrict__ ev) {
    int t = blockIdx.x * blockDim.x + threadIdx.x;
    if (t >= BB*NN*CD) return;
    int row = t / CD, c = t % CD;
    int b = row / NN, n = row % NN;
    if (n >= ev[b]) return;
    const float* gi = g_gi + (size_t)row*384;
    const float* gh = g_gh + (size_t)row*384;
    float ir = gi[c], iz = gi[CD+c], in = gi[2*CD+c];
    float hr = gh[c], hz = gh[CD+c], hn = gh[2*CD+c];
    float r  = 1.f/(1.f + expf(-(ir+hr)));
    float z  = 1.f/(1.f + expf(-(iz+hz)));
    float nn = tanhf(in + r*hn);
    float hold = g_h[t];
    g_h[t] = (1.f - z)*nn + z*hold;
}

// ===================== readout (HMMA, validity-skipped blocks) ================
#define ROF_AHI 0u
#define ROF_ALO 65536u
#define ROF_W0  131072u
#define ROF_W1  163840u
#define RO_SMEM 196608

__global__ __launch_bounds__(256, 1)
void k_readout_mma(const float* __restrict__ br1, const float* __restrict__ Wr2g,
                   const float* __restrict__ br2, const int* __restrict__ ev,
                   float* __restrict__ out) {
    extern __shared__ char smem[];
    __shared__ float sWr2[2560];
    __shared__ float sBr1[256];
    uint32_t sb = smem_u32(smem);
    int tid = threadIdx.x, warp = tid >> 5, l = tid & 31, q = l & 3;
    int b = blockIdx.y, p0 = blockIdx.x * 128;
    int vn = ev[b];
    const char* wsrc = (const char*)g_wr;

    int myValid = 0;
    if (tid < 128) {
        int p = p0 + tid;
        if (p < PP && g_ju[p] < vn) myValid = 1;
    }
    if (!__syncthreads_or(myValid)) return;

#pragma unroll
    for (int t = 0; t < 8; ++t)
        cp16(sb + ROF_W0 + (uint32_t)(tid + t*256)*16u, wsrc + (size_t)(tid + t*256)*16);
    CP_COMMIT();
#pragma unroll
    for (int t = 0; t < 8; ++t)
        cp16(sb + ROF_W1 + (uint32_t)(tid + t*256)*16u, wsrc + 32768 + (size_t)(tid + t*256)*16);
    CP_COMMIT();

    for (int t = tid; t < 2560; t += 256) sWr2[t] = Wr2g[t];
    if (tid < 256) sBr1[tid] = br1[tid];

    for (int t = tid; t < 8192; t += 256) {
        int lp = t >> 6, c = (t & 63) << 2;
        int p = p0 + lp; if (p >= PP) p = PP - 1;
        int iu = g_iu[p], ju = g_ju[p];
        const char* base; uint32_t o;
        if (c < 128) {
            base = (const char*)g_ebf + (size_t)(b*NN + iu)*65536;
            o = swz<8>(ju, c);
        } else {
            base = (const char*)g_ebf + (size_t)(b*NN + ju)*65536;
            o = swz<8>(iu, c - 128);
        }
        uint2 hi = *(const uint2*)(base + o);
        uint2 lo = *(const uint2*)(base + 32768 + o);
        uint32_t off = swz<9>(lp, c);
        *(uint2*)(smem + ROF_AHI + off) = hi;
        *(uint2*)(smem + ROF_ALO + off) = lo;
    }

    int rA = (warp << 4) + (l >> 2), rB = rA + 8;
    float outA[10], outB[10];
#pragma unroll
    for (int t5 = 0; t5 < 10; ++t5) { outA[t5] = 0.f; outB[t5] = 0.f; }
    float acc[8][4];

#pragma unroll
    for (int c = 0; c < 8; ++c) {
        if (c == 7) { CP_WAIT0(); } else { CP_WAIT1(); }
        __syncthreads();
        if ((c & 1) == 0) {
#pragma unroll
            for (int t = 0; t < 8; ++t)
#pragma unroll
                for (int e = 0; e < 4; ++e) acc[t][e] = 0.f;
        }
        uint32_t wb = sb + ROF_W0 + (uint32_t)(c & 1)*32768u;
        gemm_split2<9,8,8,4>(sb, ROF_AHI, ROF_ALO, wb, wb + 16384u, warp << 4, (c & 1)*8, l, acc);
        if (c & 1) {
            int cc = c >> 1;
#pragma unroll
            for (int t = 0; t < 8; ++t) {
                int n0 = (cc << 6) + (t << 3) + (q << 1);
#pragma unroll
                for (int e = 0; e < 4; ++e) {
                    int n = n0 + (e & 1);
                    float h = fmaxf(acc[t][e] + sBr1[n], 0.f);
                    float* o = (e < 2) ? outA : outB;
                    const float* w = sWr2 + n*10;
#pragma unroll
                    for (int t5 = 0; t5 < 10; ++t5) o[t5] = fmaf(h, w[t5], o[t5]);
                }
            }
        }
        __syncthreads();
        if (c + 2 < 8) {
            uint32_t db = sb + ROF_W0 + (uint32_t)(c & 1)*32768u;
            const char* src = wsrc + (size_t)(c + 2)*32768;
#pragma unroll
            for (int t = 0; t < 8; ++t)
                cp16(db + (uint32_t)(tid + t*256)*16u, src + (size_t)(tid + t*256)*16);
            CP_COMMIT();
        }
    }

#pragma unroll
    for (int t5 = 0; t5 < 10; ++t5) {
        outA[t5] += __shfl_xor_sync(~0u, outA[t5], 1);
        outA[t5] += __shfl_xor_sync(~0u, outA[t5], 2);
        outB[t5] += __shfl_xor_sync(~0u, outB[t5], 1);
        outB[t5] += __shfl_xor_sync(~0u, outB[t5], 2);
    }
    if (q == 0) {
#pragma unroll
        for (int h2 = 0; h2 < 2; ++h2) {
            int r = h2 ? rB : rA;
            float* o = h2 ? outB : outA;
            int p = p0 + r;
            if (p < PP) {
                int iu = g_iu[p], ju = g_ju[p];
                if (ju < vn) {
                    int idx = iu*vn - iu*(iu+1)/2 + (ju - iu - 1);
#pragma unroll
                    for (int t5 = 0; t5 < 10; ++t5)
                        out[(((size_t)b*5 + (t5 >> 1))*PP + idx)*2 + (t5 & 1)] = o[t5] + br2[t5];
                }
            }
        }
    }
}

// ===================== host orchestration =====================================
extern "C" void kernel_launch(void* const* d_in, const int* in_sizes, int n_in,
                              void* d_out, int out_size) {
    const int*   edge_ids      = (const int*)  d_in[0];
    const float* node_features = (const float*)d_in[1];
    const int*   ev            = (const int*)  d_in[3];
    const float* emb           = (const float*)d_in[4];
    const float* Wl_e = (const float*)d_in[5];
    const float* Wl_w = (const float*)d_in[6];
    const float* Wl_v = (const float*)d_in[7];
    const float* bl1  = (const float*)d_in[8];
    const float* wl2  = (const float*)d_in[9];
    const float* bl2  = (const float*)d_in[10];
    const float* Wm_w = (const float*)d_in[11];
    const float* Wm_v = (const float*)d_in[12];
    const float* Wm_e = (const float*)d_in[13];
    const float* bm   = (const float*)d_in[14];
    const float* Wu_e = (const float*)d_in[15];
    const float* Wu_m = (const float*)d_in[16];
    const float* bu   = (const float*)d_in[17];
    const float* W_ih = (const float*)d_in[18];
    const float* W_hh = (const float*)d_in[19];
    const float* b_ih = (const float*)d_in[20];
    const float* b_hh = (const float*)d_in[21];
    const float* Wr1  = (const float*)d_in[22];
    const float* br1  = (const float*)d_in[23];
    const float* Wr2  = (const float*)d_in[24];
    const float* br2  = (const float*)d_in[25];

    cudaFuncSetAttribute(k_edge_mma,    cudaFuncAttributeMaxDynamicSharedMemorySize, EDGE_SMEM);
    cudaFuncSetAttribute(k_readout_mma, cudaFuncAttributeMaxDynamicSharedMemorySize, RO_SMEM);

    // launches: prep_w(0), prep_wr(1), hp(2), edge(3) — ncu captures index 3
    k_prep_w<<<256, 256>>>(Wl_e, Wm_e, Wu_e, Wu_m);
    k_prep_wr<<<256, 256>>>(Wr1);
    k_hp<<<dim3(128, 4), 256>>>(node_features, Wl_w, Wl_v, Wm_w, Wm_v, bl1, bm, 1);

    for (int r = 0; r < RNDS; ++r) {
        if (r > 0)
            k_hp<<<dim3(128, 4), 256>>>(node_features, Wl_w, Wl_v, Wm_w, Wm_v, bl1, bm, 0);
        k_edge_mma<<<BB*NN*2, 256, EDGE_SMEM>>>(wl2, bl2, bu, ev, edge_ids, emb, r == 0);
        k_reduce_ms<<<(BB*NN*CD/4 + 255)/256, 256>>>(ev);
        k_gig<<<dim3(128, 3, 2), 256>>>(W_ih, W_hh, b_ih, b_hh);
        k_gru<<<(BB*NN*CD + 255)/256, 256>>>(ev);
    }

    cudaMemsetAsync(d_out, 0, (size_t)out_size * sizeof(float));
    k_readout_mma<<<dim3(64, BB), 256, RO_SMEM>>>(br1, Wr2, br2, ev, (float*)d_out);
}

// round 15
// speedup vs baseline: 6.6870x; 1.0248x over previous
#include <cuda_runtime.h>
#include <cuda_bf16.h>
#include <cuda_fp16.h>
#include <math.h>
#include <stdint.h>

#define BB 32
#define NN 128
#define CD 128
#define PP 8128
#define RNDS 3

// ===================== low-level helpers (base ISA only) ======================
__device__ __forceinline__ uint32_t smem_u32(const void* p) {
    uint32_t a;
    asm("{ .reg .u64 t; cvta.to.shared.u64 t, %1; cvt.u32.u64 %0, t; }" : "=r"(a) : "l"(p));
    return a;
}
__device__ __forceinline__ void ldsm4(uint32_t r[4], uint32_t addr) {
    asm volatile("ldmatrix.sync.aligned.m8n8.x4.shared.b16 {%0,%1,%2,%3}, [%4];"
        : "=r"(r[0]), "=r"(r[1]), "=r"(r[2]), "=r"(r[3]) : "r"(addr));
}
__device__ __forceinline__ void mma_bf16(float c[4], const uint32_t a[4],
                                         uint32_t b0, uint32_t b1) {
    asm volatile("mma.sync.aligned.m16n8k16.row.col.f32.bf16.bf16.f32 "
        "{%0,%1,%2,%3}, {%4,%5,%6,%7}, {%8,%9}, {%0,%1,%2,%3};"
        : "+f"(c[0]), "+f"(c[1]), "+f"(c[2]), "+f"(c[3])
        : "r"(a[0]), "r"(a[1]), "r"(a[2]), "r"(a[3]), "r"(b0), "r"(b1));
}
__device__ __forceinline__ void cp16(uint32_t dst, const void* src) {
    asm volatile("cp.async.cg.shared.global [%0], [%1], 16;" :: "r"(dst), "l"(src));
}
#define CP_COMMIT() asm volatile("cp.async.commit_group;" ::: "memory")
#define CP_WAIT1()  asm volatile("cp.async.wait_group 1;" ::: "memory")
#define CP_WAIT0()  asm volatile("cp.async.wait_group 0;" ::: "memory")

__device__ __forceinline__ void split_pair(float x, float y, uint32_t& hi, uint32_t& lo) {
    __nv_bfloat16 hx = __float2bfloat16(x), hy = __float2bfloat16(y);
    float rx = x - __bfloat162float(hx), ry = y - __bfloat162float(hy);
    __nv_bfloat16 lx = __float2bfloat16(rx), ly = __float2bfloat16(ry);
    hi = (uint32_t)*(uint16_t*)&hx | ((uint32_t)*(uint16_t*)&hy << 16);
    lo = (uint32_t)*(uint16_t*)&lx | ((uint32_t)*(uint16_t*)&ly << 16);
}
template<int SH>
__device__ __host__ __forceinline__ uint32_t swz(int r, int k) {
    return ((uint32_t)r << SH) + ((uint32_t)(((k >> 3) ^ (r & 7))) << 4) + ((uint32_t)(k & 7) << 1);
}

// ---- GEMM: warp = M16 x N64 (NTP=4), 3-pass split, ILP-reordered ----
template<int SHA, int SHB, int NKS, int NTP>
__device__ __forceinline__ void gemm_split2(uint32_t sb, uint32_t offA, uint32_t offAlo,
                                            uint32_t bHi, uint32_t bLo,
                                            int mbase, int ks0, int lane, float acc[][4]) {
    int arow = mbase + (lane & 7) + (((lane >> 3) & 1) << 3);
    uint32_t aBase   = sb + offA + ((uint32_t)arow << SHA);
    uint32_t aBaseLo = sb + offAlo + ((uint32_t)arow << SHA);
    int a7 = arow & 7, agrp = (lane >> 4) & 1;
    int brow0 = (lane & 7) + ((lane >> 4) << 3);
    int b7 = lane & 7, bkb = (lane >> 3) & 1;
#pragma unroll
    for (int ks = 0; ks < NKS; ++ks) {
        uint32_t ak = (uint32_t)(((((ks0 + ks) << 1) | agrp) ^ a7) << 4);
        uint32_t Ah[4], Al[4];
        ldsm4(Ah, aBase + ak);
        ldsm4(Al, aBaseLo + ak);
        uint32_t bk = (uint32_t)((((ks << 1) | bkb) ^ b7) << 4);
#pragma unroll
        for (int tp = 0; tp < NTP; ++tp) {
            uint32_t brow = (uint32_t)(brow0 + (tp << 4)) << SHB;
            uint32_t Bh[4], Bl[4];
            ldsm4(Bh, bHi + brow + bk);
            ldsm4(Bl, bLo + brow + bk);
            mma_bf16(acc[2*tp],     Ah, Bh[0], Bh[1]);
            mma_bf16(acc[2*tp + 1], Ah, Bh[2], Bh[3]);
            mma_bf16(acc[2*tp],     Al, Bh[0], Bh[1]);
            mma_bf16(acc[2*tp + 1], Al, Bh[2], Bh[3]);
            mma_bf16(acc[2*tp],     Ah, Bl[0], Bl[1]);
            mma_bf16(acc[2*tp + 1], Ah, Bl[2], Bl[3]);
        }
    }
}

// ---- edge GEMM: warp = M32 x N32 (2 row-tiles, NTP=2), 3-pass split ----
template<int SHA, int SHB, int NKS>
__device__ __forceinline__ void gemm_split22(uint32_t sb, uint32_t offA, uint32_t offAlo,
                                             uint32_t bHi, uint32_t bLo,
                                             int rbase, int ncol0, int ks0, int lane,
                                             float acc[][4]) {
    int arow = rbase + (lane & 7) + (((lane >> 3) & 1) << 3);
    uint32_t a0h = sb + offA   + ((uint32_t)arow << SHA);
    uint32_t a0l = sb + offAlo + ((uint32_t)arow << SHA);
    uint32_t a1h = a0h + (16u << SHA);
    uint32_t a1l = a0l + (16u << SHA);
    int a7 = lane & 7, agrp = (lane >> 4) & 1;
    int brow0 = (lane & 7) + ((lane >> 4) << 3) + ncol0;
    int b7 = lane & 7, bkb = (lane >> 3) & 1;
#pragma unroll
    for (int ks = 0; ks < NKS; ++ks) {
        uint32_t ak = (uint32_t)(((((ks0 + ks) << 1) | agrp) ^ a7) << 4);
        uint32_t A0h[4], A0l[4], A1h[4], A1l[4];
        ldsm4(A0h, a0h + ak); ldsm4(A0l, a0l + ak);
        ldsm4(A1h, a1h + ak); ldsm4(A1l, a1l + ak);
        uint32_t bk = (uint32_t)((((ks << 1) | bkb) ^ b7) << 4);
#pragma unroll
        for (int tp = 0; tp < 2; ++tp) {
            uint32_t brow = (uint32_t)(brow0 + (tp << 4)) << SHB;
            uint32_t Bh[4], Bl[4];
            ldsm4(Bh, bHi + brow + bk);
            ldsm4(Bl, bLo + brow + bk);
            mma_bf16(acc[tp*2],       A0h, Bh[0], Bh[1]);
            mma_bf16(acc[tp*2 + 1],   A0h, Bh[2], Bh[3]);
            mma_bf16(acc[4+tp*2],     A1h, Bh[0], Bh[1]);
            mma_bf16(acc[4+tp*2 + 1], A1h, Bh[2], Bh[3]);
            mma_bf16(acc[tp*2],       A0l, Bh[0], Bh[1]);
            mma_bf16(acc[tp*2 + 1],   A0l, Bh[2], Bh[3]);
            mma_bf16(acc[4+tp*2],     A1l, Bh[0], Bh[1]);
            mma_bf16(acc[4+tp*2 + 1], A1l, Bh[2], Bh[3]);
            mma_bf16(acc[tp*2],       A0h, Bl[0], Bl[1]);
            mma_bf16(acc[tp*2 + 1],   A0h, Bl[2], Bl[3]);
            mma_bf16(acc[4+tp*2],     A1h, Bl[0], Bl[1]);
            mma_bf16(acc[4+tp*2 + 1], A1h, Bl[2], Bl[3]);
        }
    }
}

// ===================== persistent device scratch ==============================
__device__ unsigned short g_ebf[(size_t)BB*NN*32768];
__device__ uint32_t g_mbuf[(size_t)BB*NN*NN*CD/2];
__device__ float g_h   [BB*NN*CD];
__device__ float g_hp  [BB*NN*512];
__device__ float g_ms  [BB*NN*CD];
__device__ float g_gi  [BB*NN*384];
__device__ float g_gh  [BB*NN*384];
__device__ int   g_iu  [PP];
__device__ int   g_ju  [PP];
__device__ unsigned short g_wt [4*32768];   // edge weights
__device__ unsigned short g_wr [4*32768];   // Wr1 chunks
__device__ unsigned short g_whp[4*32768];   // Wl_w,Wl_v,Wm_w,Wm_v: 2 N64-chunks each
__device__ unsigned short g_wgi[2*98304];   // W_ih, W_hh: 6 N64-chunks (32KB each) per matrix

// ===================== prep kernels ===========================================
__global__ void k_prep_w(const float* __restrict__ Wl_e, const float* __restrict__ Wm_e,
                         const float* __restrict__ Wu_e, const float* __restrict__ Wu_m,
                         const float* __restrict__ Wl_w, const float* __restrict__ Wl_v,
                         const float* __restrict__ Wm_w, const float* __restrict__ Wm_v,
                         const float* __restrict__ W_ih, const float* __restrict__ W_hh) {
    int idx = blockIdx.x * blockDim.x + threadIdx.x;
    if (idx < 65536) {
        int m = idx >> 14, r = idx & 16383, n = r >> 7, k = r & 127;
        const float* W = (m == 0) ? Wl_e : (m == 1) ? Wm_e : (m == 2) ? Wu_e : Wu_m;
        float v = W[k*128 + n];
        __nv_bfloat16 hi = __float2bfloat16(v);
        __nv_bfloat16 lo = __float2bfloat16(v - __bfloat162float(hi));
        uint32_t o = (uint32_t)m*65536u + (uint32_t)(k >> 6)*32768u + swz<7>(n, k & 63);
        *(__nv_bfloat16*)((char*)g_wt + o) = hi;
        *(__nv_bfloat16*)((char*)g_wt + o + 16384) = lo;
    } else if (idx < 131072) {
        int r = idx - 65536;
        int m = r >> 14, e = r & 16383, n = e >> 7, k = e & 127;
        const float* W = (m == 0) ? Wl_w : (m == 1) ? Wl_v : (m == 2) ? Wm_w : Wm_v;
        float v = W[k*128 + n];
        __nv_bfloat16 hi = __float2bfloat16(v);
        __nv_bfloat16 lo = __float2bfloat16(v - __bfloat162float(hi));
        uint32_t o = (uint32_t)((m << 1) | (n >> 6))*32768u + swz<8>(n & 63, k);
        *(__nv_bfloat16*)((char*)g_whp + o) = hi;
        *(__nv_bfloat16*)((char*)g_whp + o + 16384) = lo;
    } else if (idx < 229376) {
        int r = idx - 131072;
        int m = r / 49152, e = r % 49152, n = e >> 7, k = e & 127;   // n < 384
        const float* W = m ? W_hh : W_ih;
        float v = W[k*384 + n];
        __nv_bfloat16 hi = __float2bfloat16(v);
        __nv_bfloat16 lo = __float2bfloat16(v - __bfloat162float(hi));
        // per matrix: 6 chunks x 32768 B = 196608 B
        uint32_t o = (uint32_t)m*196608u + (uint32_t)(n >> 6)*32768u + swz<8>(n & 63, k);
        *(__nv_bfloat16*)((char*)g_wgi + o) = hi;
        *(__nv_bfloat16*)((char*)g_wgi + o + 16384) = lo;
    }
}

__global__ void k_prep_wr(const float* __restrict__ Wr1) {
    int idx = blockIdx.x * blockDim.x + threadIdx.x;
    if (idx < NN*NN) {
        int i = idx / NN, j = idx % NN;
        if (j > i) {
            int p = i*(NN-1) - i*(i-1)/2 + (j - i - 1);
            g_iu[p] = i; g_ju[p] = j;
        }
    }
    if (idx >= 65536) return;
    int n = idx >> 8, k = idx & 255;
    float v = Wr1[k*256 + n];
    __nv_bfloat16 hi = __float2bfloat16(v);
    __nv_bfloat16 lo = __float2bfloat16(v - __bfloat162float(hi));
    uint32_t o = (uint32_t)(n >> 6)*65536u + (uint32_t)(k >> 7)*32768u + swz<8>(n & 63, k & 127);
    *(__nv_bfloat16*)((char*)g_wr + o) = hi;
    *(__nv_bfloat16*)((char*)g_wr + o + 16384) = lo;
}

// ===================== HMMA node GEMMs ========================================
// smem: [Ahi 32K][Alo 32K][Wbuf0 32K][Wbuf1 32K] = 128KB; CTA tile M128 x N64/chunk
#define RG_AHI 0u
#define RG_ALO 32768u
#define RG_W0  65536u
#define RG_W1  98304u
#define RG_SMEM 131072

// hp: g_hp[row][512] = h @ [Wl_w|Wl_v|Wm_w|Wm_v] (+bl1/bm); 8 chunks
__global__ __launch_bounds__(256, 1)
void k_rgemm_hp(const float* __restrict__ nf, const float* __restrict__ bl1,
                const float* __restrict__ bm, int first) {
    extern __shared__ char smem[];
    uint32_t sb = smem_u32(smem);
    int tid = threadIdx.x, warp = tid >> 5, l = tid & 31, q = l & 3;
    int row0 = blockIdx.x * 128;
    const float* A = first ? nf : g_h;
    const char* wsrc = (const char*)g_whp;

#pragma unroll
    for (int t = 0; t < 8; ++t)
        cp16(sb + RG_W0 + (uint32_t)(tid + t*256)*16u, wsrc + (size_t)(tid + t*256)*16);
    CP_COMMIT();
#pragma unroll
    for (int t = 0; t < 8; ++t)
        cp16(sb + RG_W1 + (uint32_t)(tid + t*256)*16u, wsrc + 32768 + (size_t)(tid + t*256)*16);
    CP_COMMIT();

    for (int t = tid; t < 4096; t += 256) {          // 128 rows x 32 float4
        float4 v = ((const float4*)(A + (size_t)row0*128))[t];
        if (first) ((float4*)(g_h + (size_t)row0*128))[t] = v;
        int r = t >> 5, k0 = (t & 31) << 2;
        uint32_t h01, l01, h23, l23;
        split_pair(v.x, v.y, h01, l01);
        split_pair(v.z, v.w, h23, l23);
        uint32_t o = swz<8>(r, k0);
        *(uint2*)(smem + RG_AHI + o) = make_uint2(h01, h23);
        *(uint2*)(smem + RG_ALO + o) = make_uint2(l01, l23);
    }

    int rA = row0 + (warp << 4) + (l >> 2), rB = rA + 8;
    float acc[8][4];
#pragma unroll
    for (int c = 0; c < 8; ++c) {
        if (c == 7) { CP_WAIT0(); } else { CP_WAIT1(); }
        __syncthreads();
#pragma unroll
        for (int t = 0; t < 8; ++t)
#pragma unroll
            for (int e = 0; e < 4; ++e) acc[t][e] = 0.f;
        uint32_t wb = sb + RG_W0 + (uint32_t)(c & 1)*32768u;
        gemm_split2<8,8,8,4>(sb, RG_AHI, RG_ALO, wb, wb + 16384u, warp << 4, 0, l, acc);
        __syncthreads();
        if (c + 2 < 8) {
            uint32_t db = sb + RG_W0 + (uint32_t)(c & 1)*32768u;
            const char* src = wsrc + (size_t)(c + 2)*32768;
#pragma unroll
            for (int t = 0; t < 8; ++t)
                cp16(db + (uint32_t)(tid + t*256)*16u, src + (size_t)(tid + t*256)*16);
            CP_COMMIT();
        }
        int m = c >> 1;
        const float* bias = (m == 0) ? bl1 : (m == 2) ? bm : nullptr;
        int cIn = (c & 1) * 64;
        int cOut = (m << 7) + cIn;
#pragma unroll
        for (int t = 0; t < 8; ++t) {
            int col = (t << 3) + (q << 1);
            float bx = 0.f, by = 0.f;
            if (bias) { bx = bias[cIn + col]; by = bias[cIn + col + 1]; }
            *(float2*)&g_hp[(size_t)rA*512 + cOut + col] = make_float2(acc[t][0] + bx, acc[t][1] + by);
            *(float2*)&g_hp[(size_t)rB*512 + cOut + col] = make_float2(acc[t][2] + bx, acc[t][3] + by);
        }
    }
}

// gig: z=0: g_gi = ms @ W_ih + bih; z=1: g_gh = h @ W_hh + bhh; 6 chunks
__global__ __launch_bounds__(256, 1)
void k_rgemm_gig(const float* __restrict__ bih, const float* __restrict__ bhh) {
    extern __shared__ char smem[];
    uint32_t sb = smem_u32(smem);
    int tid = threadIdx.x, warp = tid >> 5, l = tid & 31, q = l & 3;
    int row0 = blockIdx.x * 128;
    int z = blockIdx.y;
    const float* A = z ? g_h : g_ms;
    const float* bias = z ? bhh : bih;
    float* C = z ? g_gh : g_gi;
    const char* wsrc = (const char*)g_wgi + (size_t)z*196608;

#pragma unroll
    for (int t = 0; t < 8; ++t)
        cp16(sb + RG_W0 + (uint32_t)(tid + t*256)*16u, wsrc + (size_t)(tid + t*256)*16);
    CP_COMMIT();
#pragma unroll
    for (int t = 0; t < 8; ++t)
        cp16(sb + RG_W1 + (uint32_t)(tid + t*256)*16u, wsrc + 32768 + (size_t)(tid + t*256)*16);
    CP_COMMIT();

    for (int t = tid; t < 4096; t += 256) {
        float4 v = ((const float4*)(A + (size_t)row0*128))[t];
        int r = t >> 5, k0 = (t & 31) << 2;
        uint32_t h01, l01, h23, l23;
        split_pair(v.x, v.y, h01, l01);
        split_pair(v.z, v.w, h23, l23);
        uint32_t o = swz<8>(r, k0);
        *(uint2*)(smem + RG_AHI + o) = make_uint2(h01, h23);
        *(uint2*)(smem + RG_ALO + o) = make_uint2(l01, l23);
    }

    int rA = row0 + (warp << 4) + (l >> 2), rB = rA + 8;
    float acc[8][4];
#pragma unroll
    for (int c = 0; c < 6; ++c) {
        if (c == 5) { CP_WAIT0(); } else { CP_WAIT1(); }
        __syncthreads();
#pragma unroll
        for (int t = 0; t < 8; ++t)
#pragma unroll
            for (int e = 0; e < 4; ++e) acc[t][e] = 0.f;
        uint32_t wb = sb + RG_W0 + (uint32_t)(c & 1)*32768u;
        gemm_split2<8,8,8,4>(sb, RG_AHI, RG_ALO, wb, wb + 16384u, warp << 4, 0, l, acc);
        __syncthreads();
        if (c + 2 < 6) {
            uint32_t db = sb + RG_W0 + (uint32_t)(c & 1)*32768u;
            const char* src = wsrc + (size_t)(c + 2)*32768;
#pragma unroll
            for (int t = 0; t < 8; ++t)
                cp16(db + (uint32_t)(tid + t*256)*16u, src + (size_t)(tid + t*256)*16);
            CP_COMMIT();
        }
        int cOut = c * 64;
#pragma unroll
        for (int t = 0; t < 8; ++t) {
            int col = (t << 3) + (q << 1);
            float bx = bias[cOut + col], by = bias[cOut + col + 1];
            *(float2*)&C[(size_t)rA*384 + cOut + col] = make_float2(acc[t][0] + bx, acc[t][1] + by);
            *(float2*)&C[(size_t)rB*384 + cOut + col] = make_float2(acc[t][2] + bx, acc[t][3] + by);
        }
    }
}

// ===================== fused edge kernel: 256 thr, M32xN32 warps ==============
#define EHI 0u
#define ELO 16384u
#define EW0 32768u
#define EW1 65536u
#define ESCR 98304u
#define EDGE_SMEM 99328

__global__ __launch_bounds__(256, 2)
void k_edge_mma(const float* __restrict__ wl2, const float* __restrict__ bl2,
                const float* __restrict__ bu,  const int* __restrict__ ev,
                const int* __restrict__ eids,  const float* __restrict__ emb, int first) {
    extern __shared__ char smem[];
    uint32_t sb = smem_u32(smem);
    int tid = threadIdx.x, warp = tid >> 5, l = tid & 31, q = l & 3;
    int cta = blockIdx.x;
    int bi = cta >> 1, jh = cta & 1;
    int b = bi >> 7, i = bi & 127;
    int vn = ev[b];
    bool pmi = (i < vn);
    bool ctaValid = pmi && (jh*64 < vn);
    const char* wsrc = (const char*)g_wt;
    char* eb = (char*)g_ebf + (size_t)bi*65536;

    if (!ctaValid) {
        if (first) {
            for (int t = tid; t < 2048; t += 256) {
                int lr = t >> 5, c4 = t & 31;
                int gj = jh*64 + lr;
                int id = eids[((size_t)bi << 7) + gj];
                float4 v = ((const float4*)emb)[id*32 + c4];
                uint32_t h01, l01, h23, l23;
                split_pair(v.x, v.y, h01, l01);
                split_pair(v.z, v.w, h23, l23);
                uint32_t go = swz<8>(gj, c4 << 2);
                *(uint2*)(eb + go)          = make_uint2(h01, h23);
                *(uint2*)(eb + 32768u + go) = make_uint2(l01, l23);
            }
        }
        return;
    }

    const int mats[8] = {0, 0, 2, 2, 1, 1, 3, 3};   // G1,G1,G3,G3,G2,G2,G4,G4

    if (!first) {
#pragma unroll
        for (int t = 0; t < 4; ++t)
            cp16(sb + EHI + (uint32_t)(tid + t*256)*16u,
                 eb + (uint32_t)jh*16384u + (size_t)(tid + t*256)*16);
#pragma unroll
        for (int t = 0; t < 4; ++t)
            cp16(sb + ELO + (uint32_t)(tid + t*256)*16u,
                 eb + 32768u + (uint32_t)jh*16384u + (size_t)(tid + t*256)*16);
        CP_COMMIT();
    }
#pragma unroll
    for (int t = 0; t < 8; ++t)
        cp16(sb + EW0 + (uint32_t)(tid + t*256)*16u, wsrc + (size_t)(tid + t*256)*16);
    CP_COMMIT();
#pragma unroll
    for (int t = 0; t < 8; ++t)
        cp16(sb + EW1 + (uint32_t)(tid + t*256)*16u, wsrc + 32768 + (size_t)(tid + t*256)*16);
    CP_COMMIT();

    if (first) {
        int* sEid = (int*)(smem + ESCR);
        if (tid < 64) sEid[tid] = eids[((size_t)bi << 7) + jh*64 + tid];
        __syncthreads();
        for (int t = tid; t < 2048; t += 256) {
            int lr = t >> 5, c4 = t & 31;
            int id = sEid[lr];
            float4 v = ((const float4*)emb)[id*32 + c4];
            uint32_t h01, l01, h23, l23;
            split_pair(v.x, v.y, h01, l01);
            split_pair(v.z, v.w, h23, l23);
            uint32_t o = swz<8>(lr, c4 << 2);
            *(uint2*)(smem + EHI + o) = make_uint2(h01, h23);
            *(uint2*)(smem + ELO + o) = make_uint2(l01, l23);
            int gj = jh*64 + lr;
            if (gj >= vn) {
                uint32_t go = swz<8>(gj, c4 << 2);
                *(uint2*)(eb + go)          = make_uint2(h01, h23);
                *(uint2*)(eb + 32768u + go) = make_uint2(l01, l23);
            }
        }
    }

    int wg = warp >> 2, nq = warp & 3;
    int rbase = wg << 5, ncol0 = nq << 5;
    int r0 = l >> 2;
    int Ls[4] = { rbase + r0, rbase + r0 + 8, rbase + r0 + 16, rbase + r0 + 24 };
    bool vs[4];
#pragma unroll
    for (int k2 = 0; k2 < 4; ++k2) vs[k2] = (jh*64 + Ls[k2] < vn);
    const float* hpi = g_hp + (size_t)bi*512;
    float acc[8][4], accU[8][4];
    float sig[4];

#pragma unroll
    for (int c = 0; c < 8; ++c) {
        if (c == 7) { CP_WAIT0(); } else { CP_WAIT1(); }
        __syncthreads();
        if (c == 0 || c == 4) {
#pragma unroll
            for (int t = 0; t < 8; ++t)
#pragma unroll
                for (int e = 0; e < 4; ++e) acc[t][e] = 0.f;
        }
        if (c == 2) {
#pragma unroll
            for (int t = 0; t < 8; ++t)
#pragma unroll
                for (int e = 0; e < 4; ++e) accU[t][e] = 0.f;
        }
        uint32_t wb = sb + EW0 + (uint32_t)(c & 1)*32768u;
        float (*tg)[4] = (c == 2 || c == 3 || c >= 6) ? accU : acc;
        gemm_split22<8,7,4>(sb, EHI, ELO, wb, wb + 16384u, rbase, ncol0, (c & 1)*4, l, tg);
        __syncthreads();                       // buffer (c&1) free; E/M reads done
        if (c + 2 < 8) {                       // prefetch BEFORE epilogue (overlap)
            uint32_t db = sb + EW0 + (uint32_t)(c & 1)*32768u;
            const char* src = wsrc + (size_t)mats[c + 2]*65536 + (size_t)(c & 1)*32768;
#pragma unroll
            for (int t = 0; t < 8; ++t)
                cp16(db + (uint32_t)(tid + t*256)*16u, src + (size_t)(tid + t*256)*16);
            CP_COMMIT();
        }

        if (c == 1) {
            float par[4] = {0.f, 0.f, 0.f, 0.f};
#pragma unroll
            for (int rt = 0; rt < 2; ++rt) {
                const float* hvA = g_hp + ((size_t)(b*NN + jh*64 + Ls[rt*2]))*512 + 128;
                const float* hvB = g_hp + ((size_t)(b*NN + jh*64 + Ls[rt*2+1]))*512 + 128;
#pragma unroll
                for (int nt = 0; nt < 4; ++nt) {
                    int cc = ncol0 + (nt << 3) + (q << 1);
                    float2 hw = *(const float2*)(hpi + cc);
                    float2 w2 = *(const float2*)(wl2 + cc);
                    float2 vA = *(const float2*)(hvA + cc);
                    float2 vB = *(const float2*)(hvB + cc);
                    const float* a = acc[rt*4 + nt];
                    par[rt*2]   = fmaf(fmaxf(a[0] + hw.x + vA.x, 0.f), w2.x, par[rt*2]);
                    par[rt*2]   = fmaf(fmaxf(a[1] + hw.y + vA.y, 0.f), w2.y, par[rt*2]);
                    par[rt*2+1] = fmaf(fmaxf(a[2] + hw.x + vB.x, 0.f), w2.x, par[rt*2+1]);
                    par[rt*2+1] = fmaf(fmaxf(a[3] + hw.y + vB.y, 0.f), w2.y, par[rt*2+1]);
                }
            }
#pragma unroll
            for (int k2 = 0; k2 < 4; ++k2) {
                par[k2] += __shfl_xor_sync(~0u, par[k2], 1);
                par[k2] += __shfl_xor_sync(~0u, par[k2], 2);
            }
            float* sPart = (float*)(smem + ESCR);
            if (q == 0) {
#pragma unroll
                for (int k2 = 0; k2 < 4; ++k2) sPart[Ls[k2]*4 + nq] = par[k2];
            }
            __syncthreads();
            float bl2v = bl2[0];
#pragma unroll
            for (int k2 = 0; k2 < 4; ++k2) {
                const float* sp = (const float*)(smem + ESCR) + Ls[k2]*4;
                float adj = sp[0] + sp[1] + sp[2] + sp[3] + bl2v;
                sig[k2] = vs[k2] ? (1.f/(1.f + expf(-adj))) : 0.f;
            }
        }
        if (c == 5) {
            uint32_t* mbu = g_mbuf + (size_t)bi*NN*(CD/2);
#pragma unroll
            for (int rt = 0; rt < 2; ++rt) {
                int RA = Ls[rt*2], RB = Ls[rt*2+1];
                int gA = jh*64 + RA, gB = jh*64 + RB;
                const float* hvA = g_hp + ((size_t)(b*NN + gA))*512 + 384;
                const float* hvB = g_hp + ((size_t)(b*NN + gB))*512 + 384;
#pragma unroll
                for (int nt = 0; nt < 4; ++nt) {
                    int cc = ncol0 + (nt << 3) + (q << 1);
                    float2 hw = *(const float2*)(hpi + 256 + cc);
                    float2 vA = *(const float2*)(hvA + cc);
                    float2 vB = *(const float2*)(hvB + cc);
                    const float* a = acc[rt*4 + nt];
                    float mA0 = fmaxf(a[0] + hw.x + vA.x, 0.f) * sig[rt*2];
                    float mA1 = fmaxf(a[1] + hw.y + vA.y, 0.f) * sig[rt*2];
                    float mB0 = fmaxf(a[2] + hw.x + vB.x, 0.f) * sig[rt*2+1];
                    float mB1 = fmaxf(a[3] + hw.y + vB.y, 0.f) * sig[rt*2+1];
                    *(__half2*)&mbu[gA*(CD/2) + (cc >> 1)] = __floats2half2_rn(mA0, mA1);
                    *(__half2*)&mbu[gB*(CD/2) + (cc >> 1)] = __floats2half2_rn(mB0, mB1);
                    uint32_t hA, lA, hB, lB;
                    split_pair(mA0, mA1, hA, lA);
                    split_pair(mB0, mB1, hB, lB);
                    uint32_t oA = swz<8>(RA, cc), oB = swz<8>(RB, cc);
                    *(uint32_t*)(smem + EHI + oA) = hA;
                    *(uint32_t*)(smem + ELO + oA) = lA;
                    *(uint32_t*)(smem + EHI + oB) = hB;
                    *(uint32_t*)(smem + ELO + oB) = lB;
                }
            }
        }
    }

    // epi3: e_new = relu(accU + bu) where valid; invalid rows keep old state
#pragma unroll
    for (int rt = 0; rt < 2; ++rt) {
        int gA = jh*64 + Ls[rt*2], gB = jh*64 + Ls[rt*2+1];
#pragma unroll
        for (int nt = 0; nt < 4; ++nt) {
            int cc = ncol0 + (nt << 3) + (q << 1);
            float2 b2 = *(const float2*)(bu + cc);
            const float* a = accU[rt*4 + nt];
            if (vs[rt*2]) {
                uint32_t h, lo2;
                split_pair(fmaxf(a[0] + b2.x, 0.f), fmaxf(a[1] + b2.y, 0.f), h, lo2);
                uint32_t o = swz<8>(gA, cc);
                *(uint32_t*)(eb + o) = h;
                *(uint32_t*)(eb + 32768u + o) = lo2;
            }
            if (vs[rt*2+1]) {
                uint32_t h, lo2;
                split_pair(fmaxf(a[2] + b2.x, 0.f), fmaxf(a[3] + b2.y, 0.f), h, lo2);
                uint32_t o = swz<8>(gB, cc);
                *(uint32_t*)(eb + o) = h;
                *(uint32_t*)(eb + 32768u + o) = lo2;
            }
        }
    }
}

// ===================== ms reduce (packed fp16, i < vn) / GRU ==================
__global__ void k_reduce_ms(const int* __restrict__ ev) {
    int t = blockIdx.x * blockDim.x + threadIdx.x;
    if (t >= BB*NN*CD/4) return;
    int b   = t / (NN*CD/4);
    int jk4 = t % (NN*CD/4);
    int vn = ev[b];
    const uint2* base = (const uint2*)g_mbuf + (size_t)b*NN*(NN*CD/4) + jk4;
    float4 s = make_float4(0.f, 0.f, 0.f, 0.f);
    for (int i = 0; i < vn; ++i) {
        uint2 u = base[(size_t)i*(NN*CD/4)];
        float2 p0 = __half22float2(*(__half2*)&u.x);
        float2 p1 = __half22float2(*(__half2*)&u.y);
        s.x += p0.x; s.y += p0.y; s.z += p1.x; s.w += p1.y;
    }
    ((float4*)g_ms)[t] = s;
}

__global__ void k_gru(const int* __restrict__ ev) {
    int t = blockIdx.x * blockDim.x + threadIdx.x;
    if (t >= BB*NN*CD) return;
    int row = t / CD, c = t % CD;
    int b = row / NN, n = row % NN;
    if (n >= ev[b]) return;
    const float* gi = g_gi + (size_t)row*384;
    const float* gh = g_gh + (size_t)row*384;
    float ir = gi[c], iz = gi[CD+c], in = gi[2*CD+c];
    float hr = gh[c], hz = gh[CD+c], hn = gh[2*CD+c];
    float r  = 1.f/(1.f + expf(-(ir+hr)));
    float z  = 1.f/(1.f + expf(-(iz+hz)));
    float nn = tanhf(in + r*hn);
    float hold = g_h[t];
    g_h[t] = (1.f - z)*nn + z*hold;
}

// ===================== readout (HMMA, validity-skipped blocks) ================
#define ROF_AHI 0u
#define ROF_ALO 65536u
#define ROF_W0  131072u
#define ROF_W1  163840u
#define RO_SMEM 196608

__global__ __launch_bounds__(256, 1)
void k_readout_mma(const float* __restrict__ br1, const float* __restrict__ Wr2g,
                   const float* __restrict__ br2, const int* __restrict__ ev,
                   float* __restrict__ out) {
    extern __shared__ char smem[];
    __shared__ float sWr2[2560];
    __shared__ float sBr1[256];
    uint32_t sb = smem_u32(smem);
    int tid = threadIdx.x, warp = tid >> 5, l = tid & 31, q = l & 3;
    int b = blockIdx.y, p0 = blockIdx.x * 128;
    int vn = ev[b];
    const char* wsrc = (const char*)g_wr;

    int myValid = 0;
    if (tid < 128) {
        int p = p0 + tid;
        if (p < PP && g_ju[p] < vn) myValid = 1;
    }
    if (!__syncthreads_or(myValid)) return;

#pragma unroll
    for (int t = 0; t < 8; ++t)
        cp16(sb + ROF_W0 + (uint32_t)(tid + t*256)*16u, wsrc + (size_t)(tid + t*256)*16);
    CP_COMMIT();
#pragma unroll
    for (int t = 0; t < 8; ++t)
        cp16(sb + ROF_W1 + (uint32_t)(tid + t*256)*16u, wsrc + 32768 + (size_t)(tid + t*256)*16);
    CP_COMMIT();

    for (int t = tid; t < 2560; t += 256) sWr2[t] = Wr2g[t];
    if (tid < 256) sBr1[tid] = br1[tid];

    for (int t = tid; t < 8192; t += 256) {
        int lp = t >> 6, c = (t & 63) << 2;
        int p = p0 + lp; if (p >= PP) p = PP - 1;
        int iu = g_iu[p], ju = g_ju[p];
        const char* base; uint32_t o;
        if (c < 128) {
            base = (const char*)g_ebf + (size_t)(b*NN + iu)*65536;
            o = swz<8>(ju, c);
        } else {
            base = (const char*)g_ebf + (size_t)(b*NN + ju)*65536;
            o = swz<8>(iu, c - 128);
        }
        uint2 hi = *(const uint2*)(base + o);
        uint2 lo = *(const uint2*)(base + 32768 + o);
        uint32_t off = swz<9>(lp, c);
        *(uint2*)(smem + ROF_AHI + off) = hi;
        *(uint2*)(smem + ROF_ALO + off) = lo;
    }

    int rA = (warp << 4) + (l >> 2), rB = rA + 8;
    float outA[10], outB[10];
#pragma unroll
    for (int t5 = 0; t5 < 10; ++t5) { outA[t5] = 0.f; outB[t5] = 0.f; }
    float acc[8][4];

#pragma unroll
    for (int c = 0; c < 8; ++c) {
        if (c == 7) { CP_WAIT0(); } else { CP_WAIT1(); }
        __syncthreads();
        if ((c & 1) == 0) {
#pragma unroll
            for (int t = 0; t < 8; ++t)
#pragma unroll
                for (int e = 0; e < 4; ++e) acc[t][e] = 0.f;
        }
        uint32_t wb = sb + ROF_W0 + (uint32_t)(c & 1)*32768u;
        gemm_split2<9,8,8,4>(sb, ROF_AHI, ROF_ALO, wb, wb + 16384u, warp << 4, (c & 1)*8, l, acc);
        if (c & 1) {
            int cc = c >> 1;
#pragma unroll
            for (int t = 0; t < 8; ++t) {
                int n0 = (cc << 6) + (t << 3) + (q << 1);
#pragma unroll
                for (int e = 0; e < 4; ++e) {
                    int n = n0 + (e & 1);
                    float h = fmaxf(acc[t][e] + sBr1[n], 0.f);
                    float* o = (e < 2) ? outA : outB;
                    const float* w = sWr2 + n*10;
#pragma unroll
                    for (int t5 = 0; t5 < 10; ++t5) o[t5] = fmaf(h, w[t5], o[t5]);
                }
            }
        }
        __syncthreads();
        if (c + 2 < 8) {
            uint32_t db = sb + ROF_W0 + (uint32_t)(c & 1)*32768u;
            const char* src = wsrc + (size_t)(c + 2)*32768;
#pragma unroll
            for (int t = 0; t < 8; ++t)
                cp16(db + (uint32_t)(tid + t*256)*16u, src + (size_t)(tid + t*256)*16);
            CP_COMMIT();
        }
    }

#pragma unroll
    for (int t5 = 0; t5 < 10; ++t5) {
        outA[t5] += __shfl_xor_sync(~0u, outA[t5], 1);
        outA[t5] += __shfl_xor_sync(~0u, outA[t5], 2);
        outB[t5] += __shfl_xor_sync(~0u, outB[t5], 1);
        outB[t5] += __shfl_xor_sync(~0u, outB[t5], 2);
    }
    if (q == 0) {
#pragma unroll
        for (int h2 = 0; h2 < 2; ++h2) {
            int r = h2 ? rB : rA;
            float* o = h2 ? outB : outA;
            int p = p0 + r;
            if (p < PP) {
                int iu = g_iu[p], ju = g_ju[p];
                if (ju < vn) {
                    int idx = iu*vn - iu*(iu+1)/2 + (ju - iu - 1);
#pragma unroll
                    for (int t5 = 0; t5 < 10; ++t5)
                        out[(((size_t)b*5 + (t5 >> 1))*PP + idx)*2 + (t5 & 1)] = o[t5] + br2[t5];
                }
            }
        }
    }
}

// ===================== host orchestration =====================================
extern "C" void kernel_launch(void* const* d_in, const int* in_sizes, int n_in,
                              void* d_out, int out_size) {
    const int*   edge_ids      = (const int*)  d_in[0];
    const float* node_features = (const float*)d_in[1];
    const int*   ev            = (const int*)  d_in[3];
    const float* emb           = (const float*)d_in[4];
    const float* Wl_e = (const float*)d_in[5];
    const float* Wl_w = (const float*)d_in[6];
    const float* Wl_v = (const float*)d_in[7];
    const float* bl1  = (const float*)d_in[8];
    const float* wl2  = (const float*)d_in[9];
    const float* bl2  = (const float*)d_in[10];
    const float* Wm_w = (const float*)d_in[11];
    const float* Wm_v = (const float*)d_in[12];
    const float* Wm_e = (const float*)d_in[13];
    const float* bm   = (const float*)d_in[14];
    const float* Wu_e = (const float*)d_in[15];
    const float* Wu_m = (const float*)d_in[16];
    const float* bu   = (const float*)d_in[17];
    const float* W_ih = (const float*)d_in[18];
    const float* W_hh = (const float*)d_in[19];
    const float* b_ih = (const float*)d_in[20];
    const float* b_hh = (const float*)d_in[21];
    const float* Wr1  = (const float*)d_in[22];
    const float* br1  = (const float*)d_in[23];
    const float* Wr2  = (const float*)d_in[24];
    const float* br2  = (const float*)d_in[25];

    cudaFuncSetAttribute(k_edge_mma,    cudaFuncAttributeMaxDynamicSharedMemorySize, EDGE_SMEM);
    cudaFuncSetAttribute(k_readout_mma, cudaFuncAttributeMaxDynamicSharedMemorySize, RO_SMEM);
    cudaFuncSetAttribute(k_rgemm_hp,    cudaFuncAttributeMaxDynamicSharedMemorySize, RG_SMEM);
    cudaFuncSetAttribute(k_rgemm_gig,   cudaFuncAttributeMaxDynamicSharedMemorySize, RG_SMEM);

    // launches: prep_w(0), prep_wr(1), hp(2), edge(3) — ncu captures index 3
    k_prep_w<<<896, 256>>>(Wl_e, Wm_e, Wu_e, Wu_m, Wl_w, Wl_v, Wm_w, Wm_v, W_ih, W_hh);
    k_prep_wr<<<256, 256>>>(Wr1);
    k_rgemm_hp<<<32, 256, RG_SMEM>>>(node_features, bl1, bm, 1);

    for (int r = 0; r < RNDS; ++r) {
        if (r > 0)
            k_rgemm_hp<<<32, 256, RG_SMEM>>>(node_features, bl1, bm, 0);
        k_edge_mma<<<BB*NN*2, 256, EDGE_SMEM>>>(wl2, bl2, bu, ev, edge_ids, emb, r == 0);
        k_reduce_ms<<<(BB*NN*CD/4 + 255)/256, 256>>>(ev);
        k_rgemm_gig<<<dim3(32, 2), 256, RG_SMEM>>>(b_ih, b_hh);
        k_gru<<<(BB*NN*CD + 255)/256, 256>>>(ev);
    }

    cudaMemsetAsync(d_out, 0, (size_t)out_size * sizeof(float));
    k_readout_mma<<<dim3(64, BB), 256, RO_SMEM>>>(br1, Wr2, br2, ev, (float*)d_out);
}

// round 16
// speedup vs baseline: 6.9797x; 1.0438x over previous
#include <cuda_runtime.h>
#include <cuda_bf16.h>
#include <cuda_fp16.h>
#include <math.h>
#include <stdint.h>

#define BB 32
#define NN 128
#define CD 128
#define PP 8128
#define RNDS 3

// ===================== low-level helpers (base ISA only) ======================
__device__ __forceinline__ uint32_t smem_u32(const void* p) {
    uint32_t a;
    asm("{ .reg .u64 t; cvta.to.shared.u64 t, %1; cvt.u32.u64 %0, t; }" : "=r"(a) : "l"(p));
    return a;
}
__device__ __forceinline__ void ldsm4(uint32_t r[4], uint32_t addr) {
    asm volatile("ldmatrix.sync.aligned.m8n8.x4.shared.b16 {%0,%1,%2,%3}, [%4];"
        : "=r"(r[0]), "=r"(r[1]), "=r"(r[2]), "=r"(r[3]) : "r"(addr));
}
__device__ __forceinline__ void mma_bf16(float c[4], const uint32_t a[4],
                                         uint32_t b0, uint32_t b1) {
    asm volatile("mma.sync.aligned.m16n8k16.row.col.f32.bf16.bf16.f32 "
        "{%0,%1,%2,%3}, {%4,%5,%6,%7}, {%8,%9}, {%0,%1,%2,%3};"
        : "+f"(c[0]), "+f"(c[1]), "+f"(c[2]), "+f"(c[3])
        : "r"(a[0]), "r"(a[1]), "r"(a[2]), "r"(a[3]), "r"(b0), "r"(b1));
}
__device__ __forceinline__ void cp16(uint32_t dst, const void* src) {
    asm volatile("cp.async.cg.shared.global [%0], [%1], 16;" :: "r"(dst), "l"(src));
}
#define CP_COMMIT() asm volatile("cp.async.commit_group;" ::: "memory")
#define CP_WAIT1()  asm volatile("cp.async.wait_group 1;" ::: "memory")
#define CP_WAIT0()  asm volatile("cp.async.wait_group 0;" ::: "memory")

__device__ __forceinline__ void split_pair(float x, float y, uint32_t& hi, uint32_t& lo) {
    __nv_bfloat16 hx = __float2bfloat16(x), hy = __float2bfloat16(y);
    float rx = x - __bfloat162float(hx), ry = y - __bfloat162float(hy);
    __nv_bfloat16 lx = __float2bfloat16(rx), ly = __float2bfloat16(ry);
    hi = (uint32_t)*(uint16_t*)&hx | ((uint32_t)*(uint16_t*)&hy << 16);
    lo = (uint32_t)*(uint16_t*)&lx | ((uint32_t)*(uint16_t*)&ly << 16);
}
template<int SH>
__device__ __host__ __forceinline__ uint32_t swz(int r, int k) {
    return ((uint32_t)r << SH) + ((uint32_t)(((k >> 3) ^ (r & 7))) << 4) + ((uint32_t)(k & 7) << 1);
}

// ---- GEMM: warp = M16 x N(8*NTP), 3-pass split, ILP-reordered ----
template<int SHA, int SHB, int NKS, int NTP>
__device__ __forceinline__ void gemm_split2(uint32_t sb, uint32_t offA, uint32_t offAlo,
                                            uint32_t bHi, uint32_t bLo,
                                            int mbase, int ks0, int lane, float acc[][4]) {
    int arow = mbase + (lane & 7) + (((lane >> 3) & 1) << 3);
    uint32_t aBase   = sb + offA + ((uint32_t)arow << SHA);
    uint32_t aBaseLo = sb + offAlo + ((uint32_t)arow << SHA);
    int a7 = arow & 7, agrp = (lane >> 4) & 1;
    int brow0 = (lane & 7) + ((lane >> 4) << 3);
    int b7 = lane & 7, bkb = (lane >> 3) & 1;
#pragma unroll
    for (int ks = 0; ks < NKS; ++ks) {
        uint32_t ak = (uint32_t)(((((ks0 + ks) << 1) | agrp) ^ a7) << 4);
        uint32_t Ah[4], Al[4];
        ldsm4(Ah, aBase + ak);
        ldsm4(Al, aBaseLo + ak);
        uint32_t bk = (uint32_t)((((ks << 1) | bkb) ^ b7) << 4);
#pragma unroll
        for (int tp = 0; tp < NTP; ++tp) {
            uint32_t brow = (uint32_t)(brow0 + (tp << 4)) << SHB;
            uint32_t Bh[4], Bl[4];
            ldsm4(Bh, bHi + brow + bk);
            ldsm4(Bl, bLo + brow + bk);
            mma_bf16(acc[2*tp],     Ah, Bh[0], Bh[1]);
            mma_bf16(acc[2*tp + 1], Ah, Bh[2], Bh[3]);
            mma_bf16(acc[2*tp],     Al, Bh[0], Bh[1]);
            mma_bf16(acc[2*tp + 1], Al, Bh[2], Bh[3]);
            mma_bf16(acc[2*tp],     Ah, Bl[0], Bl[1]);
            mma_bf16(acc[2*tp + 1], Ah, Bl[2], Bl[3]);
        }
    }
}

// ---- edge GEMM: warp = M32 x N32 (2 row-tiles, NTP=2), 3-pass split ----
template<int SHA, int SHB, int NKS>
__device__ __forceinline__ void gemm_split22(uint32_t sb, uint32_t offA, uint32_t offAlo,
                                             uint32_t bHi, uint32_t bLo,
                                             int rbase, int ncol0, int ks0, int lane,
                                             float acc[][4]) {
    int arow = rbase + (lane & 7) + (((lane >> 3) & 1) << 3);
    uint32_t a0h = sb + offA   + ((uint32_t)arow << SHA);
    uint32_t a0l = sb + offAlo + ((uint32_t)arow << SHA);
    uint32_t a1h = a0h + (16u << SHA);
    uint32_t a1l = a0l + (16u << SHA);
    int a7 = lane & 7, agrp = (lane >> 4) & 1;
    int brow0 = (lane & 7) + ((lane >> 4) << 3) + ncol0;
    int b7 = lane & 7, bkb = (lane >> 3) & 1;
#pragma unroll
    for (int ks = 0; ks < NKS; ++ks) {
        uint32_t ak = (uint32_t)(((((ks0 + ks) << 1) | agrp) ^ a7) << 4);
        uint32_t A0h[4], A0l[4], A1h[4], A1l[4];
        ldsm4(A0h, a0h + ak); ldsm4(A0l, a0l + ak);
        ldsm4(A1h, a1h + ak); ldsm4(A1l, a1l + ak);
        uint32_t bk = (uint32_t)((((ks << 1) | bkb) ^ b7) << 4);
#pragma unroll
        for (int tp = 0; tp < 2; ++tp) {
            uint32_t brow = (uint32_t)(brow0 + (tp << 4)) << SHB;
            uint32_t Bh[4], Bl[4];
            ldsm4(Bh, bHi + brow + bk);
            ldsm4(Bl, bLo + brow + bk);
            mma_bf16(acc[tp*2],       A0h, Bh[0], Bh[1]);
            mma_bf16(acc[tp*2 + 1],   A0h, Bh[2], Bh[3]);
            mma_bf16(acc[4+tp*2],     A1h, Bh[0], Bh[1]);
            mma_bf16(acc[4+tp*2 + 1], A1h, Bh[2], Bh[3]);
            mma_bf16(acc[tp*2],       A0l, Bh[0], Bh[1]);
            mma_bf16(acc[tp*2 + 1],   A0l, Bh[2], Bh[3]);
            mma_bf16(acc[4+tp*2],     A1l, Bh[0], Bh[1]);
            mma_bf16(acc[4+tp*2 + 1], A1l, Bh[2], Bh[3]);
            mma_bf16(acc[tp*2],       A0h, Bl[0], Bl[1]);
            mma_bf16(acc[tp*2 + 1],   A0h, Bl[2], Bl[3]);
            mma_bf16(acc[4+tp*2],     A1h, Bl[0], Bl[1]);
            mma_bf16(acc[4+tp*2 + 1], A1h, Bl[2], Bl[3]);
        }
    }
}

// ===================== persistent device scratch ==============================
__device__ unsigned short g_ebf[(size_t)BB*NN*32768];
__device__ uint32_t g_mbuf[(size_t)BB*NN*NN*CD/2];
__device__ float g_h   [BB*NN*CD];
__device__ float g_hp  [BB*NN*512];
__device__ float g_ms  [BB*NN*CD];
__device__ float g_gi  [BB*NN*384];
__device__ float g_gh  [BB*NN*384];
__device__ int   g_iu  [PP];
__device__ int   g_ju  [PP];
__device__ unsigned short g_wt [4*32768];
__device__ unsigned short g_wr [4*32768];
__device__ unsigned short g_whp[4*32768];
__device__ unsigned short g_wgi[2*98304];

// ===================== prep kernels ===========================================
__global__ void k_prep_w(const float* __restrict__ Wl_e, const float* __restrict__ Wm_e,
                         const float* __restrict__ Wu_e, const float* __restrict__ Wu_m,
                         const float* __restrict__ Wl_w, const float* __restrict__ Wl_v,
                         const float* __restrict__ Wm_w, const float* __restrict__ Wm_v,
                         const float* __restrict__ W_ih, const float* __restrict__ W_hh) {
    int idx = blockIdx.x * blockDim.x + threadIdx.x;
    if (idx < 65536) {
        int m = idx >> 14, r = idx & 16383, n = r >> 7, k = r & 127;
        const float* W = (m == 0) ? Wl_e : (m == 1) ? Wm_e : (m == 2) ? Wu_e : Wu_m;
        float v = W[k*128 + n];
        __nv_bfloat16 hi = __float2bfloat16(v);
        __nv_bfloat16 lo = __float2bfloat16(v - __bfloat162float(hi));
        uint32_t o = (uint32_t)m*65536u + (uint32_t)(k >> 6)*32768u + swz<7>(n, k & 63);
        *(__nv_bfloat16*)((char*)g_wt + o) = hi;
        *(__nv_bfloat16*)((char*)g_wt + o + 16384) = lo;
    } else if (idx < 131072) {
        int r = idx - 65536;
        int m = r >> 14, e = r & 16383, n = e >> 7, k = e & 127;
        const float* W = (m == 0) ? Wl_w : (m == 1) ? Wl_v : (m == 2) ? Wm_w : Wm_v;
        float v = W[k*128 + n];
        __nv_bfloat16 hi = __float2bfloat16(v);
        __nv_bfloat16 lo = __float2bfloat16(v - __bfloat162float(hi));
        uint32_t o = (uint32_t)((m << 1) | (n >> 6))*32768u + swz<8>(n & 63, k);
        *(__nv_bfloat16*)((char*)g_whp + o) = hi;
        *(__nv_bfloat16*)((char*)g_whp + o + 16384) = lo;
    } else if (idx < 229376) {
        int r = idx - 131072;
        int m = r / 49152, e = r % 49152, n = e >> 7, k = e & 127;
        const float* W = m ? W_hh : W_ih;
        float v = W[k*384 + n];
        __nv_bfloat16 hi = __float2bfloat16(v);
        __nv_bfloat16 lo = __float2bfloat16(v - __bfloat162float(hi));
        uint32_t o = (uint32_t)m*196608u + (uint32_t)(n >> 6)*32768u + swz<8>(n & 63, k);
        *(__nv_bfloat16*)((char*)g_wgi + o) = hi;
        *(__nv_bfloat16*)((char*)g_wgi + o + 16384) = lo;
    }
}

__global__ void k_prep_wr(const float* __restrict__ Wr1) {
    int idx = blockIdx.x * blockDim.x + threadIdx.x;
    if (idx < NN*NN) {
        int i = idx / NN, j = idx % NN;
        if (j > i) {
            int p = i*(NN-1) - i*(i-1)/2 + (j - i - 1);
            g_iu[p] = i; g_ju[p] = j;
        }
    }
    if (idx >= 65536) return;
    int n = idx >> 8, k = idx & 255;
    float v = Wr1[k*256 + n];
    __nv_bfloat16 hi = __float2bfloat16(v);
    __nv_bfloat16 lo = __float2bfloat16(v - __bfloat162float(hi));
    uint32_t o = (uint32_t)(n >> 6)*65536u + (uint32_t)(k >> 7)*32768u + swz<8>(n & 63, k & 127);
    *(__nv_bfloat16*)((char*)g_wr + o) = hi;
    *(__nv_bfloat16*)((char*)g_wr + o + 16384) = lo;
}

// ===================== HMMA node GEMMs (chunk-parallel, occ 2) ================
// smem: [Ahi 32K][Alo 32K][W 32K] = 96KB; CTA = (row-block 128, one N64 chunk)
#define H2_AHI 0u
#define H2_ALO 32768u
#define H2_W   65536u
#define H2_SMEM 98304

__global__ __launch_bounds__(256, 2)
void k_rgemm_hp(const float* __restrict__ nf, const float* __restrict__ bl1,
                const float* __restrict__ bm, int first) {
    extern __shared__ char smem[];
    uint32_t sb = smem_u32(smem);
    int tid = threadIdx.x, warp = tid >> 5, l = tid & 31, q = l & 3;
    int row0 = blockIdx.x * 128;
    int c = blockIdx.y;                     // chunk: m = c>>1, n-half = c&1
    const float* A = first ? nf : g_h;
    const char* wsrc = (const char*)g_whp + (size_t)c*32768;

#pragma unroll
    for (int t = 0; t < 8; ++t)
        cp16(sb + H2_W + (uint32_t)(tid + t*256)*16u, wsrc + (size_t)(tid + t*256)*16);
    CP_COMMIT();

    for (int t = tid; t < 4096; t += 256) {
        float4 v = ((const float4*)(A + (size_t)row0*128))[t];
        if (first && c == 0) ((float4*)(g_h + (size_t)row0*128))[t] = v;
        int r = t >> 5, k0 = (t & 31) << 2;
        uint32_t h01, l01, h23, l23;
        split_pair(v.x, v.y, h01, l01);
        split_pair(v.z, v.w, h23, l23);
        uint32_t o = swz<8>(r, k0);
        *(uint2*)(smem + H2_AHI + o) = make_uint2(h01, h23);
        *(uint2*)(smem + H2_ALO + o) = make_uint2(l01, l23);
    }
    CP_WAIT0();
    __syncthreads();

    int rA = row0 + (warp << 4) + (l >> 2), rB = rA + 8;
    float acc[8][4];
#pragma unroll
    for (int t = 0; t < 8; ++t)
#pragma unroll
        for (int e = 0; e < 4; ++e) acc[t][e] = 0.f;
    gemm_split2<8,8,8,4>(sb, H2_AHI, H2_ALO, sb + H2_W, sb + H2_W + 16384u, warp << 4, 0, l, acc);

    int m = c >> 1;
    const float* bias = (m == 0) ? bl1 : (m == 2) ? bm : nullptr;
    int cIn = (c & 1) * 64;
    int cOut = (m << 7) + cIn;
#pragma unroll
    for (int t = 0; t < 8; ++t) {
        int col = (t << 3) + (q << 1);
        float bx = 0.f, by = 0.f;
        if (bias) { bx = bias[cIn + col]; by = bias[cIn + col + 1]; }
        *(float2*)&g_hp[(size_t)rA*512 + cOut + col] = make_float2(acc[t][0] + bx, acc[t][1] + by);
        *(float2*)&g_hp[(size_t)rB*512 + cOut + col] = make_float2(acc[t][2] + bx, acc[t][3] + by);
    }
}

__global__ __launch_bounds__(256, 2)
void k_rgemm_gig(const float* __restrict__ bih, const float* __restrict__ bhh) {
    extern __shared__ char smem[];
    uint32_t sb = smem_u32(smem);
    int tid = threadIdx.x, warp = tid >> 5, l = tid & 31, q = l & 3;
    int row0 = blockIdx.x * 128;
    int c = blockIdx.y;                     // 0..5
    int z = blockIdx.z;
    const float* A = z ? g_h : g_ms;
    const float* bias = z ? bhh : bih;
    float* C = z ? g_gh : g_gi;
    const char* wsrc = (const char*)g_wgi + (size_t)z*196608 + (size_t)c*32768;

#pragma unroll
    for (int t = 0; t < 8; ++t)
        cp16(sb + H2_W + (uint32_t)(tid + t*256)*16u, wsrc + (size_t)(tid + t*256)*16);
    CP_COMMIT();

    for (int t = tid; t < 4096; t += 256) {
        float4 v = ((const float4*)(A + (size_t)row0*128))[t];
        int r = t >> 5, k0 = (t & 31) << 2;
        uint32_t h01, l01, h23, l23;
        split_pair(v.x, v.y, h01, l01);
        split_pair(v.z, v.w, h23, l23);
        uint32_t o = swz<8>(r, k0);
        *(uint2*)(smem + H2_AHI + o) = make_uint2(h01, h23);
        *(uint2*)(smem + H2_ALO + o) = make_uint2(l01, l23);
    }
    CP_WAIT0();
    __syncthreads();

    int rA = row0 + (warp << 4) + (l >> 2), rB = rA + 8;
    float acc[8][4];
#pragma unroll
    for (int t = 0; t < 8; ++t)
#pragma unroll
        for (int e = 0; e < 4; ++e) acc[t][e] = 0.f;
    gemm_split2<8,8,8,4>(sb, H2_AHI, H2_ALO, sb + H2_W, sb + H2_W + 16384u, warp << 4, 0, l, acc);

    int cOut = c * 64;
#pragma unroll
    for (int t = 0; t < 8; ++t) {
        int col = (t << 3) + (q << 1);
        float bx = bias[cOut + col], by = bias[cOut + col + 1];
        *(float2*)&C[(size_t)rA*384 + cOut + col] = make_float2(acc[t][0] + bx, acc[t][1] + by);
        *(float2*)&C[(size_t)rB*384 + cOut + col] = make_float2(acc[t][2] + bx, acc[t][3] + by);
    }
}

// ===================== fused edge kernel: 256 thr, M32xN32 warps ==============
#define EHI 0u
#define ELO 16384u
#define EW0 32768u
#define EW1 65536u
#define ESCR 98304u
#define EDGE_SMEM 99328

__global__ __launch_bounds__(256, 2)
void k_edge_mma(const float* __restrict__ wl2, const float* __restrict__ bl2,
                const float* __restrict__ bu,  const int* __restrict__ ev,
                const int* __restrict__ eids,  const float* __restrict__ emb, int first) {
    extern __shared__ char smem[];
    uint32_t sb = smem_u32(smem);
    int tid = threadIdx.x, warp = tid >> 5, l = tid & 31, q = l & 3;
    int cta = blockIdx.x;
    int bi = cta >> 1, jh = cta & 1;
    int b = bi >> 7, i = bi & 127;
    int vn = ev[b];
    bool pmi = (i < vn);
    bool ctaValid = pmi && (jh*64 < vn);
    const char* wsrc = (const char*)g_wt;
    char* eb = (char*)g_ebf + (size_t)bi*65536;

    if (!ctaValid) {
        if (first) {
            for (int t = tid; t < 2048; t += 256) {
                int lr = t >> 5, c4 = t & 31;
                int gj = jh*64 + lr;
                int id = eids[((size_t)bi << 7) + gj];
                float4 v = ((const float4*)emb)[id*32 + c4];
                uint32_t h01, l01, h23, l23;
                split_pair(v.x, v.y, h01, l01);
                split_pair(v.z, v.w, h23, l23);
                uint32_t go = swz<8>(gj, c4 << 2);
                *(uint2*)(eb + go)          = make_uint2(h01, h23);
                *(uint2*)(eb + 32768u + go) = make_uint2(l01, l23);
            }
        }
        return;
    }

    const int mats[8] = {0, 0, 2, 2, 1, 1, 3, 3};

    if (!first) {
#pragma unroll
        for (int t = 0; t < 4; ++t)
            cp16(sb + EHI + (uint32_t)(tid + t*256)*16u,
                 eb + (uint32_t)jh*16384u + (size_t)(tid + t*256)*16);
#pragma unroll
        for (int t = 0; t < 4; ++t)
            cp16(sb + ELO + (uint32_t)(tid + t*256)*16u,
                 eb + 32768u + (uint32_t)jh*16384u + (size_t)(tid + t*256)*16);
        CP_COMMIT();
    }
#pragma unroll
    for (int t = 0; t < 8; ++t)
        cp16(sb + EW0 + (uint32_t)(tid + t*256)*16u, wsrc + (size_t)(tid + t*256)*16);
    CP_COMMIT();
#pragma unroll
    for (int t = 0; t < 8; ++t)
        cp16(sb + EW1 + (uint32_t)(tid + t*256)*16u, wsrc + 32768 + (size_t)(tid + t*256)*16);
    CP_COMMIT();

    if (first) {
        int* sEid = (int*)(smem + ESCR);
        if (tid < 64) sEid[tid] = eids[((size_t)bi << 7) + jh*64 + tid];
        __syncthreads();
        for (int t = tid; t < 2048; t += 256) {
            int lr = t >> 5, c4 = t & 31;
            int id = sEid[lr];
            float4 v = ((const float4*)emb)[id*32 + c4];
            uint32_t h01, l01, h23, l23;
            split_pair(v.x, v.y, h01, l01);
            split_pair(v.z, v.w, h23, l23);
            uint32_t o = swz<8>(lr, c4 << 2);
            *(uint2*)(smem + EHI + o) = make_uint2(h01, h23);
            *(uint2*)(smem + ELO + o) = make_uint2(l01, l23);
            int gj = jh*64 + lr;
            if (gj >= vn) {
                uint32_t go = swz<8>(gj, c4 << 2);
                *(uint2*)(eb + go)          = make_uint2(h01, h23);
                *(uint2*)(eb + 32768u + go) = make_uint2(l01, l23);
            }
        }
    }

    int wg = warp >> 2, nq = warp & 3;
    int rbase = wg << 5, ncol0 = nq << 5;
    int r0 = l >> 2;
    int Ls[4] = { rbase + r0, rbase + r0 + 8, rbase + r0 + 16, rbase + r0 + 24 };
    bool vs[4];
#pragma unroll
    for (int k2 = 0; k2 < 4; ++k2) vs[k2] = (jh*64 + Ls[k2] < vn);
    const float* hpi = g_hp + (size_t)bi*512;
    float acc[8][4], accU[8][4];
    float sig[4];

#pragma unroll
    for (int c = 0; c < 8; ++c) {
        if (c == 7) { CP_WAIT0(); } else { CP_WAIT1(); }
        __syncthreads();
        if (c == 0 || c == 4) {
#pragma unroll
            for (int t = 0; t < 8; ++t)
#pragma unroll
                for (int e = 0; e < 4; ++e) acc[t][e] = 0.f;
        }
        if (c == 2) {
#pragma unroll
            for (int t = 0; t < 8; ++t)
#pragma unroll
                for (int e = 0; e < 4; ++e) accU[t][e] = 0.f;
        }
        uint32_t wb = sb + EW0 + (uint32_t)(c & 1)*32768u;
        float (*tg)[4] = (c == 2 || c == 3 || c >= 6) ? accU : acc;
        gemm_split22<8,7,4>(sb, EHI, ELO, wb, wb + 16384u, rbase, ncol0, (c & 1)*4, l, tg);
        __syncthreads();
        if (c + 2 < 8) {
            uint32_t db = sb + EW0 + (uint32_t)(c & 1)*32768u;
            const char* src = wsrc + (size_t)mats[c + 2]*65536 + (size_t)(c & 1)*32768;
#pragma unroll
            for (int t = 0; t < 8; ++t)
                cp16(db + (uint32_t)(tid + t*256)*16u, src + (size_t)(tid + t*256)*16);
            CP_COMMIT();
        }

        if (c == 1) {
            float par[4] = {0.f, 0.f, 0.f, 0.f};
#pragma unroll
            for (int rt = 0; rt < 2; ++rt) {
                const float* hvA = g_hp + ((size_t)(b*NN + jh*64 + Ls[rt*2]))*512 + 128;
                const float* hvB = g_hp + ((size_t)(b*NN + jh*64 + Ls[rt*2+1]))*512 + 128;
#pragma unroll
                for (int nt = 0; nt < 4; ++nt) {
                    int cc = ncol0 + (nt << 3) + (q << 1);
                    float2 hw = *(const float2*)(hpi + cc);
                    float2 w2 = *(const float2*)(wl2 + cc);
                    float2 vA = *(const float2*)(hvA + cc);
                    float2 vB = *(const float2*)(hvB + cc);
                    const float* a = acc[rt*4 + nt];
                    par[rt*2]   = fmaf(fmaxf(a[0] + hw.x + vA.x, 0.f), w2.x, par[rt*2]);
                    par[rt*2]   = fmaf(fmaxf(a[1] + hw.y + vA.y, 0.f), w2.y, par[rt*2]);
                    par[rt*2+1] = fmaf(fmaxf(a[2] + hw.x + vB.x, 0.f), w2.x, par[rt*2+1]);
                    par[rt*2+1] = fmaf(fmaxf(a[3] + hw.y + vB.y, 0.f), w2.y, par[rt*2+1]);
                }
            }
#pragma unroll
            for (int k2 = 0; k2 < 4; ++k2) {
                par[k2] += __shfl_xor_sync(~0u, par[k2], 1);
                par[k2] += __shfl_xor_sync(~0u, par[k2], 2);
            }
            float* sPart = (float*)(smem + ESCR);
            if (q == 0) {
#pragma unroll
                for (int k2 = 0; k2 < 4; ++k2) sPart[Ls[k2]*4 + nq] = par[k2];
            }
            __syncthreads();
            float bl2v = bl2[0];
#pragma unroll
            for (int k2 = 0; k2 < 4; ++k2) {
                const float* sp = (const float*)(smem + ESCR) + Ls[k2]*4;
                float adj = sp[0] + sp[1] + sp[2] + sp[3] + bl2v;
                sig[k2] = vs[k2] ? (1.f/(1.f + expf(-adj))) : 0.f;
            }
        }
        if (c == 5) {
            uint32_t* mbu = g_mbuf + (size_t)bi*NN*(CD/2);
#pragma unroll
            for (int rt = 0; rt < 2; ++rt) {
                int RA = Ls[rt*2], RB = Ls[rt*2+1];
                int gA = jh*64 + RA, gB = jh*64 + RB;
                const float* hvA = g_hp + ((size_t)(b*NN + gA))*512 + 384;
                const float* hvB = g_hp + ((size_t)(b*NN + gB))*512 + 384;
#pragma unroll
                for (int nt = 0; nt < 4; ++nt) {
                    int cc = ncol0 + (nt << 3) + (q << 1);
                    float2 hw = *(const float2*)(hpi + 256 + cc);
                    float2 vA = *(const float2*)(hvA + cc);
                    float2 vB = *(const float2*)(hvB + cc);
                    const float* a = acc[rt*4 + nt];
                    float mA0 = fmaxf(a[0] + hw.x + vA.x, 0.f) * sig[rt*2];
                    float mA1 = fmaxf(a[1] + hw.y + vA.y, 0.f) * sig[rt*2];
                    float mB0 = fmaxf(a[2] + hw.x + vB.x, 0.f) * sig[rt*2+1];
                    float mB1 = fmaxf(a[3] + hw.y + vB.y, 0.f) * sig[rt*2+1];
                    *(__half2*)&mbu[gA*(CD/2) + (cc >> 1)] = __floats2half2_rn(mA0, mA1);
                    *(__half2*)&mbu[gB*(CD/2) + (cc >> 1)] = __floats2half2_rn(mB0, mB1);
                    uint32_t hA, lA, hB, lB;
                    split_pair(mA0, mA1, hA, lA);
                    split_pair(mB0, mB1, hB, lB);
                    uint32_t oA = swz<8>(RA, cc), oB = swz<8>(RB, cc);
                    *(uint32_t*)(smem + EHI + oA) = hA;
                    *(uint32_t*)(smem + ELO + oA) = lA;
                    *(uint32_t*)(smem + EHI + oB) = hB;
                    *(uint32_t*)(smem + ELO + oB) = lB;
                }
            }
        }
    }

#pragma unroll
    for (int rt = 0; rt < 2; ++rt) {
        int gA = jh*64 + Ls[rt*2], gB = jh*64 + Ls[rt*2+1];
#pragma unroll
        for (int nt = 0; nt < 4; ++nt) {
            int cc = ncol0 + (nt << 3) + (q << 1);
            float2 b2 = *(const float2*)(bu + cc);
            const float* a = accU[rt*4 + nt];
            if (vs[rt*2]) {
                uint32_t h, lo2;
                split_pair(fmaxf(a[0] + b2.x, 0.f), fmaxf(a[1] + b2.y, 0.f), h, lo2);
                uint32_t o = swz<8>(gA, cc);
                *(uint32_t*)(eb + o) = h;
                *(uint32_t*)(eb + 32768u + o) = lo2;
            }
            if (vs[rt*2+1]) {
                uint32_t h, lo2;
                split_pair(fmaxf(a[2] + b2.x, 0.f), fmaxf(a[3] + b2.y, 0.f), h, lo2);
                uint32_t o = swz<8>(gB, cc);
                *(uint32_t*)(eb + o) = h;
                *(uint32_t*)(eb + 32768u + o) = lo2;
            }
        }
    }
}

// ===================== ms reduce (packed fp16, i < vn) / GRU ==================
__global__ void k_reduce_ms(const int* __restrict__ ev) {
    int t = blockIdx.x * blockDim.x + threadIdx.x;
    if (t >= BB*NN*CD/4) return;
    int b   = t / (NN*CD/4);
    int jk4 = t % (NN*CD/4);
    int vn = ev[b];
    const uint2* base = (const uint2*)g_mbuf + (size_t)b*NN*(NN*CD/4) + jk4;
    float4 s = make_float4(0.f, 0.f, 0.f, 0.f);
    for (int i = 0; i < vn; ++i) {
        uint2 u = base[(size_t)i*(NN*CD/4)];
        float2 p0 = __half22float2(*(__half2*)&u.x);
        float2 p1 = __half22float2(*(__half2*)&u.y);
        s.x += p0.x; s.y += p0.y; s.z += p1.x; s.w += p1.y;
    }
    ((float4*)g_ms)[t] = s;
}

__global__ void k_gru(const int* __restrict__ ev) {
    int t = blockIdx.x * blockDim.x + threadIdx.x;
    if (t >= BB*NN*CD) return;
    int row = t / CD, c = t % CD;
    int b = row / NN, n = row % NN;
    if (n >= ev[b]) return;
    const float* gi = g_gi + (size_t)row*384;
    const float* gh = g_gh + (size_t)row*384;
    float ir = gi[c], iz = gi[CD+c], in = gi[2*CD+c];
    float hr = gh[c], hz = gh[CD+c], hn = gh[2*CD+c];
    float r  = 1.f/(1.f + expf(-(ir+hr)));
    float z  = 1.f/(1.f + expf(-(iz+hz)));
    float nn = tanhf(in + r*hn);
    float hold = g_h[t];
    g_h[t] = (1.f - z)*nn + z*hold;
}

// ===================== readout (HMMA, 64-pair blocks, occ 2) ==================
// smem: [Ahi 32K][Alo 32K][Wbuf0 16K][Wbuf1 16K] = 96KB; 128 thr, 4 warps M16xN32
#define R2_AHI 0u
#define R2_ALO 32768u
#define R2_W0  65536u
#define R2_W1  81920u
#define R2_SMEM 98304

__global__ __launch_bounds__(128, 2)
void k_readout_mma(const float* __restrict__ br1, const float* __restrict__ Wr2g,
                   const float* __restrict__ br2, const int* __restrict__ ev,
                   float* __restrict__ out) {
    extern __shared__ char smem[];
    __shared__ float sWr2[2560];
    __shared__ float sBr1[256];
    uint32_t sb = smem_u32(smem);
    int tid = threadIdx.x, warp = tid >> 5, l = tid & 31, q = l & 3;
    int b = blockIdx.y, p0 = blockIdx.x * 64;   // PP = 127*64 exactly
    int vn = ev[b];
    const char* wsrc = (const char*)g_wr;

    // block validity: any pair with ju < vn?
    int myValid = 0;
    if (tid < 64) { if (g_ju[p0 + tid] < vn) myValid = 1; }
    if (!__syncthreads_or(myValid)) return;

    // prologue: prefetch W sub-chunks 0,1 (chunk c2: g=c2>>1 n32 group, half=c2&1)
    // src hi: g_wr + cc*65536 + half*32768 + nh*8192; lo at +16384
#pragma unroll
    for (int t = 0; t < 4; ++t) {
        cp16(sb + R2_W0 + (uint32_t)(tid + t*128)*16u, wsrc + (size_t)(tid + t*128)*16);
        cp16(sb + R2_W0 + 8192u + (uint32_t)(tid + t*128)*16u, wsrc + 16384 + (size_t)(tid + t*128)*16);
    }
    CP_COMMIT();
#pragma unroll
    for (int t = 0; t < 4; ++t) {
        cp16(sb + R2_W1 + (uint32_t)(tid + t*128)*16u, wsrc + 32768 + (size_t)(tid + t*128)*16);
        cp16(sb + R2_W1 + 8192u + (uint32_t)(tid + t*128)*16u, wsrc + 32768 + 16384 + (size_t)(tid + t*128)*16);
    }
    CP_COMMIT();

    for (int t = tid; t < 2560; t += 128) sWr2[t] = Wr2g[t];
    for (int t = tid; t < 256; t += 128) sBr1[t] = br1[t];

    // gather feat [64 pairs][256] from pre-split planes
    for (int t = tid; t < 4096; t += 128) {
        int lp = t >> 6, c = (t & 63) << 2;
        int p = p0 + lp;
        int iu = g_iu[p], ju = g_ju[p];
        const char* base; uint32_t o;
        if (c < 128) {
            base = (const char*)g_ebf + (size_t)(b*NN + iu)*65536;
            o = swz<8>(ju, c);
        } else {
            base = (const char*)g_ebf + (size_t)(b*NN + ju)*65536;
            o = swz<8>(iu, c - 128);
        }
        uint2 hi = *(const uint2*)(base + o);
        uint2 lo = *(const uint2*)(base + 32768 + o);
        uint32_t off = swz<9>(lp, c);
        *(uint2*)(smem + R2_AHI + off) = hi;
        *(uint2*)(smem + R2_ALO + off) = lo;
    }

    int rA = (warp << 4) + (l >> 2), rB = rA + 8;   // local pair idx
    float outA[10], outB[10];
#pragma unroll
    for (int t5 = 0; t5 < 10; ++t5) { outA[t5] = 0.f; outB[t5] = 0.f; }
    float acc[4][4];

#pragma unroll
    for (int c2 = 0; c2 < 16; ++c2) {
        if (c2 == 15) { CP_WAIT0(); } else { CP_WAIT1(); }
        __syncthreads();
        if ((c2 & 1) == 0) {
#pragma unroll
            for (int t = 0; t < 4; ++t)
#pragma unroll
                for (int e = 0; e < 4; ++e) acc[t][e] = 0.f;
        }
        uint32_t wb = sb + R2_W0 + (uint32_t)(c2 & 1)*16384u;
        gemm_split2<9,8,8,2>(sb, R2_AHI, R2_ALO, wb, wb + 8192u, warp << 4, (c2 & 1)*8, l, acc);
        __syncthreads();
        if (c2 + 2 < 16) {
            int nc = c2 + 2;
            int g = nc >> 1, cc = g >> 1, nh = g & 1, half = nc & 1;
            const char* srcHi = wsrc + (size_t)cc*65536 + (size_t)half*32768 + (size_t)nh*8192;
            uint32_t db = sb + R2_W0 + (uint32_t)(c2 & 1)*16384u;
#pragma unroll
            for (int t = 0; t < 4; ++t) {
                cp16(db + (uint32_t)(tid + t*128)*16u, srcHi + (size_t)(tid + t*128)*16);
                cp16(db + 8192u + (uint32_t)(tid + t*128)*16u, srcHi + 16384 + (size_t)(tid + t*128)*16);
            }
            CP_COMMIT();
        }
        if (c2 & 1) {
            int g = c2 >> 1;   // n32 group 0..7
#pragma unroll
            for (int t = 0; t < 4; ++t) {
                int n0 = (g << 5) + (t << 3) + (q << 1);
#pragma unroll
                for (int e = 0; e < 4; ++e) {
                    int n = n0 + (e & 1);
                    float h = fmaxf(acc[t][e] + sBr1[n], 0.f);
                    float* o = (e < 2) ? outA : outB;
                    const float* w = sWr2 + n*10;
#pragma unroll
                    for (int t5 = 0; t5 < 10; ++t5) o[t5] = fmaf(h, w[t5], o[t5]);
                }
            }
        }
    }

#pragma unroll
    for (int t5 = 0; t5 < 10; ++t5) {
        outA[t5] += __shfl_xor_sync(~0u, outA[t5], 1);
        outA[t5] += __shfl_xor_sync(~0u, outA[t5], 2);
        outB[t5] += __shfl_xor_sync(~0u, outB[t5], 1);
        outB[t5] += __shfl_xor_sync(~0u, outB[t5], 2);
    }
    if (q == 0) {
#pragma unroll
        for (int h2 = 0; h2 < 2; ++h2) {
            int r = h2 ? rB : rA;
            float* o = h2 ? outB : outA;
            int p = p0 + r;
            int iu = g_iu[p], ju = g_ju[p];
            if (ju < vn) {
                int idx = iu*vn - iu*(iu+1)/2 + (ju - iu - 1);
#pragma unroll
                for (int t5 = 0; t5 < 10; ++t5)
                    out[(((size_t)b*5 + (t5 >> 1))*PP + idx)*2 + (t5 & 1)] = o[t5] + br2[t5];
            }
        }
    }
}

// ===================== host orchestration =====================================
extern "C" void kernel_launch(void* const* d_in, const int* in_sizes, int n_in,
                              void* d_out, int out_size) {
    const int*   edge_ids      = (const int*)  d_in[0];
    const float* node_features = (const float*)d_in[1];
    const int*   ev            = (const int*)  d_in[3];
    const float* emb           = (const float*)d_in[4];
    const float* Wl_e = (const float*)d_in[5];
    const float* Wl_w = (const float*)d_in[6];
    const float* Wl_v = (const float*)d_in[7];
    const float* bl1  = (const float*)d_in[8];
    const float* wl2  = (const float*)d_in[9];
    const float* bl2  = (const float*)d_in[10];
    const float* Wm_w = (const float*)d_in[11];
    const float* Wm_v = (const float*)d_in[12];
    const float* Wm_e = (const float*)d_in[13];
    const float* bm   = (const float*)d_in[14];
    const float* Wu_e = (const float*)d_in[15];
    const float* Wu_m = (const float*)d_in[16];
    const float* bu   = (const float*)d_in[17];
    const float* W_ih = (const float*)d_in[18];
    const float* W_hh = (const float*)d_in[19];
    const float* b_ih = (const float*)d_in[20];
    const float* b_hh = (const float*)d_in[21];
    const float* Wr1  = (const float*)d_in[22];
    const float* br1  = (const float*)d_in[23];
    const float* Wr2  = (const float*)d_in[24];
    const float* br2  = (const float*)d_in[25];

    cudaFuncSetAttribute(k_edge_mma,    cudaFuncAttributeMaxDynamicSharedMemorySize, EDGE_SMEM);
    cudaFuncSetAttribute(k_readout_mma, cudaFuncAttributeMaxDynamicSharedMemorySize, R2_SMEM);
    cudaFuncSetAttribute(k_rgemm_hp,    cudaFuncAttributeMaxDynamicSharedMemorySize, H2_SMEM);
    cudaFuncSetAttribute(k_rgemm_gig,   cudaFuncAttributeMaxDynamicSharedMemorySize, H2_SMEM);

    // launches: prep_w(0), prep_wr(1), hp(2), edge(3) — ncu captures index 3
    k_prep_w<<<896, 256>>>(Wl_e, Wm_e, Wu_e, Wu_m, Wl_w, Wl_v, Wm_w, Wm_v, W_ih, W_hh);
    k_prep_wr<<<256, 256>>>(Wr1);
    k_rgemm_hp<<<dim3(32, 8), 256, H2_SMEM>>>(node_features, bl1, bm, 1);

    for (int r = 0; r < RNDS; ++r) {
        if (r > 0)
            k_rgemm_hp<<<dim3(32, 8), 256, H2_SMEM>>>(node_features, bl1, bm, 0);
        k_edge_mma<<<BB*NN*2, 256, EDGE_SMEM>>>(wl2, bl2, bu, ev, edge_ids, emb, r == 0);
        k_reduce_ms<<<(BB*NN*CD/4 + 255)/256, 256>>>(ev);
        k_rgemm_gig<<<dim3(32, 6, 2), 256, H2_SMEM>>>(b_ih, b_hh);
        k_gru<<<(BB*NN*CD + 255)/256, 256>>>(ev);
    }

    cudaMemsetAsync(d_out, 0, (size_t)out_size * sizeof(float));
    k_readout_mma<<<dim3(PP/64, BB), 128, R2_SMEM>>>(br1, Wr2, br2, ev, (float*)d_out);
}